// round 11
// baseline (speedup 1.0000x reference)
#include <cuda_runtime.h>
#include <math.h>

#define BB 256
#define TT 64
#define NN 128
#define MM 256
#define INROW 129   // N + YD
#define NBLK 256

typedef unsigned long long ull;

// ---------------- scratch (device globals; no allocation) ----------------
__device__ float g_Xp[BB*TT*NN];     // immutable after xp
__device__ float g_Xe[BB*TT*MM];     // immutable after encode
__device__ float g_Xd[BB*TT*MM];     // immutable after xd
__device__ float g_h[2][BB*MM];      // mutable (ldcg)
__device__ float g_c[2][BB*MM];      // mutable (ldcg)
__device__ float g_xin[BB*NN];       // mutable (ldcg)
__device__ float g_hsW[BB*MM];       // mutable (ldcg)
__device__ float g_ehsW[BB*TT];      // mutable (ldcg) enc state projection
__device__ float g_gpre[BB*1024];    // mutable (ldcg) gate preactivations (h-part)
__device__ float g_ctx[BB*MM];

// ---------------- grid barrier ----------------
__device__ unsigned g_bar_count;
__device__ volatile unsigned g_bar_gen;

__device__ __forceinline__ void grid_sync() {
    __syncthreads();
    __threadfence();
    if (threadIdx.x == 0) {
        unsigned gen = g_bar_gen;
        if (atomicAdd(&g_bar_count, 1) == NBLK - 1) {
            g_bar_count = 0;
            __threadfence();
            g_bar_gen = gen + 1;
        } else {
            while (g_bar_gen == gen) { __nanosleep(32); }
        }
    }
    __syncthreads();
}

// ---------------- math helpers ----------------
__device__ __forceinline__ float fast_sigm(float x) {
    return __fdividef(1.0f, 1.0f + __expf(-x));
}
__device__ __forceinline__ float fast_tanh(float x) {
    float e = __expf(2.0f * x);
    return 1.0f - __fdividef(2.0f, e + 1.0f);
}
// single-MUFU tanh — attention score loops only
__device__ __forceinline__ float tanh_apx(float x) {
    float y; asm("tanh.approx.f32 %0, %1;" : "=f"(y) : "f"(x)); return y;
}
__device__ __forceinline__ float wredsum(float v) {
    #pragma unroll
    for (int o = 16; o > 0; o >>= 1) v += __shfl_down_sync(0xffffffffu, v, o);
    return v;
}
__device__ __forceinline__ float wredmax(float v) {
    #pragma unroll
    for (int o = 16; o > 0; o >>= 1) v = fmaxf(v, __shfl_down_sync(0xffffffffu, v, o));
    return v;
}
__device__ __forceinline__ ull f2pack(float lo, float hi) {
    ull r; asm("mov.b64 %0, {%1, %2};" : "=l"(r) : "f"(lo), "f"(hi)); return r;
}
__device__ __forceinline__ void ffma2(ull& d, ull a, ull b) {
    asm("fma.rn.f32x2 %0, %1, %2, %3;" : "=l"(d) : "l"(a), "l"(b), "l"(d));
}
__device__ __forceinline__ float2 f2unpack(ull v) {
    float2 r; asm("mov.b64 {%0, %1}, %2;" : "=f"(r.x), "=f"(r.y) : "l"(v)); return r;
}
__device__ __forceinline__ void cp4(void* dst, const float* src) {
    unsigned d = (unsigned)__cvta_generic_to_shared(dst);
    asm volatile("cp.async.ca.shared.global [%0], [%1], 4;" :: "r"(d), "l"(src));
}
__device__ __forceinline__ void cp_commit() {
    asm volatile("cp.async.commit_group;" ::: "memory");
}
template <int N>
__device__ __forceinline__ void cp_wait() {
    asm volatile("cp.async.wait_group %0;" :: "n"(N) : "memory");
}

// ---------------- shared memory union ----------------
struct SmGates  { float A[2][2][32][18]; float W[2][2][32][68]; float red[16][66]; };
struct SmXp     { float WUx[4096]; float Xs[8192]; };
struct SmAtt    { float hsW[64]; float ves[64]; float ep[128]; float redm[4]; float reds[4]; };
struct SmHsw    { float A[2][32][20]; float W[2][32][20]; float red[16][18]; };
struct SmEncHsw { float A[16][516]; };
struct SmXd     { float A[32][68]; float W[32][68]; };
struct SmDatt   { float hsw[256]; float vds[256]; float l[64]; float beta[64]; float reds[8]; float yt; };
struct SmFin    { float hc[512]; float hid[256]; float reds[8]; };
union SmAll {
    SmGates g; SmXp xp; SmAtt a; SmHsw h; SmEncHsw eh; SmXd xd; SmDatt d; SmFin f;
};

// ---------------- phase: Xp precompute (+ zero h/c) ----------------
__device__ __forceinline__ void ph_xp(const float* __restrict__ inp,
                                      const float* __restrict__ WU_e, SmXp& s) {
    int b = blockIdx.x, tid = threadIdx.x;
    {
        int idx = b * 256 + tid;
        g_h[0][idx] = 0.f; g_h[1][idx] = 0.f;
        g_c[0][idx] = 0.f; g_c[1][idx] = 0.f;
    }
    for (int idx = tid; idx < 4096; idx += 256) {
        int t = idx >> 6, tp = idx & 63;
        s.WUx[idx] = WU_e[t*576 + 512 + tp];
    }
    for (int idx = tid; idx < 8192; idx += 256) {
        int tp = idx >> 7, n = idx & 127;
        s.Xs[idx] = inp[b*TT*INROW + tp*INROW + n];
    }
    __syncthreads();
    int half = tid >> 7, n = tid & 127;
    float acc[32];
    #pragma unroll
    for (int t = 0; t < 32; ++t) acc[t] = 0.f;
    for (int tp = 0; tp < 64; ++tp) {
        float xv = s.Xs[tp*128 + n];
        #pragma unroll
        for (int t = 0; t < 32; ++t) acc[t] += xv * s.WUx[(half*32 + t)*64 + tp];
    }
    #pragma unroll
    for (int t = 0; t < 32; ++t) g_Xp[(b*TT + half*32 + t)*NN + n] = acc[t];
}

// ---------------- shared sub-phase: gates h-GEMM (K=256) -> g_gpre ----------------
// grid mapping (bb = blk>>4 batch group, mo = blk&15 m group), tile 16b x 64 gate-cols
__device__ __forceinline__ void ph_gates_h(const float* __restrict__ Whh, int par, SmGates& s) {
    int bb = blockIdx.x >> 4, mo = blockIdx.x & 15;
    int tid = threadIdx.x;
    int kg = tid >> 7;
    int t128 = tid & 127;
    int ty = t128 >> 4, tx = t128 & 15;
    ull acc[2][2] = {{0ull, 0ull}, {0ull, 0ull}};
    const float* hsrc = g_h[par];
    int kbase = kg * 128;
    float ra[4];

    #define GH_LOAD_A(c) do {                                                  \
        int kc = kbase + (c)*32;                                               \
        _Pragma("unroll")                                                      \
        for (int u = 0; u < 4; ++u) {                                          \
            int idx = t128 + u*128;                                            \
            int row = idx >> 5, kk = idx & 31;                                 \
            ra[u] = __ldcg(hsrc + (bb*16 + row)*MM + kc + kk);                 \
        }                                                                      \
    } while (0)
    #define GH_STORE_A(st) do {                                                \
        _Pragma("unroll")                                                      \
        for (int u = 0; u < 4; ++u) {                                          \
            int idx = t128 + u*128;                                            \
            s.A[st][kg][idx & 31][idx >> 5] = ra[u];                           \
        }                                                                      \
    } while (0)
    #define GH_ISSUE_W(c, st) do {                                             \
        int kc = kbase + (c)*32;                                               \
        _Pragma("unroll")                                                      \
        for (int u = 0; u < 16; ++u) {                                         \
            int idx = t128 + u*128;                                            \
            int co = idx >> 5, kk = idx & 31;                                  \
            int row = (co >> 4)*256 + mo*16 + (co & 15);                       \
            cp4(&s.W[st][kg][kk][co], Whh + row*256 + kc + kk);                \
        }                                                                      \
        cp_commit();                                                           \
    } while (0)

    GH_LOAD_A(0); GH_ISSUE_W(0, 0); GH_STORE_A(0);
    #pragma unroll
    for (int c = 0; c < 4; ++c) {
        int st = c & 1;
        if (c < 3) { GH_ISSUE_W(c + 1, st ^ 1); GH_LOAD_A(c + 1); cp_wait<1>(); }
        else       { cp_wait<0>(); }
        __syncthreads();
        #pragma unroll
        for (int kk = 0; kk < 32; ++kk) {
            float2 a = *(const float2*)&s.A[st][kg][kk][ty*2];
            float4 w = *(const float4*)&s.W[st][kg][kk][tx*4];
            ull ax = f2pack(a.x, a.x), ay = f2pack(a.y, a.y);
            ull w01 = f2pack(w.x, w.y), w23 = f2pack(w.z, w.w);
            ffma2(acc[0][0], ax, w01); ffma2(acc[0][1], ax, w23);
            ffma2(acc[1][0], ay, w01); ffma2(acc[1][1], ay, w23);
        }
        if (c < 3) GH_STORE_A(st ^ 1);
        __syncthreads();
    }
    #undef GH_LOAD_A
    #undef GH_STORE_A
    #undef GH_ISSUE_W

    if (kg == 0) {
        #pragma unroll
        for (int i = 0; i < 2; ++i) {
            *(float2*)&s.red[ty*2 + i][tx*4]     = f2unpack(acc[i][0]);
            *(float2*)&s.red[ty*2 + i][tx*4 + 2] = f2unpack(acc[i][1]);
        }
    }
    __syncthreads();
    if (kg == 1) {
        #pragma unroll
        for (int i = 0; i < 2; ++i) {
            float2 v0 = f2unpack(acc[i][0]), v1 = f2unpack(acc[i][1]);
            float2 c0 = *(float2*)&s.red[ty*2 + i][tx*4];
            float2 c1 = *(float2*)&s.red[ty*2 + i][tx*4 + 2];
            c0.x += v0.x; c0.y += v0.y; c1.x += v1.x; c1.y += v1.y;
            *(float2*)&s.red[ty*2 + i][tx*4]     = c0;
            *(float2*)&s.red[ty*2 + i][tx*4 + 2] = c1;
        }
    }
    __syncthreads();
    // store gpre: layout [gb][mo*64 + co], co = gate*16 + ml
    for (int p = tid; p < 1024; p += 256) {
        int bi = p >> 6, co = p & 63;
        g_gpre[(bb*16 + bi)*1024 + mo*64 + co] = s.red[bi][co];
    }
}

// ---------------- encoder phase E1: state-projection GEMM + h-gates GEMM ----------------
__device__ __forceinline__ void ph_enc_e1(const float* __restrict__ WU_e,
                                          const float* __restrict__ Whh_e,
                                          int par, SmAll& sm) {
    // sub1: ehsW[b][t] = sum_k [h|c][b][k] * WU_e[t][k], tile 16b x 4t
    {
        SmEncHsw& s = sm.eh;
        int rb = blockIdx.x >> 4, ob = blockIdx.x & 15;
        int tid = threadIdx.x;
        for (int idx = tid; idx < 8192; idx += 256) {
            int r = idx >> 9, k = idx & 511;
            int gb = rb*16 + r;
            s.A[r][k] = (k < 256) ? __ldcg(&g_h[par][gb*MM + k])
                                  : __ldcg(&g_c[par][gb*MM + k - 256]);
        }
        __syncthreads();
        int w = tid >> 5, l = tid & 31;
        float acc[2][4];
        #pragma unroll
        for (int i = 0; i < 2; ++i)
            #pragma unroll
            for (int cc = 0; cc < 4; ++cc) acc[i][cc] = 0.f;
        for (int kb = l; kb < 512; kb += 32) {
            float a0 = s.A[2*w][kb], a1 = s.A[2*w + 1][kb];
            #pragma unroll
            for (int cc = 0; cc < 4; ++cc) {
                float wv = WU_e[(ob*4 + cc)*576 + kb];
                acc[0][cc] += a0*wv; acc[1][cc] += a1*wv;
            }
        }
        #pragma unroll
        for (int i = 0; i < 2; ++i)
            #pragma unroll
            for (int cc = 0; cc < 4; ++cc) {
                float v = wredsum(acc[i][cc]);
                if (l == 0) g_ehsW[(rb*16 + 2*w + i)*TT + ob*4 + cc] = v;
            }
    }
    __syncthreads();
    // sub2: h-gates GEMM
    ph_gates_h(Whh_e, par, sm.g);
}

// ---------------- encoder phase E2: attention (E + softmax + xin) ----------------
__device__ __forceinline__ void ph_enc_att2(const float* __restrict__ inp,
                                            const float* __restrict__ v_e,
                                            int step, SmAtt& s) {
    int b = blockIdx.x, tid = threadIdx.x;
    int w = tid >> 5, l = tid & 31;
    if (tid < 64) { s.hsW[tid] = __ldcg(&g_ehsW[b*TT + tid]); s.ves[tid] = v_e[tid]; }
    __syncthreads();
    int half = tid >> 7, n = tid & 127;
    float e = 0.f;
    {
        const float* xp = g_Xp + b*TT*NN + half*32*NN + n;
        const float* vh = s.ves + half*32;
        const float* hh = s.hsW + half*32;
        #pragma unroll 8
        for (int t = 0; t < 32; ++t) e += vh[t] * tanh_apx(hh[t] + xp[t*NN]);
    }
    if (half == 1) s.ep[n] = e;
    __syncthreads();
    float p = 0.f;
    if (half == 0) {
        e += s.ep[n];
        float m = wredmax(e);
        if (l == 0) s.redm[w] = m;
    }
    __syncthreads();
    if (half == 0) {
        float m = fmaxf(fmaxf(s.redm[0], s.redm[1]), fmaxf(s.redm[2], s.redm[3]));
        p = __expf(e - m);
        float sv = wredsum(p);
        if (l == 0) s.reds[w] = sv;
    }
    __syncthreads();
    if (half == 0) {
        float tot = s.reds[0] + s.reds[1] + s.reds[2] + s.reds[3];
        float alpha = __fdividef(p, tot);
        g_xin[b*NN + n] = inp[b*TT*INROW + step*INROW + n] * alpha;
    }
}

// ---------------- encoder phase E3: x-gates GEMM (K=128) + LSTM epilogue ----------------
__device__ __forceinline__ void ph_enc_gatesx(const float* __restrict__ Wih,
                                              const float* __restrict__ bih,
                                              const float* __restrict__ bhh,
                                              int step, int par, SmGates& s) {
    int bb = blockIdx.x >> 4, mo = blockIdx.x & 15;
    int tid = threadIdx.x;
    int kg = tid >> 7;
    int t128 = tid & 127;
    int ty = t128 >> 4, tx = t128 & 15;
    ull acc[2][2] = {{0ull, 0ull}, {0ull, 0ull}};
    int kbase = kg * 64;
    float ra[4];

    #define GX_LOAD_A(c) do {                                                  \
        int kc = kbase + (c)*32;                                               \
        _Pragma("unroll")                                                      \
        for (int u = 0; u < 4; ++u) {                                          \
            int idx = t128 + u*128;                                            \
            int row = idx >> 5, kk = idx & 31;                                 \
            ra[u] = __ldcg(g_xin + (bb*16 + row)*NN + kc + kk);                \
        }                                                                      \
    } while (0)
    #define GX_STORE_A(st) do {                                                \
        _Pragma("unroll")                                                      \
        for (int u = 0; u < 4; ++u) {                                          \
            int idx = t128 + u*128;                                            \
            s.A[st][kg][idx & 31][idx >> 5] = ra[u];                           \
        }                                                                      \
    } while (0)
    #define GX_ISSUE_W(c, st) do {                                             \
        int kc = kbase + (c)*32;                                               \
        _Pragma("unroll")                                                      \
        for (int u = 0; u < 16; ++u) {                                         \
            int idx = t128 + u*128;                                            \
            int co = idx >> 5, kk = idx & 31;                                  \
            int row = (co >> 4)*256 + mo*16 + (co & 15);                       \
            cp4(&s.W[st][kg][kk][co], Wih + row*128 + kc + kk);                \
        }                                                                      \
        cp_commit();                                                           \
    } while (0)

    GX_LOAD_A(0); GX_ISSUE_W(0, 0); GX_STORE_A(0);
    #pragma unroll
    for (int c = 0; c < 2; ++c) {
        int st = c & 1;
        if (c < 1) { GX_ISSUE_W(c + 1, st ^ 1); GX_LOAD_A(c + 1); cp_wait<1>(); }
        else       { cp_wait<0>(); }
        __syncthreads();
        #pragma unroll
        for (int kk = 0; kk < 32; ++kk) {
            float2 a = *(const float2*)&s.A[st][kg][kk][ty*2];
            float4 w = *(const float4*)&s.W[st][kg][kk][tx*4];
            ull ax = f2pack(a.x, a.x), ay = f2pack(a.y, a.y);
            ull w01 = f2pack(w.x, w.y), w23 = f2pack(w.z, w.w);
            ffma2(acc[0][0], ax, w01); ffma2(acc[0][1], ax, w23);
            ffma2(acc[1][0], ay, w01); ffma2(acc[1][1], ay, w23);
        }
        if (c < 1) GX_STORE_A(st ^ 1);
        __syncthreads();
    }
    #undef GX_LOAD_A
    #undef GX_STORE_A
    #undef GX_ISSUE_W

    if (kg == 0) {
        #pragma unroll
        for (int i = 0; i < 2; ++i) {
            *(float2*)&s.red[ty*2 + i][tx*4]     = f2unpack(acc[i][0]);
            *(float2*)&s.red[ty*2 + i][tx*4 + 2] = f2unpack(acc[i][1]);
        }
    }
    __syncthreads();
    if (kg == 1) {
        #pragma unroll
        for (int i = 0; i < 2; ++i) {
            float2 v0 = f2unpack(acc[i][0]), v1 = f2unpack(acc[i][1]);
            float2 c0 = *(float2*)&s.red[ty*2 + i][tx*4];
            float2 c1 = *(float2*)&s.red[ty*2 + i][tx*4 + 2];
            c0.x += v0.x; c0.y += v0.y; c1.x += v1.x; c1.y += v1.y;
            *(float2*)&s.red[ty*2 + i][tx*4]     = c0;
            *(float2*)&s.red[ty*2 + i][tx*4 + 2] = c1;
        }
    }
    __syncthreads();
    {
        int bi = tid >> 4, ml = tid & 15;
        int gb = bb*16 + bi, m = mo*16 + ml;
        const float* gp = g_gpre + gb*1024 + mo*64;
        float gi = s.red[bi][ml]      + __ldcg(gp + ml)      + bih[m]       + bhh[m];
        float gf = s.red[bi][16 + ml] + __ldcg(gp + 16 + ml) + bih[256 + m] + bhh[256 + m];
        float gg = s.red[bi][32 + ml] + __ldcg(gp + 32 + ml) + bih[512 + m] + bhh[512 + m];
        float go = s.red[bi][48 + ml] + __ldcg(gp + 48 + ml) + bih[768 + m] + bhh[768 + m];
        float cold = __ldcg(&g_c[par][gb*MM + m]);
        float cn = fast_sigm(gf)*cold + fast_sigm(gi)*fast_tanh(gg);
        float hn = fast_sigm(go)*fast_tanh(cn);
        g_c[par ^ 1][gb*MM + m] = cn;
        g_h[par ^ 1][gb*MM + m] = hn;
        g_Xe[(gb*TT + step)*MM + m] = hn;
    }
}

// ---------------- phase: Xd precompute (+ re-zero h/c) ----------------
__device__ __forceinline__ void ph_xd(const float* __restrict__ WU_d, SmXd& s) {
    int rb = blockIdx.x, tid = threadIdx.x;
    int ty = tid >> 4, tx = tid & 15;
    for (int ob = 0; ob < 4; ++ob) {
        float acc[4][4];
        #pragma unroll
        for (int i = 0; i < 4; ++i)
            #pragma unroll
            for (int j = 0; j < 4; ++j) acc[i][j] = 0.f;
        for (int kc = 0; kc < 256; kc += 32) {
            for (int idx = tid; idx < 2048; idx += 256) {
                int ri = idx >> 5, kk = idx & 31;
                s.A[kk][ri] = g_Xe[(rb*64 + ri)*MM + kc + kk];
            }
            for (int idx = tid; idx < 2048; idx += 256) {
                int co = idx >> 5, kk = idx & 31;
                s.W[kk][co] = WU_d[(ob*64 + co)*768 + 512 + kc + kk];
            }
            __syncthreads();
            #pragma unroll
            for (int kk = 0; kk < 32; ++kk) {
                float4 a = *(const float4*)&s.A[kk][ty*4];
                float4 w = *(const float4*)&s.W[kk][tx*4];
                acc[0][0] += a.x*w.x; acc[0][1] += a.x*w.y; acc[0][2] += a.x*w.z; acc[0][3] += a.x*w.w;
                acc[1][0] += a.y*w.x; acc[1][1] += a.y*w.y; acc[1][2] += a.y*w.z; acc[1][3] += a.y*w.w;
                acc[2][0] += a.z*w.x; acc[2][1] += a.z*w.y; acc[2][2] += a.z*w.z; acc[2][3] += a.z*w.w;
                acc[3][0] += a.w*w.x; acc[3][1] += a.w*w.y; acc[3][2] += a.w*w.z; acc[3][3] += a.w*w.w;
            }
            __syncthreads();
        }
        #pragma unroll
        for (int i = 0; i < 4; ++i)
            #pragma unroll
            for (int j = 0; j < 4; ++j)
                g_Xd[(rb*64 + ty*4 + i)*MM + ob*64 + tx*4 + j] = acc[i][j];
    }
    int idx = blockIdx.x * 256 + tid;
    g_h[0][idx] = 0.f; g_h[1][idx] = 0.f;
    g_c[0][idx] = 0.f; g_c[1][idx] = 0.f;
}

// ---------------- decoder phase D1: hsW GEMM + h-gates GEMM ----------------
__device__ __forceinline__ void ph_dec_d1(const float* __restrict__ WU_d,
                                          const float* __restrict__ Whh_d,
                                          int par, SmAll& sm) {
    // sub1: hsW tile 16b x 16o
    {
        SmHsw& s = sm.h;
        int rb = blockIdx.x >> 4, ob = blockIdx.x & 15;
        int tid = threadIdx.x;
        int kg = tid >> 7;
        int t128 = tid & 127;
        int ty = t128 >> 4, tx = t128 & 15;
        ull acc = 0ull;
        int kbase = kg * 256;
        for (int c = 0; c < 8; ++c) {
            int kc = kbase + c*32;
            #pragma unroll
            for (int u = 0; u < 4; ++u) {
                int idx = t128 + u*128;
                int ri = idx >> 5, kk = idx & 31;
                int k = kc + kk, gb = rb*16 + ri;
                s.A[kg][kk][ri] = (k < 256) ? __ldcg(&g_h[par][gb*MM + k])
                                            : __ldcg(&g_c[par][gb*MM + k - 256]);
            }
            #pragma unroll
            for (int u = 0; u < 4; ++u) {
                int idx = t128 + u*128;
                int co = idx >> 5, kk = idx & 31;
                s.W[kg][kk][co] = WU_d[(ob*16 + co)*768 + kc + kk];
            }
            __syncthreads();
            #pragma unroll
            for (int kk = 0; kk < 32; ++kk) {
                float2 a = *(const float2*)&s.A[kg][kk][ty*2];
                float w = s.W[kg][kk][tx];
                ffma2(acc, f2pack(a.x, a.y), f2pack(w, w));
            }
            __syncthreads();
        }
        float2 v = f2unpack(acc);
        if (kg == 0) { s.red[ty*2][tx] = v.x; s.red[ty*2 + 1][tx] = v.y; }
        __syncthreads();
        if (kg == 1) { s.red[ty*2][tx] += v.x; s.red[ty*2 + 1][tx] += v.y; }
        __syncthreads();
        {
            int ri = tid >> 4, co = tid & 15;
            g_hsW[(rb*16 + ri)*MM + ob*16 + co] = s.red[ri][co];
        }
    }
    __syncthreads();
    // sub2: h-gates GEMM
    ph_gates_h(Whh_d, par, sm.g);
}

// ---------------- decoder phase D2: attention + ctx + y_tilde + LSTM epilogue ----------------
__device__ __forceinline__ void ph_dec_att2(const float* __restrict__ inp,
                                            const float* __restrict__ v_d,
                                            const float* __restrict__ wbt,
                                            const float* __restrict__ Wihd,
                                            const float* __restrict__ bih,
                                            const float* __restrict__ bhh,
                                            int step, int par, SmDatt& s) {
    int b = blockIdx.x, tid = threadIdx.x;
    int w = tid >> 5, l = tid & 31;
    s.hsw[tid] = __ldcg(&g_hsW[b*MM + tid]);
    s.vds[tid] = v_d[tid];
    __syncthreads();
    for (int t = w; t < 64; t += 8) {
        const float* xd = g_Xd + (b*TT + t)*MM;
        float sv = 0.f;
        #pragma unroll
        for (int m = l; m < 256; m += 32) sv += s.vds[m] * tanh_apx(s.hsw[m] + xd[m]);
        sv = wredsum(sv);
        if (l == 0) s.l[t] = sv;
    }
    __syncthreads();
    if (tid < 32) {
        float a0 = s.l[tid], a1 = s.l[tid + 32];
        float mx = wredmax(fmaxf(a0, a1));
        mx = __shfl_sync(0xffffffffu, mx, 0);
        float p0 = __expf(a0 - mx), p1 = __expf(a1 - mx);
        float sm2 = wredsum(p0 + p1);
        sm2 = __shfl_sync(0xffffffffu, sm2, 0);
        s.beta[tid] = __fdividef(p0, sm2);
        s.beta[tid + 32] = __fdividef(p1, sm2);
    }
    __syncthreads();
    float c = 0.f;
    const float* xe = g_Xe + b*TT*MM + tid;
    #pragma unroll 8
    for (int t = 0; t < 64; ++t) c += s.beta[t] * xe[t*MM];
    g_ctx[b*MM + tid] = c;
    float part = wbt[1 + tid] * c;
    part = wredsum(part);
    if (l == 0) s.reds[w] = part;
    __syncthreads();
    if (tid == 0) {
        float tot = 0.f;
        #pragma unroll
        for (int i = 0; i < 8; ++i) tot += s.reds[i];
        s.yt = wbt[0] * inp[b*TT*INROW + step*INROW + 128] + tot;
    }
    __syncthreads();
    // LSTM epilogue (batch b, m = tid)
    {
        float yt = s.yt;
        int mo = tid >> 4, ml = tid & 15, m = tid;
        const float* gp = g_gpre + b*1024 + mo*64;
        float gi = __ldcg(gp + ml)      + bih[m]       + bhh[m]       + yt*Wihd[m];
        float gf = __ldcg(gp + 16 + ml) + bih[256 + m] + bhh[256 + m] + yt*Wihd[256 + m];
        float gg = __ldcg(gp + 32 + ml) + bih[512 + m] + bhh[512 + m] + yt*Wihd[512 + m];
        float go = __ldcg(gp + 48 + ml) + bih[768 + m] + bhh[768 + m] + yt*Wihd[768 + m];
        float cold = __ldcg(&g_c[par][b*MM + m]);
        float cn = fast_sigm(gf)*cold + fast_sigm(gi)*fast_tanh(gg);
        float hn = fast_sigm(go)*fast_tanh(cn);
        g_c[par ^ 1][b*MM + m] = cn;
        g_h[par ^ 1][b*MM + m] = hn;
    }
}

// ---------------- phase: final projection ----------------
__device__ __forceinline__ void ph_final(const float* __restrict__ WbW,
                                         const float* __restrict__ Wbb,
                                         const float* __restrict__ vbW,
                                         const float* __restrict__ vbb,
                                         float* __restrict__ out, int par, SmFin& s) {
    int b = blockIdx.x, tid = threadIdx.x;
    int w = tid >> 5, l = tid & 31;
    s.hc[tid]       = __ldcg(&g_h[par][b*MM + tid]);
    s.hc[256 + tid] = __ldcg(&g_ctx[b*MM + tid]);
    __syncthreads();
    for (int p = w*32; p < w*32 + 32; ++p) {
        const float* row = WbW + p*512;
        float sv = 0.f;
        #pragma unroll
        for (int k = l; k < 512; k += 32) sv += s.hc[k] * row[k];
        sv = wredsum(sv);
        if (l == 0) s.hid[p] = sv + Wbb[p];
    }
    __syncthreads();
    float part = s.hid[tid] * vbW[tid];
    part = wredsum(part);
    if (l == 0) s.reds[w] = part;
    __syncthreads();
    if (tid == 0) {
        float tot = 0.f;
        #pragma unroll
        for (int i = 0; i < 8; ++i) tot += s.reds[i];
        out[b] = tot + vbb[0];
    }
}

// ---------------- persistent megakernel ----------------
__global__ void __launch_bounds__(256, 2) k_darnn(
        const float* __restrict__ inp,  const float* __restrict__ WU_e,
        const float* __restrict__ v_e,  const float* __restrict__ Wih_e,
        const float* __restrict__ Whh_e,const float* __restrict__ bih_e,
        const float* __restrict__ bhh_e,const float* __restrict__ WU_d,
        const float* __restrict__ v_d,  const float* __restrict__ wbt,
        const float* __restrict__ Wih_d,const float* __restrict__ Whh_d,
        const float* __restrict__ bih_d,const float* __restrict__ bhh_d,
        const float* __restrict__ WbW,  const float* __restrict__ Wbb,
        const float* __restrict__ vbW,  const float* __restrict__ vbb,
        float* __restrict__ out) {
    __shared__ SmAll sm;

    ph_xp(inp, WU_e, sm.xp);
    grid_sync();

    for (int s = 0; s < 64; ++s) {
        int par = s & 1;
        ph_enc_e1(WU_e, Whh_e, par, sm);
        grid_sync();
        ph_enc_att2(inp, v_e, s, sm.a);
        grid_sync();
        ph_enc_gatesx(Wih_e, bih_e, bhh_e, s, par, sm.g);
        grid_sync();
    }

    ph_xd(WU_d, sm.xd);
    grid_sync();

    for (int s = 0; s < 63; ++s) {
        int par = s & 1;
        ph_dec_d1(WU_d, Whh_d, par, sm);
        grid_sync();
        ph_dec_att2(inp, v_d, wbt, Wih_d, bih_d, bhh_d, s, par, sm.d);
        grid_sync();
    }

    ph_final(WbW, Wbb, vbW, vbb, out, 1, sm.f);
}

// ---------------- launcher ----------------
extern "C" void kernel_launch(void* const* d_in, const int* in_sizes, int n_in,
                              void* d_out, int out_size) {
    const float* inp   = (const float*)d_in[0];
    const float* WU_e  = (const float*)d_in[1];
    const float* v_e   = (const float*)d_in[2];
    const float* Wih_e = (const float*)d_in[3];
    const float* Whh_e = (const float*)d_in[4];
    const float* bih_e = (const float*)d_in[5];
    const float* bhh_e = (const float*)d_in[6];
    const float* WU_d  = (const float*)d_in[7];
    const float* v_d   = (const float*)d_in[8];
    const float* wbt   = (const float*)d_in[9];
    const float* Wih_d = (const float*)d_in[10];
    const float* Whh_d = (const float*)d_in[11];
    const float* bih_d = (const float*)d_in[12];
    const float* bhh_d = (const float*)d_in[13];
    const float* WbW   = (const float*)d_in[14];
    const float* Wbb   = (const float*)d_in[15];
    const float* vbW   = (const float*)d_in[16];
    const float* vbb   = (const float*)d_in[17];
    float* out = (float*)d_out;

    k_darnn<<<NBLK, 256>>>(inp, WU_e, v_e, Wih_e, Whh_e, bih_e, bhh_e,
                           WU_d, v_d, wbt, Wih_d, Whh_d, bih_d, bhh_d,
                           WbW, Wbb, vbW, vbb, out);
}

// round 12
// speedup vs baseline: 1.0744x; 1.0744x over previous
#include <cuda_runtime.h>
#include <math.h>

#define BB 256
#define TT 64
#define NN 128
#define MM 256
#define INROW 129   // N + YD
#define NBLK 256

typedef unsigned long long ull;

// ---------------- scratch (device globals; no allocation) ----------------
__device__ float g_Xp[BB*TT*NN];     // immutable after xp
__device__ float g_Xe[BB*TT*MM];     // immutable after encode
__device__ float g_Xd[BB*TT*MM];     // immutable after xd
__device__ float g_h[2][BB*MM];      // mutable (ldcg)
__device__ float g_c[2][BB*MM];      // mutable (ldcg)
__device__ float g_xin[BB*NN];       // mutable (ldcg)
__device__ float g_hsW[BB*MM];       // mutable (ldcg)
__device__ float g_gpre[BB*1024];    // mutable (ldcg) dec gate preactivations (h-part)
__device__ float g_ctx[BB*MM];

// ---------------- grid barrier ----------------
__device__ unsigned g_bar_count;
__device__ volatile unsigned g_bar_gen;

__device__ __forceinline__ void grid_sync() {
    __syncthreads();
    __threadfence();
    if (threadIdx.x == 0) {
        unsigned gen = g_bar_gen;
        if (atomicAdd(&g_bar_count, 1) == NBLK - 1) {
            g_bar_count = 0;
            __threadfence();
            g_bar_gen = gen + 1;
        } else {
            while (g_bar_gen == gen) { __nanosleep(32); }
        }
    }
    __syncthreads();
}

// ---------------- math helpers ----------------
__device__ __forceinline__ float fast_sigm(float x) {
    return __fdividef(1.0f, 1.0f + __expf(-x));
}
__device__ __forceinline__ float fast_tanh(float x) {
    float e = __expf(2.0f * x);
    return 1.0f - __fdividef(2.0f, e + 1.0f);
}
// single-MUFU tanh — attention score loops only
__device__ __forceinline__ float tanh_apx(float x) {
    float y; asm("tanh.approx.f32 %0, %1;" : "=f"(y) : "f"(x)); return y;
}
__device__ __forceinline__ float wredsum(float v) {
    #pragma unroll
    for (int o = 16; o > 0; o >>= 1) v += __shfl_down_sync(0xffffffffu, v, o);
    return v;
}
__device__ __forceinline__ float wredmax(float v) {
    #pragma unroll
    for (int o = 16; o > 0; o >>= 1) v = fmaxf(v, __shfl_down_sync(0xffffffffu, v, o));
    return v;
}
__device__ __forceinline__ ull f2pack(float lo, float hi) {
    ull r; asm("mov.b64 %0, {%1, %2};" : "=l"(r) : "f"(lo), "f"(hi)); return r;
}
__device__ __forceinline__ void ffma2(ull& d, ull a, ull b) {
    asm("fma.rn.f32x2 %0, %1, %2, %3;" : "=l"(d) : "l"(a), "l"(b), "l"(d));
}
__device__ __forceinline__ float2 f2unpack(ull v) {
    float2 r; asm("mov.b64 {%0, %1}, %2;" : "=f"(r.x), "=f"(r.y) : "l"(v)); return r;
}
__device__ __forceinline__ void cp4(void* dst, const float* src) {
    unsigned d = (unsigned)__cvta_generic_to_shared(dst);
    asm volatile("cp.async.ca.shared.global [%0], [%1], 4;" :: "r"(d), "l"(src));
}
__device__ __forceinline__ void cp_commit() {
    asm volatile("cp.async.commit_group;" ::: "memory");
}
template <int N>
__device__ __forceinline__ void cp_wait() {
    asm volatile("cp.async.wait_group %0;" :: "n"(N) : "memory");
}

// ---------------- shared memory union ----------------
struct SmGates { float A[2][2][32][18]; float W[2][2][32][68]; float red[16][66]; };
struct SmXp    { float WUx[4096]; float Xs[8192]; };
struct SmAtt   { float hs[512]; float hsW[64]; float ves[64]; float ep[128]; float redm[4]; float reds[4]; };
struct SmHsw   { float A[2][32][20]; float W[2][32][20]; float red[16][18]; };
struct SmXd    { float A[32][68]; float W[32][68]; };
struct SmDatt  { float hsw[256]; float vds[256]; float l[64]; float beta[64]; float reds[8]; float yt; };
struct SmFin   { float hc[512]; float hid[256]; float reds[8]; };
union SmAll {
    SmGates g; SmXp xp; SmAtt a; SmHsw h; SmXd xd; SmDatt d; SmFin f;
};

// ---------------- phase: Xp precompute (+ zero h/c) ----------------
__device__ __forceinline__ void ph_xp(const float* __restrict__ inp,
                                      const float* __restrict__ WU_e, SmXp& s) {
    int b = blockIdx.x, tid = threadIdx.x;
    {
        int idx = b * 256 + tid;
        g_h[0][idx] = 0.f; g_h[1][idx] = 0.f;
        g_c[0][idx] = 0.f; g_c[1][idx] = 0.f;
    }
    for (int idx = tid; idx < 4096; idx += 256) {
        int t = idx >> 6, tp = idx & 63;
        s.WUx[idx] = WU_e[t*576 + 512 + tp];
    }
    for (int idx = tid; idx < 8192; idx += 256) {
        int tp = idx >> 7, n = idx & 127;
        s.Xs[idx] = inp[b*TT*INROW + tp*INROW + n];
    }
    __syncthreads();
    int half = tid >> 7, n = tid & 127;
    float acc[32];
    #pragma unroll
    for (int t = 0; t < 32; ++t) acc[t] = 0.f;
    for (int tp = 0; tp < 64; ++tp) {
        float xv = s.Xs[tp*128 + n];
        #pragma unroll
        for (int t = 0; t < 32; ++t) acc[t] += xv * s.WUx[(half*32 + t)*64 + tp];
    }
    #pragma unroll
    for (int t = 0; t < 32; ++t) g_Xp[(b*TT + half*32 + t)*NN + n] = acc[t];
}

// ---------------- phase: encoder attention (hsW fused, round-10 form) ----------------
__device__ __forceinline__ void ph_enc_att(const float* __restrict__ inp,
                                           const float* __restrict__ WU_e,
                                           const float* __restrict__ v_e,
                                           int step, int par, SmAtt& s) {
    int b = blockIdx.x, tid = threadIdx.x;
    int w = tid >> 5, l = tid & 31;
    s.hs[tid]       = __ldcg(&g_h[par][b*MM + tid]);
    s.hs[tid + 256] = __ldcg(&g_c[par][b*MM + tid]);
    if (tid < 64) s.ves[tid] = v_e[tid];
    __syncthreads();
    #pragma unroll
    for (int t = w*8; t < w*8 + 8; ++t) {
        const float* row = WU_e + t*576;
        float sv = 0.f;
        #pragma unroll
        for (int k = l; k < 512; k += 32) sv += s.hs[k] * row[k];
        sv = wredsum(sv);
        if (l == 0) s.hsW[t] = sv;
    }
    __syncthreads();
    int half = tid >> 7, n = tid & 127;
    float e = 0.f;
    {
        const float* xp = g_Xp + b*TT*NN + half*32*NN + n;
        const float* vh = s.ves + half*32;
        const float* hh = s.hsW + half*32;
        #pragma unroll 8
        for (int t = 0; t < 32; ++t) e += vh[t] * tanh_apx(hh[t] + xp[t*NN]);
    }
    if (half == 1) s.ep[n] = e;
    __syncthreads();
    float p = 0.f;
    if (half == 0) {
        e += s.ep[n];
        float m = wredmax(e);
        if (l == 0) s.redm[w] = m;
    }
    __syncthreads();
    if (half == 0) {
        float m = fmaxf(fmaxf(s.redm[0], s.redm[1]), fmaxf(s.redm[2], s.redm[3]));
        p = __expf(e - m);
        float sv = wredsum(p);
        if (l == 0) s.reds[w] = sv;
    }
    __syncthreads();
    if (half == 0) {
        float tot = s.reds[0] + s.reds[1] + s.reds[2] + s.reds[3];
        float alpha = __fdividef(p, tot);
        g_xin[b*NN + n] = inp[b*TT*INROW + step*INROW + n] * alpha;
    }
}

// ---------------- phase: encoder gates GEMM + LSTM (round-10 form) ----------------
__device__ __forceinline__ void ph_enc_gates(const float* __restrict__ Wih,
                                             const float* __restrict__ Whh,
                                             const float* __restrict__ bih,
                                             const float* __restrict__ bhh,
                                             int step, int par, SmGates& s) {
    int bb = blockIdx.x >> 4, mo = blockIdx.x & 15;
    int tid = threadIdx.x;
    int kg = tid >> 7;
    int t128 = tid & 127;
    int ty = t128 >> 4, tx = t128 & 15;
    ull acc[2][2] = {{0ull, 0ull}, {0ull, 0ull}};
    const float* hsrc = g_h[par];
    int kbase = kg * 192;
    float ra[4];

    #define ENC_LOAD_A(c) do {                                                 \
        int kc = kbase + (c)*32;                                               \
        _Pragma("unroll")                                                      \
        for (int u = 0; u < 4; ++u) {                                          \
            int idx = t128 + u*128;                                            \
            int row = idx >> 5, kk = idx & 31;                                 \
            int k = kc + kk, gb = bb*16 + row;                                 \
            ra[u] = (k < 128) ? __ldcg(g_xin + gb*NN + k)                      \
                              : __ldcg(hsrc + gb*MM + (k - 128));              \
        }                                                                      \
    } while (0)
    #define ENC_STORE_A(st) do {                                               \
        _Pragma("unroll")                                                      \
        for (int u = 0; u < 4; ++u) {                                          \
            int idx = t128 + u*128;                                            \
            s.A[st][kg][idx & 31][idx >> 5] = ra[u];                           \
        }                                                                      \
    } while (0)
    #define ENC_ISSUE_W(c, st) do {                                            \
        int kc = kbase + (c)*32;                                               \
        _Pragma("unroll")                                                      \
        for (int u = 0; u < 16; ++u) {                                         \
            int idx = t128 + u*128;                                            \
            int co = idx >> 5, kk = idx & 31;                                  \
            int row = (co >> 4)*256 + mo*16 + (co & 15);                       \
            int k = kc + kk;                                                   \
            const float* src = (k < 128) ? (Wih + row*128 + k)                 \
                                         : (Whh + row*256 + (k - 128));        \
            cp4(&s.W[st][kg][kk][co], src);                                    \
        }                                                                      \
        cp_commit();                                                           \
    } while (0)

    ENC_LOAD_A(0); ENC_ISSUE_W(0, 0); ENC_STORE_A(0);
    #pragma unroll
    for (int c = 0; c < 6; ++c) {
        int st = c & 1;
        if (c < 5) { ENC_ISSUE_W(c + 1, st ^ 1); ENC_LOAD_A(c + 1); cp_wait<1>(); }
        else       { cp_wait<0>(); }
        __syncthreads();
        #pragma unroll
        for (int kk = 0; kk < 32; ++kk) {
            float2 a = *(const float2*)&s.A[st][kg][kk][ty*2];
            float4 w = *(const float4*)&s.W[st][kg][kk][tx*4];
            ull ax = f2pack(a.x, a.x), ay = f2pack(a.y, a.y);
            ull w01 = f2pack(w.x, w.y), w23 = f2pack(w.z, w.w);
            ffma2(acc[0][0], ax, w01); ffma2(acc[0][1], ax, w23);
            ffma2(acc[1][0], ay, w01); ffma2(acc[1][1], ay, w23);
        }
        if (c < 5) ENC_STORE_A(st ^ 1);
        __syncthreads();
    }
    #undef ENC_LOAD_A
    #undef ENC_STORE_A
    #undef ENC_ISSUE_W

    if (kg == 0) {
        #pragma unroll
        for (int i = 0; i < 2; ++i) {
            *(float2*)&s.red[ty*2 + i][tx*4]     = f2unpack(acc[i][0]);
            *(float2*)&s.red[ty*2 + i][tx*4 + 2] = f2unpack(acc[i][1]);
        }
    }
    __syncthreads();
    if (kg == 1) {
        #pragma unroll
        for (int i = 0; i < 2; ++i) {
            float2 v0 = f2unpack(acc[i][0]), v1 = f2unpack(acc[i][1]);
            float2 c0 = *(float2*)&s.red[ty*2 + i][tx*4];
            float2 c1 = *(float2*)&s.red[ty*2 + i][tx*4 + 2];
            c0.x += v0.x; c0.y += v0.y; c1.x += v1.x; c1.y += v1.y;
            *(float2*)&s.red[ty*2 + i][tx*4]     = c0;
            *(float2*)&s.red[ty*2 + i][tx*4 + 2] = c1;
        }
    }
    __syncthreads();
    {
        int bi = tid >> 4, ml = tid & 15;
        int gb = bb*16 + bi, m = mo*16 + ml;
        float gi = s.red[bi][ml]      + bih[m]       + bhh[m];
        float gf = s.red[bi][16 + ml] + bih[256 + m] + bhh[256 + m];
        float gg = s.red[bi][32 + ml] + bih[512 + m] + bhh[512 + m];
        float go = s.red[bi][48 + ml] + bih[768 + m] + bhh[768 + m];
        float cold = __ldcg(&g_c[par][gb*MM + m]);
        float cn = fast_sigm(gf)*cold + fast_sigm(gi)*fast_tanh(gg);
        float hn = fast_sigm(go)*fast_tanh(cn);
        g_c[par ^ 1][gb*MM + m] = cn;
        g_h[par ^ 1][gb*MM + m] = hn;
        g_Xe[(gb*TT + step)*MM + m] = hn;
    }
}

// ---------------- phase: Xd precompute (+ re-zero h/c) ----------------
__device__ __forceinline__ void ph_xd(const float* __restrict__ WU_d, SmXd& s) {
    int rb = blockIdx.x, tid = threadIdx.x;
    int ty = tid >> 4, tx = tid & 15;
    for (int ob = 0; ob < 4; ++ob) {
        float acc[4][4];
        #pragma unroll
        for (int i = 0; i < 4; ++i)
            #pragma unroll
            for (int j = 0; j < 4; ++j) acc[i][j] = 0.f;
        for (int kc = 0; kc < 256; kc += 32) {
            for (int idx = tid; idx < 2048; idx += 256) {
                int ri = idx >> 5, kk = idx & 31;
                s.A[kk][ri] = g_Xe[(rb*64 + ri)*MM + kc + kk];
            }
            for (int idx = tid; idx < 2048; idx += 256) {
                int co = idx >> 5, kk = idx & 31;
                s.W[kk][co] = WU_d[(ob*64 + co)*768 + 512 + kc + kk];
            }
            __syncthreads();
            #pragma unroll
            for (int kk = 0; kk < 32; ++kk) {
                float4 a = *(const float4*)&s.A[kk][ty*4];
                float4 w = *(const float4*)&s.W[kk][tx*4];
                acc[0][0] += a.x*w.x; acc[0][1] += a.x*w.y; acc[0][2] += a.x*w.z; acc[0][3] += a.x*w.w;
                acc[1][0] += a.y*w.x; acc[1][1] += a.y*w.y; acc[1][2] += a.y*w.z; acc[1][3] += a.y*w.w;
                acc[2][0] += a.z*w.x; acc[2][1] += a.z*w.y; acc[2][2] += a.z*w.z; acc[2][3] += a.z*w.w;
                acc[3][0] += a.w*w.x; acc[3][1] += a.w*w.y; acc[3][2] += a.w*w.z; acc[3][3] += a.w*w.w;
            }
            __syncthreads();
        }
        #pragma unroll
        for (int i = 0; i < 4; ++i)
            #pragma unroll
            for (int j = 0; j < 4; ++j)
                g_Xd[(rb*64 + ty*4 + i)*MM + ob*64 + tx*4 + j] = acc[i][j];
    }
    int idx = blockIdx.x * 256 + tid;
    g_h[0][idx] = 0.f; g_h[1][idx] = 0.f;
    g_c[0][idx] = 0.f; g_c[1][idx] = 0.f;
}

// ---------------- decoder sub-phase: h-gates GEMM (K=256) -> g_gpre ----------------
__device__ __forceinline__ void ph_gates_h(const float* __restrict__ Whh, int par, SmGates& s) {
    int bb = blockIdx.x >> 4, mo = blockIdx.x & 15;
    int tid = threadIdx.x;
    int kg = tid >> 7;
    int t128 = tid & 127;
    int ty = t128 >> 4, tx = t128 & 15;
    ull acc[2][2] = {{0ull, 0ull}, {0ull, 0ull}};
    const float* hsrc = g_h[par];
    int kbase = kg * 128;
    float ra[4];

    #define GH_LOAD_A(c) do {                                                  \
        int kc = kbase + (c)*32;                                               \
        _Pragma("unroll")                                                      \
        for (int u = 0; u < 4; ++u) {                                          \
            int idx = t128 + u*128;                                            \
            int row = idx >> 5, kk = idx & 31;                                 \
            ra[u] = __ldcg(hsrc + (bb*16 + row)*MM + kc + kk);                 \
        }                                                                      \
    } while (0)
    #define GH_STORE_A(st) do {                                                \
        _Pragma("unroll")                                                      \
        for (int u = 0; u < 4; ++u) {                                          \
            int idx = t128 + u*128;                                            \
            s.A[st][kg][idx & 31][idx >> 5] = ra[u];                           \
        }                                                                      \
    } while (0)
    #define GH_ISSUE_W(c, st) do {                                             \
        int kc = kbase + (c)*32;                                               \
        _Pragma("unroll")                                                      \
        for (int u = 0; u < 16; ++u) {                                         \
            int idx = t128 + u*128;                                            \
            int co = idx >> 5, kk = idx & 31;                                  \
            int row = (co >> 4)*256 + mo*16 + (co & 15);                       \
            cp4(&s.W[st][kg][kk][co], Whh + row*256 + kc + kk);                \
        }                                                                      \
        cp_commit();                                                           \
    } while (0)

    GH_LOAD_A(0); GH_ISSUE_W(0, 0); GH_STORE_A(0);
    #pragma unroll
    for (int c = 0; c < 4; ++c) {
        int st = c & 1;
        if (c < 3) { GH_ISSUE_W(c + 1, st ^ 1); GH_LOAD_A(c + 1); cp_wait<1>(); }
        else       { cp_wait<0>(); }
        __syncthreads();
        #pragma unroll
        for (int kk = 0; kk < 32; ++kk) {
            float2 a = *(const float2*)&s.A[st][kg][kk][ty*2];
            float4 w = *(const float4*)&s.W[st][kg][kk][tx*4];
            ull ax = f2pack(a.x, a.x), ay = f2pack(a.y, a.y);
            ull w01 = f2pack(w.x, w.y), w23 = f2pack(w.z, w.w);
            ffma2(acc[0][0], ax, w01); ffma2(acc[0][1], ax, w23);
            ffma2(acc[1][0], ay, w01); ffma2(acc[1][1], ay, w23);
        }
        if (c < 3) GH_STORE_A(st ^ 1);
        __syncthreads();
    }
    #undef GH_LOAD_A
    #undef GH_STORE_A
    #undef GH_ISSUE_W

    if (kg == 0) {
        #pragma unroll
        for (int i = 0; i < 2; ++i) {
            *(float2*)&s.red[ty*2 + i][tx*4]     = f2unpack(acc[i][0]);
            *(float2*)&s.red[ty*2 + i][tx*4 + 2] = f2unpack(acc[i][1]);
        }
    }
    __syncthreads();
    if (kg == 1) {
        #pragma unroll
        for (int i = 0; i < 2; ++i) {
            float2 v0 = f2unpack(acc[i][0]), v1 = f2unpack(acc[i][1]);
            float2 c0 = *(float2*)&s.red[ty*2 + i][tx*4];
            float2 c1 = *(float2*)&s.red[ty*2 + i][tx*4 + 2];
            c0.x += v0.x; c0.y += v0.y; c1.x += v1.x; c1.y += v1.y;
            *(float2*)&s.red[ty*2 + i][tx*4]     = c0;
            *(float2*)&s.red[ty*2 + i][tx*4 + 2] = c1;
        }
    }
    __syncthreads();
    for (int p = tid; p < 1024; p += 256) {
        int bi = p >> 6, co = p & 63;
        g_gpre[(bb*16 + bi)*1024 + mo*64 + co] = s.red[bi][co];
    }
}

// ---------------- decoder phase D1: hsW GEMM + h-gates GEMM ----------------
__device__ __forceinline__ void ph_dec_d1(const float* __restrict__ WU_d,
                                          const float* __restrict__ Whh_d,
                                          int par, SmAll& sm) {
    {
        SmHsw& s = sm.h;
        int rb = blockIdx.x >> 4, ob = blockIdx.x & 15;
        int tid = threadIdx.x;
        int kg = tid >> 7;
        int t128 = tid & 127;
        int ty = t128 >> 4, tx = t128 & 15;
        ull acc = 0ull;
        int kbase = kg * 256;
        for (int c = 0; c < 8; ++c) {
            int kc = kbase + c*32;
            #pragma unroll
            for (int u = 0; u < 4; ++u) {
                int idx = t128 + u*128;
                int ri = idx >> 5, kk = idx & 31;
                int k = kc + kk, gb = rb*16 + ri;
                s.A[kg][kk][ri] = (k < 256) ? __ldcg(&g_h[par][gb*MM + k])
                                            : __ldcg(&g_c[par][gb*MM + k - 256]);
            }
            #pragma unroll
            for (int u = 0; u < 4; ++u) {
                int idx = t128 + u*128;
                int co = idx >> 5, kk = idx & 31;
                s.W[kg][kk][co] = WU_d[(ob*16 + co)*768 + kc + kk];
            }
            __syncthreads();
            #pragma unroll
            for (int kk = 0; kk < 32; ++kk) {
                float2 a = *(const float2*)&s.A[kg][kk][ty*2];
                float w = s.W[kg][kk][tx];
                ffma2(acc, f2pack(a.x, a.y), f2pack(w, w));
            }
            __syncthreads();
        }
        float2 v = f2unpack(acc);
        if (kg == 0) { s.red[ty*2][tx] = v.x; s.red[ty*2 + 1][tx] = v.y; }
        __syncthreads();
        if (kg == 1) { s.red[ty*2][tx] += v.x; s.red[ty*2 + 1][tx] += v.y; }
        __syncthreads();
        {
            int ri = tid >> 4, co = tid & 15;
            g_hsW[(rb*16 + ri)*MM + ob*16 + co] = s.red[ri][co];
        }
    }
    __syncthreads();
    ph_gates_h(Whh_d, par, sm.g);
}

// ---------------- decoder phase D2: attention + ctx + y_tilde + LSTM epilogue ----------------
__device__ __forceinline__ void ph_dec_att2(const float* __restrict__ inp,
                                            const float* __restrict__ v_d,
                                            const float* __restrict__ wbt,
                                            const float* __restrict__ Wihd,
                                            const float* __restrict__ bih,
                                            const float* __restrict__ bhh,
                                            int step, int par, SmDatt& s) {
    int b = blockIdx.x, tid = threadIdx.x;
    int w = tid >> 5, l = tid & 31;
    s.hsw[tid] = __ldcg(&g_hsW[b*MM + tid]);
    s.vds[tid] = v_d[tid];
    __syncthreads();
    for (int t = w; t < 64; t += 8) {
        const float* xd = g_Xd + (b*TT + t)*MM;
        float sv = 0.f;
        #pragma unroll
        for (int m = l; m < 256; m += 32) sv += s.vds[m] * tanh_apx(s.hsw[m] + xd[m]);
        sv = wredsum(sv);
        if (l == 0) s.l[t] = sv;
    }
    __syncthreads();
    if (tid < 32) {
        float a0 = s.l[tid], a1 = s.l[tid + 32];
        float mx = wredmax(fmaxf(a0, a1));
        mx = __shfl_sync(0xffffffffu, mx, 0);
        float p0 = __expf(a0 - mx), p1 = __expf(a1 - mx);
        float sm2 = wredsum(p0 + p1);
        sm2 = __shfl_sync(0xffffffffu, sm2, 0);
        s.beta[tid] = __fdividef(p0, sm2);
        s.beta[tid + 32] = __fdividef(p1, sm2);
    }
    __syncthreads();
    float c = 0.f;
    const float* xe = g_Xe + b*TT*MM + tid;
    #pragma unroll 8
    for (int t = 0; t < 64; ++t) c += s.beta[t] * xe[t*MM];
    g_ctx[b*MM + tid] = c;
    float part = wbt[1 + tid] * c;
    part = wredsum(part);
    if (l == 0) s.reds[w] = part;
    __syncthreads();
    if (tid == 0) {
        float tot = 0.f;
        #pragma unroll
        for (int i = 0; i < 8; ++i) tot += s.reds[i];
        s.yt = wbt[0] * inp[b*TT*INROW + step*INROW + 128] + tot;
    }
    __syncthreads();
    {
        float yt = s.yt;
        int mo = tid >> 4, ml = tid & 15, m = tid;
        const float* gp = g_gpre + b*1024 + mo*64;
        float gi = __ldcg(gp + ml)      + bih[m]       + bhh[m]       + yt*Wihd[m];
        float gf = __ldcg(gp + 16 + ml) + bih[256 + m] + bhh[256 + m] + yt*Wihd[256 + m];
        float gg = __ldcg(gp + 32 + ml) + bih[512 + m] + bhh[512 + m] + yt*Wihd[512 + m];
        float go = __ldcg(gp + 48 + ml) + bih[768 + m] + bhh[768 + m] + yt*Wihd[768 + m];
        float cold = __ldcg(&g_c[par][b*MM + m]);
        float cn = fast_sigm(gf)*cold + fast_sigm(gi)*fast_tanh(gg);
        float hn = fast_sigm(go)*fast_tanh(cn);
        g_c[par ^ 1][b*MM + m] = cn;
        g_h[par ^ 1][b*MM + m] = hn;
    }
}

// ---------------- phase: final projection ----------------
__device__ __forceinline__ void ph_final(const float* __restrict__ WbW,
                                         const float* __restrict__ Wbb,
                                         const float* __restrict__ vbW,
                                         const float* __restrict__ vbb,
                                         float* __restrict__ out, int par, SmFin& s) {
    int b = blockIdx.x, tid = threadIdx.x;
    int w = tid >> 5, l = tid & 31;
    s.hc[tid]       = __ldcg(&g_h[par][b*MM + tid]);
    s.hc[256 + tid] = __ldcg(&g_ctx[b*MM + tid]);
    __syncthreads();
    for (int p = w*32; p < w*32 + 32; ++p) {
        const float* row = WbW + p*512;
        float sv = 0.f;
        #pragma unroll
        for (int k = l; k < 512; k += 32) sv += s.hc[k] * row[k];
        sv = wredsum(sv);
        if (l == 0) s.hid[p] = sv + Wbb[p];
    }
    __syncthreads();
    float part = s.hid[tid] * vbW[tid];
    part = wredsum(part);
    if (l == 0) s.reds[w] = part;
    __syncthreads();
    if (tid == 0) {
        float tot = 0.f;
        #pragma unroll
        for (int i = 0; i < 8; ++i) tot += s.reds[i];
        out[b] = tot + vbb[0];
    }
}

// ---------------- persistent megakernel ----------------
__global__ void __launch_bounds__(256, 2) k_darnn(
        const float* __restrict__ inp,  const float* __restrict__ WU_e,
        const float* __restrict__ v_e,  const float* __restrict__ Wih_e,
        const float* __restrict__ Whh_e,const float* __restrict__ bih_e,
        const float* __restrict__ bhh_e,const float* __restrict__ WU_d,
        const float* __restrict__ v_d,  const float* __restrict__ wbt,
        const float* __restrict__ Wih_d,const float* __restrict__ Whh_d,
        const float* __restrict__ bih_d,const float* __restrict__ bhh_d,
        const float* __restrict__ WbW,  const float* __restrict__ Wbb,
        const float* __restrict__ vbW,  const float* __restrict__ vbb,
        float* __restrict__ out) {
    __shared__ SmAll sm;

    ph_xp(inp, WU_e, sm.xp);
    grid_sync();

    for (int s = 0; s < 64; ++s) {
        int par = s & 1;
        ph_enc_att(inp, WU_e, v_e, s, par, sm.a);
        grid_sync();
        ph_enc_gates(Wih_e, Whh_e, bih_e, bhh_e, s, par, sm.g);
        grid_sync();
    }

    ph_xd(WU_d, sm.xd);
    grid_sync();

    for (int s = 0; s < 63; ++s) {
        int par = s & 1;
        ph_dec_d1(WU_d, Whh_d, par, sm);
        grid_sync();
        ph_dec_att2(inp, v_d, wbt, Wih_d, bih_d, bhh_d, s, par, sm.d);
        grid_sync();
    }

    ph_final(WbW, Wbb, vbW, vbb, out, 1, sm.f);
}

// ---------------- launcher ----------------
extern "C" void kernel_launch(void* const* d_in, const int* in_sizes, int n_in,
                              void* d_out, int out_size) {
    const float* inp   = (const float*)d_in[0];
    const float* WU_e  = (const float*)d_in[1];
    const float* v_e   = (const float*)d_in[2];
    const float* Wih_e = (const float*)d_in[3];
    const float* Whh_e = (const float*)d_in[4];
    const float* bih_e = (const float*)d_in[5];
    const float* bhh_e = (const float*)d_in[6];
    const float* WU_d  = (const float*)d_in[7];
    const float* v_d   = (const float*)d_in[8];
    const float* wbt   = (const float*)d_in[9];
    const float* Wih_d = (const float*)d_in[10];
    const float* Whh_d = (const float*)d_in[11];
    const float* bih_d = (const float*)d_in[12];
    const float* bhh_d = (const float*)d_in[13];
    const float* WbW   = (const float*)d_in[14];
    const float* Wbb   = (const float*)d_in[15];
    const float* vbW   = (const float*)d_in[16];
    const float* vbb   = (const float*)d_in[17];
    float* out = (float*)d_out;

    k_darnn<<<NBLK, 256>>>(inp, WU_e, v_e, Wih_e, Whh_e, bih_e, bhh_e,
                           WU_d, v_d, wbt, Wih_d, Whh_d, bih_d, bhh_d,
                           WbW, Wbb, vbW, vbb, out);
}

// round 13
// speedup vs baseline: 1.0812x; 1.0063x over previous
#include <cuda_runtime.h>
#include <math.h>

#define BB 256
#define TT 64
#define NN 128
#define MM 256
#define INROW 129   // N + YD
#define NBLK 256

typedef unsigned long long ull;

// ---------------- scratch (device globals; no allocation) ----------------
__device__ float g_Xp[BB*TT*NN];     // immutable after xp
__device__ float g_Xe[BB*TT*MM];     // immutable after encode
__device__ float g_Xd[BB*TT*MM];     // immutable after xd
__device__ float g_h[2][BB*MM];      // mutable (ldcg)
__device__ float g_c[2][BB*MM];      // mutable (ldcg)
__device__ float g_xin[BB*NN];       // mutable (ldcg)
__device__ float g_hsW[BB*MM];       // mutable (ldcg)
__device__ float g_gpre[BB*1024];    // mutable (ldcg) dec gate preactivations (h-part)
__device__ float g_ctx[BB*MM];

// ---------------- grid barrier (release/acquire, single-thread arrival) ----------------
__device__ unsigned g_bar_count;
__device__ unsigned g_bar_gen;

__device__ __forceinline__ unsigned ld_acq(const unsigned* p) {
    unsigned v;
    asm volatile("ld.acquire.gpu.u32 %0, [%1];" : "=r"(v) : "l"(p) : "memory");
    return v;
}

__device__ __forceinline__ void grid_sync() {
    __syncthreads();
    if (threadIdx.x == 0) {
        unsigned gen = g_bar_gen;   // own block's last-seen gen (plain load is fine)
        unsigned old;
        asm volatile("atom.add.release.gpu.u32 %0, [%1], 1;"
                     : "=r"(old) : "l"(&g_bar_count) : "memory");
        if (old == NBLK - 1) {
            g_bar_count = 0;        // ordered before the release-store below
            asm volatile("st.release.gpu.u32 [%0], %1;"
                         :: "l"(&g_bar_gen), "r"(gen + 1) : "memory");
        } else {
            while (ld_acq(&g_bar_gen) == gen) { }
        }
    }
    __syncthreads();
}

// ---------------- math helpers ----------------
__device__ __forceinline__ float fast_sigm(float x) {
    return __fdividef(1.0f, 1.0f + __expf(-x));
}
__device__ __forceinline__ float fast_tanh(float x) {
    float e = __expf(2.0f * x);
    return 1.0f - __fdividef(2.0f, e + 1.0f);
}
// single-MUFU tanh — attention score loops only
__device__ __forceinline__ float tanh_apx(float x) {
    float y; asm("tanh.approx.f32 %0, %1;" : "=f"(y) : "f"(x)); return y;
}
__device__ __forceinline__ float wredsum(float v) {
    #pragma unroll
    for (int o = 16; o > 0; o >>= 1) v += __shfl_down_sync(0xffffffffu, v, o);
    return v;
}
__device__ __forceinline__ float wredmax(float v) {
    #pragma unroll
    for (int o = 16; o > 0; o >>= 1) v = fmaxf(v, __shfl_down_sync(0xffffffffu, v, o));
    return v;
}
__device__ __forceinline__ ull f2pack(float lo, float hi) {
    ull r; asm("mov.b64 %0, {%1, %2};" : "=l"(r) : "f"(lo), "f"(hi)); return r;
}
__device__ __forceinline__ void ffma2(ull& d, ull a, ull b) {
    asm("fma.rn.f32x2 %0, %1, %2, %3;" : "=l"(d) : "l"(a), "l"(b), "l"(d));
}
__device__ __forceinline__ float2 f2unpack(ull v) {
    float2 r; asm("mov.b64 {%0, %1}, %2;" : "=f"(r.x), "=f"(r.y) : "l"(v)); return r;
}
__device__ __forceinline__ void cp4(void* dst, const float* src) {
    unsigned d = (unsigned)__cvta_generic_to_shared(dst);
    asm volatile("cp.async.ca.shared.global [%0], [%1], 4;" :: "r"(d), "l"(src));
}
__device__ __forceinline__ void cp_commit() {
    asm volatile("cp.async.commit_group;" ::: "memory");
}
template <int N>
__device__ __forceinline__ void cp_wait() {
    asm volatile("cp.async.wait_group %0;" :: "n"(N) : "memory");
}

// ---------------- shared memory union ----------------
struct SmGates { float A[2][2][32][18]; float W[2][2][32][68]; float red[16][66]; };
struct SmXp    { float WUx[4096]; float Xs[8192]; };
struct SmAtt   { float hs[512]; float hsW[64]; float ves[64]; float ep[128]; float redm[4]; float reds[4]; };
struct SmHsw   { float A[2][32][20]; float W[2][32][20]; float red[16][18]; };
struct SmXd    { float A[32][68]; float W[32][68]; };
struct SmDatt  { float hsw[256]; float vds[256]; float l[64]; float beta[64]; float reds[8]; float yt; };
struct SmFin   { float hc[512]; float hid[256]; float reds[8]; };
union SmAll {
    SmGates g; SmXp xp; SmAtt a; SmHsw h; SmXd xd; SmDatt d; SmFin f;
};

// ---------------- phase: Xp precompute (+ zero h/c) ----------------
__device__ __forceinline__ void ph_xp(const float* __restrict__ inp,
                                      const float* __restrict__ WU_e, SmXp& s) {
    int b = blockIdx.x, tid = threadIdx.x;
    {
        int idx = b * 256 + tid;
        g_h[0][idx] = 0.f; g_h[1][idx] = 0.f;
        g_c[0][idx] = 0.f; g_c[1][idx] = 0.f;
    }
    for (int idx = tid; idx < 4096; idx += 256) {
        int t = idx >> 6, tp = idx & 63;
        s.WUx[idx] = WU_e[t*576 + 512 + tp];
    }
    for (int idx = tid; idx < 8192; idx += 256) {
        int tp = idx >> 7, n = idx & 127;
        s.Xs[idx] = inp[b*TT*INROW + tp*INROW + n];
    }
    __syncthreads();
    int half = tid >> 7, n = tid & 127;
    float acc[32];
    #pragma unroll
    for (int t = 0; t < 32; ++t) acc[t] = 0.f;
    for (int tp = 0; tp < 64; ++tp) {
        float xv = s.Xs[tp*128 + n];
        #pragma unroll
        for (int t = 0; t < 32; ++t) acc[t] += xv * s.WUx[(half*32 + t)*64 + tp];
    }
    #pragma unroll
    for (int t = 0; t < 32; ++t) g_Xp[(b*TT + half*32 + t)*NN + n] = acc[t];
}

// ---------------- phase: encoder attention (hsW fused) ----------------
__device__ __forceinline__ void ph_enc_att(const float* __restrict__ inp,
                                           const float* __restrict__ WU_e,
                                           const float* __restrict__ v_e,
                                           int step, int par, SmAtt& s) {
    int b = blockIdx.x, tid = threadIdx.x;
    int w = tid >> 5, l = tid & 31;
    s.hs[tid]       = __ldcg(&g_h[par][b*MM + tid]);
    s.hs[tid + 256] = __ldcg(&g_c[par][b*MM + tid]);
    if (tid < 64) s.ves[tid] = v_e[tid];
    __syncthreads();
    #pragma unroll
    for (int t = w*8; t < w*8 + 8; ++t) {
        const float* row = WU_e + t*576;
        float sv = 0.f;
        #pragma unroll
        for (int k = l; k < 512; k += 32) sv += s.hs[k] * row[k];
        sv = wredsum(sv);
        if (l == 0) s.hsW[t] = sv;
    }
    __syncthreads();
    int half = tid >> 7, n = tid & 127;
    float e = 0.f;
    {
        const float* xp = g_Xp + b*TT*NN + half*32*NN + n;
        const float* vh = s.ves + half*32;
        const float* hh = s.hsW + half*32;
        #pragma unroll 8
        for (int t = 0; t < 32; ++t) e += vh[t] * tanh_apx(hh[t] + xp[t*NN]);
    }
    if (half == 1) s.ep[n] = e;
    __syncthreads();
    float p = 0.f;
    if (half == 0) {
        e += s.ep[n];
        float m = wredmax(e);
        if (l == 0) s.redm[w] = m;
    }
    __syncthreads();
    if (half == 0) {
        float m = fmaxf(fmaxf(s.redm[0], s.redm[1]), fmaxf(s.redm[2], s.redm[3]));
        p = __expf(e - m);
        float sv = wredsum(p);
        if (l == 0) s.reds[w] = sv;
    }
    __syncthreads();
    if (half == 0) {
        float tot = s.reds[0] + s.reds[1] + s.reds[2] + s.reds[3];
        float alpha = __fdividef(p, tot);
        g_xin[b*NN + n] = inp[b*TT*INROW + step*INROW + n] * alpha;
    }
}

// ---------------- phase: encoder gates GEMM + LSTM ----------------
__device__ __forceinline__ void ph_enc_gates(const float* __restrict__ Wih,
                                             const float* __restrict__ Whh,
                                             const float* __restrict__ bih,
                                             const float* __restrict__ bhh,
                                             int step, int par, SmGates& s) {
    int bb = blockIdx.x >> 4, mo = blockIdx.x & 15;
    int tid = threadIdx.x;
    int kg = tid >> 7;
    int t128 = tid & 127;
    int ty = t128 >> 4, tx = t128 & 15;
    ull acc[2][2] = {{0ull, 0ull}, {0ull, 0ull}};
    const float* hsrc = g_h[par];
    int kbase = kg * 192;
    float ra[4];

    #define ENC_LOAD_A(c) do {                                                 \
        int kc = kbase + (c)*32;                                               \
        _Pragma("unroll")                                                      \
        for (int u = 0; u < 4; ++u) {                                          \
            int idx = t128 + u*128;                                            \
            int row = idx >> 5, kk = idx & 31;                                 \
            int k = kc + kk, gb = bb*16 + row;                                 \
            ra[u] = (k < 128) ? __ldcg(g_xin + gb*NN + k)                      \
                              : __ldcg(hsrc + gb*MM + (k - 128));              \
        }                                                                      \
    } while (0)
    #define ENC_STORE_A(st) do {                                               \
        _Pragma("unroll")                                                      \
        for (int u = 0; u < 4; ++u) {                                          \
            int idx = t128 + u*128;                                            \
            s.A[st][kg][idx & 31][idx >> 5] = ra[u];                           \
        }                                                                      \
    } while (0)
    #define ENC_ISSUE_W(c, st) do {                                            \
        int kc = kbase + (c)*32;                                               \
        _Pragma("unroll")                                                      \
        for (int u = 0; u < 16; ++u) {                                         \
            int idx = t128 + u*128;                                            \
            int co = idx >> 5, kk = idx & 31;                                  \
            int row = (co >> 4)*256 + mo*16 + (co & 15);                       \
            int k = kc + kk;                                                   \
            const float* src = (k < 128) ? (Wih + row*128 + k)                 \
                                         : (Whh + row*256 + (k - 128));        \
            cp4(&s.W[st][kg][kk][co], src);                                    \
        }                                                                      \
        cp_commit();                                                           \
    } while (0)

    ENC_LOAD_A(0); ENC_ISSUE_W(0, 0); ENC_STORE_A(0);
    #pragma unroll
    for (int c = 0; c < 6; ++c) {
        int st = c & 1;
        if (c < 5) { ENC_ISSUE_W(c + 1, st ^ 1); ENC_LOAD_A(c + 1); cp_wait<1>(); }
        else       { cp_wait<0>(); }
        __syncthreads();
        #pragma unroll
        for (int kk = 0; kk < 32; ++kk) {
            float2 a = *(const float2*)&s.A[st][kg][kk][ty*2];
            float4 w = *(const float4*)&s.W[st][kg][kk][tx*4];
            ull ax = f2pack(a.x, a.x), ay = f2pack(a.y, a.y);
            ull w01 = f2pack(w.x, w.y), w23 = f2pack(w.z, w.w);
            ffma2(acc[0][0], ax, w01); ffma2(acc[0][1], ax, w23);
            ffma2(acc[1][0], ay, w01); ffma2(acc[1][1], ay, w23);
        }
        if (c < 5) ENC_STORE_A(st ^ 1);
        __syncthreads();
    }
    #undef ENC_LOAD_A
    #undef ENC_STORE_A
    #undef ENC_ISSUE_W

    if (kg == 0) {
        #pragma unroll
        for (int i = 0; i < 2; ++i) {
            *(float2*)&s.red[ty*2 + i][tx*4]     = f2unpack(acc[i][0]);
            *(float2*)&s.red[ty*2 + i][tx*4 + 2] = f2unpack(acc[i][1]);
        }
    }
    __syncthreads();
    if (kg == 1) {
        #pragma unroll
        for (int i = 0; i < 2; ++i) {
            float2 v0 = f2unpack(acc[i][0]), v1 = f2unpack(acc[i][1]);
            float2 c0 = *(float2*)&s.red[ty*2 + i][tx*4];
            float2 c1 = *(float2*)&s.red[ty*2 + i][tx*4 + 2];
            c0.x += v0.x; c0.y += v0.y; c1.x += v1.x; c1.y += v1.y;
            *(float2*)&s.red[ty*2 + i][tx*4]     = c0;
            *(float2*)&s.red[ty*2 + i][tx*4 + 2] = c1;
        }
    }
    __syncthreads();
    {
        int bi = tid >> 4, ml = tid & 15;
        int gb = bb*16 + bi, m = mo*16 + ml;
        float gi = s.red[bi][ml]      + bih[m]       + bhh[m];
        float gf = s.red[bi][16 + ml] + bih[256 + m] + bhh[256 + m];
        float gg = s.red[bi][32 + ml] + bih[512 + m] + bhh[512 + m];
        float go = s.red[bi][48 + ml] + bih[768 + m] + bhh[768 + m];
        float cold = __ldcg(&g_c[par][gb*MM + m]);
        float cn = fast_sigm(gf)*cold + fast_sigm(gi)*fast_tanh(gg);
        float hn = fast_sigm(go)*fast_tanh(cn);
        g_c[par ^ 1][gb*MM + m] = cn;
        g_h[par ^ 1][gb*MM + m] = hn;
        g_Xe[(gb*TT + step)*MM + m] = hn;
    }
}

// ---------------- phase: Xd precompute (+ re-zero h/c) ----------------
__device__ __forceinline__ void ph_xd(const float* __restrict__ WU_d, SmXd& s) {
    int rb = blockIdx.x, tid = threadIdx.x;
    int ty = tid >> 4, tx = tid & 15;
    for (int ob = 0; ob < 4; ++ob) {
        float acc[4][4];
        #pragma unroll
        for (int i = 0; i < 4; ++i)
            #pragma unroll
            for (int j = 0; j < 4; ++j) acc[i][j] = 0.f;
        for (int kc = 0; kc < 256; kc += 32) {
            for (int idx = tid; idx < 2048; idx += 256) {
                int ri = idx >> 5, kk = idx & 31;
                s.A[kk][ri] = g_Xe[(rb*64 + ri)*MM + kc + kk];
            }
            for (int idx = tid; idx < 2048; idx += 256) {
                int co = idx >> 5, kk = idx & 31;
                s.W[kk][co] = WU_d[(ob*64 + co)*768 + 512 + kc + kk];
            }
            __syncthreads();
            #pragma unroll
            for (int kk = 0; kk < 32; ++kk) {
                float4 a = *(const float4*)&s.A[kk][ty*4];
                float4 w = *(const float4*)&s.W[kk][tx*4];
                acc[0][0] += a.x*w.x; acc[0][1] += a.x*w.y; acc[0][2] += a.x*w.z; acc[0][3] += a.x*w.w;
                acc[1][0] += a.y*w.x; acc[1][1] += a.y*w.y; acc[1][2] += a.y*w.z; acc[1][3] += a.y*w.w;
                acc[2][0] += a.z*w.x; acc[2][1] += a.z*w.y; acc[2][2] += a.z*w.z; acc[2][3] += a.z*w.w;
                acc[3][0] += a.w*w.x; acc[3][1] += a.w*w.y; acc[3][2] += a.w*w.z; acc[3][3] += a.w*w.w;
            }
            __syncthreads();
        }
        #pragma unroll
        for (int i = 0; i < 4; ++i)
            #pragma unroll
            for (int j = 0; j < 4; ++j)
                g_Xd[(rb*64 + ty*4 + i)*MM + ob*64 + tx*4 + j] = acc[i][j];
    }
    int idx = blockIdx.x * 256 + tid;
    g_h[0][idx] = 0.f; g_h[1][idx] = 0.f;
    g_c[0][idx] = 0.f; g_c[1][idx] = 0.f;
}

// ---------------- decoder sub-phase: h-gates GEMM (K=256) -> g_gpre ----------------
__device__ __forceinline__ void ph_gates_h(const float* __restrict__ Whh, int par, SmGates& s) {
    int bb = blockIdx.x >> 4, mo = blockIdx.x & 15;
    int tid = threadIdx.x;
    int kg = tid >> 7;
    int t128 = tid & 127;
    int ty = t128 >> 4, tx = t128 & 15;
    ull acc[2][2] = {{0ull, 0ull}, {0ull, 0ull}};
    const float* hsrc = g_h[par];
    int kbase = kg * 128;
    float ra[4];

    #define GH_LOAD_A(c) do {                                                  \
        int kc = kbase + (c)*32;                                               \
        _Pragma("unroll")                                                      \
        for (int u = 0; u < 4; ++u) {                                          \
            int idx = t128 + u*128;                                            \
            int row = idx >> 5, kk = idx & 31;                                 \
            ra[u] = __ldcg(hsrc + (bb*16 + row)*MM + kc + kk);                 \
        }                                                                      \
    } while (0)
    #define GH_STORE_A(st) do {                                                \
        _Pragma("unroll")                                                      \
        for (int u = 0; u < 4; ++u) {                                          \
            int idx = t128 + u*128;                                            \
            s.A[st][kg][idx & 31][idx >> 5] = ra[u];                           \
        }                                                                      \
    } while (0)
    #define GH_ISSUE_W(c, st) do {                                             \
        int kc = kbase + (c)*32;                                               \
        _Pragma("unroll")                                                      \
        for (int u = 0; u < 16; ++u) {                                         \
            int idx = t128 + u*128;                                            \
            int co = idx >> 5, kk = idx & 31;                                  \
            int row = (co >> 4)*256 + mo*16 + (co & 15);                       \
            cp4(&s.W[st][kg][kk][co], Whh + row*256 + kc + kk);                \
        }                                                                      \
        cp_commit();                                                           \
    } while (0)

    GH_LOAD_A(0); GH_ISSUE_W(0, 0); GH_STORE_A(0);
    #pragma unroll
    for (int c = 0; c < 4; ++c) {
        int st = c & 1;
        if (c < 3) { GH_ISSUE_W(c + 1, st ^ 1); GH_LOAD_A(c + 1); cp_wait<1>(); }
        else       { cp_wait<0>(); }
        __syncthreads();
        #pragma unroll
        for (int kk = 0; kk < 32; ++kk) {
            float2 a = *(const float2*)&s.A[st][kg][kk][ty*2];
            float4 w = *(const float4*)&s.W[st][kg][kk][tx*4];
            ull ax = f2pack(a.x, a.x), ay = f2pack(a.y, a.y);
            ull w01 = f2pack(w.x, w.y), w23 = f2pack(w.z, w.w);
            ffma2(acc[0][0], ax, w01); ffma2(acc[0][1], ax, w23);
            ffma2(acc[1][0], ay, w01); ffma2(acc[1][1], ay, w23);
        }
        if (c < 3) GH_STORE_A(st ^ 1);
        __syncthreads();
    }
    #undef GH_LOAD_A
    #undef GH_STORE_A
    #undef GH_ISSUE_W

    if (kg == 0) {
        #pragma unroll
        for (int i = 0; i < 2; ++i) {
            *(float2*)&s.red[ty*2 + i][tx*4]     = f2unpack(acc[i][0]);
            *(float2*)&s.red[ty*2 + i][tx*4 + 2] = f2unpack(acc[i][1]);
        }
    }
    __syncthreads();
    if (kg == 1) {
        #pragma unroll
        for (int i = 0; i < 2; ++i) {
            float2 v0 = f2unpack(acc[i][0]), v1 = f2unpack(acc[i][1]);
            float2 c0 = *(float2*)&s.red[ty*2 + i][tx*4];
            float2 c1 = *(float2*)&s.red[ty*2 + i][tx*4 + 2];
            c0.x += v0.x; c0.y += v0.y; c1.x += v1.x; c1.y += v1.y;
            *(float2*)&s.red[ty*2 + i][tx*4]     = c0;
            *(float2*)&s.red[ty*2 + i][tx*4 + 2] = c1;
        }
    }
    __syncthreads();
    for (int p = tid; p < 1024; p += 256) {
        int bi = p >> 6, co = p & 63;
        g_gpre[(bb*16 + bi)*1024 + mo*64 + co] = s.red[bi][co];
    }
}

// ---------------- decoder phase D1: hsW GEMM + h-gates GEMM ----------------
__device__ __forceinline__ void ph_dec_d1(const float* __restrict__ WU_d,
                                          const float* __restrict__ Whh_d,
                                          int par, SmAll& sm) {
    {
        SmHsw& s = sm.h;
        int rb = blockIdx.x >> 4, ob = blockIdx.x & 15;
        int tid = threadIdx.x;
        int kg = tid >> 7;
        int t128 = tid & 127;
        int ty = t128 >> 4, tx = t128 & 15;
        ull acc = 0ull;
        int kbase = kg * 256;
        for (int c = 0; c < 8; ++c) {
            int kc = kbase + c*32;
            #pragma unroll
            for (int u = 0; u < 4; ++u) {
                int idx = t128 + u*128;
                int ri = idx >> 5, kk = idx & 31;
                int k = kc + kk, gb = rb*16 + ri;
                s.A[kg][kk][ri] = (k < 256) ? __ldcg(&g_h[par][gb*MM + k])
                                            : __ldcg(&g_c[par][gb*MM + k - 256]);
            }
            #pragma unroll
            for (int u = 0; u < 4; ++u) {
                int idx = t128 + u*128;
                int co = idx >> 5, kk = idx & 31;
                s.W[kg][kk][co] = WU_d[(ob*16 + co)*768 + kc + kk];
            }
            __syncthreads();
            #pragma unroll
            for (int kk = 0; kk < 32; ++kk) {
                float2 a = *(const float2*)&s.A[kg][kk][ty*2];
                float w = s.W[kg][kk][tx];
                ffma2(acc, f2pack(a.x, a.y), f2pack(w, w));
            }
            __syncthreads();
        }
        float2 v = f2unpack(acc);
        if (kg == 0) { s.red[ty*2][tx] = v.x; s.red[ty*2 + 1][tx] = v.y; }
        __syncthreads();
        if (kg == 1) { s.red[ty*2][tx] += v.x; s.red[ty*2 + 1][tx] += v.y; }
        __syncthreads();
        {
            int ri = tid >> 4, co = tid & 15;
            g_hsW[(rb*16 + ri)*MM + ob*16 + co] = s.red[ri][co];
        }
    }
    __syncthreads();
    ph_gates_h(Whh_d, par, sm.g);
}

// ---------------- decoder phase D2: attention + ctx + y_tilde + LSTM epilogue ----------------
__device__ __forceinline__ void ph_dec_att2(const float* __restrict__ inp,
                                            const float* __restrict__ v_d,
                                            const float* __restrict__ wbt,
                                            const float* __restrict__ Wihd,
                                            const float* __restrict__ bih,
                                            const float* __restrict__ bhh,
                                            int step, int par, SmDatt& s) {
    int b = blockIdx.x, tid = threadIdx.x;
    int w = tid >> 5, l = tid & 31;
    s.hsw[tid] = __ldcg(&g_hsW[b*MM + tid]);
    s.vds[tid] = v_d[tid];
    __syncthreads();
    for (int t = w; t < 64; t += 8) {
        const float* xd = g_Xd + (b*TT + t)*MM;
        float sv = 0.f;
        #pragma unroll
        for (int m = l; m < 256; m += 32) sv += s.vds[m] * tanh_apx(s.hsw[m] + xd[m]);
        sv = wredsum(sv);
        if (l == 0) s.l[t] = sv;
    }
    __syncthreads();
    if (tid < 32) {
        float a0 = s.l[tid], a1 = s.l[tid + 32];
        float mx = wredmax(fmaxf(a0, a1));
        mx = __shfl_sync(0xffffffffu, mx, 0);
        float p0 = __expf(a0 - mx), p1 = __expf(a1 - mx);
        float sm2 = wredsum(p0 + p1);
        sm2 = __shfl_sync(0xffffffffu, sm2, 0);
        s.beta[tid] = __fdividef(p0, sm2);
        s.beta[tid + 32] = __fdividef(p1, sm2);
    }
    __syncthreads();
    float c = 0.f;
    const float* xe = g_Xe + b*TT*MM + tid;
    #pragma unroll 8
    for (int t = 0; t < 64; ++t) c += s.beta[t] * xe[t*MM];
    g_ctx[b*MM + tid] = c;
    float part = wbt[1 + tid] * c;
    part = wredsum(part);
    if (l == 0) s.reds[w] = part;
    __syncthreads();
    if (tid == 0) {
        float tot = 0.f;
        #pragma unroll
        for (int i = 0; i < 8; ++i) tot += s.reds[i];
        s.yt = wbt[0] * inp[b*TT*INROW + step*INROW + 128] + tot;
    }
    __syncthreads();
    {
        float yt = s.yt;
        int mo = tid >> 4, ml = tid & 15, m = tid;
        const float* gp = g_gpre + b*1024 + mo*64;
        float gi = __ldcg(gp + ml)      + bih[m]       + bhh[m]       + yt*Wihd[m];
        float gf = __ldcg(gp + 16 + ml) + bih[256 + m] + bhh[256 + m] + yt*Wihd[256 + m];
        float gg = __ldcg(gp + 32 + ml) + bih[512 + m] + bhh[512 + m] + yt*Wihd[512 + m];
        float go = __ldcg(gp + 48 + ml) + bih[768 + m] + bhh[768 + m] + yt*Wihd[768 + m];
        float cold = __ldcg(&g_c[par][b*MM + m]);
        float cn = fast_sigm(gf)*cold + fast_sigm(gi)*fast_tanh(gg);
        float hn = fast_sigm(go)*fast_tanh(cn);
        g_c[par ^ 1][b*MM + m] = cn;
        g_h[par ^ 1][b*MM + m] = hn;
    }
}

// ---------------- phase: final projection ----------------
__device__ __forceinline__ void ph_final(const float* __restrict__ WbW,
                                         const float* __restrict__ Wbb,
                                         const float* __restrict__ vbW,
                                         const float* __restrict__ vbb,
                                         float* __restrict__ out, int par, SmFin& s) {
    int b = blockIdx.x, tid = threadIdx.x;
    int w = tid >> 5, l = tid & 31;
    s.hc[tid]       = __ldcg(&g_h[par][b*MM + tid]);
    s.hc[256 + tid] = __ldcg(&g_ctx[b*MM + tid]);
    __syncthreads();
    for (int p = w*32; p < w*32 + 32; ++p) {
        const float* row = WbW + p*512;
        float sv = 0.f;
        #pragma unroll
        for (int k = l; k < 512; k += 32) sv += s.hc[k] * row[k];
        sv = wredsum(sv);
        if (l == 0) s.hid[p] = sv + Wbb[p];
    }
    __syncthreads();
    float part = s.hid[tid] * vbW[tid];
    part = wredsum(part);
    if (l == 0) s.reds[w] = part;
    __syncthreads();
    if (tid == 0) {
        float tot = 0.f;
        #pragma unroll
        for (int i = 0; i < 8; ++i) tot += s.reds[i];
        out[b] = tot + vbb[0];
    }
}

// ---------------- persistent megakernel ----------------
__global__ void __launch_bounds__(256, 2) k_darnn(
        const float* __restrict__ inp,  const float* __restrict__ WU_e,
        const float* __restrict__ v_e,  const float* __restrict__ Wih_e,
        const float* __restrict__ Whh_e,const float* __restrict__ bih_e,
        const float* __restrict__ bhh_e,const float* __restrict__ WU_d,
        const float* __restrict__ v_d,  const float* __restrict__ wbt,
        const float* __restrict__ Wih_d,const float* __restrict__ Whh_d,
        const float* __restrict__ bih_d,const float* __restrict__ bhh_d,
        const float* __restrict__ WbW,  const float* __restrict__ Wbb,
        const float* __restrict__ vbW,  const float* __restrict__ vbb,
        float* __restrict__ out) {
    __shared__ SmAll sm;

    ph_xp(inp, WU_e, sm.xp);
    grid_sync();

    for (int s = 0; s < 64; ++s) {
        int par = s & 1;
        ph_enc_att(inp, WU_e, v_e, s, par, sm.a);
        grid_sync();
        ph_enc_gates(Wih_e, Whh_e, bih_e, bhh_e, s, par, sm.g);
        grid_sync();
    }

    ph_xd(WU_d, sm.xd);
    grid_sync();

    for (int s = 0; s < 63; ++s) {
        int par = s & 1;
        ph_dec_d1(WU_d, Whh_d, par, sm);
        grid_sync();
        ph_dec_att2(inp, v_d, wbt, Wih_d, bih_d, bhh_d, s, par, sm.d);
        grid_sync();
    }

    ph_final(WbW, Wbb, vbW, vbb, out, 1, sm.f);
}

// ---------------- launcher ----------------
extern "C" void kernel_launch(void* const* d_in, const int* in_sizes, int n_in,
                              void* d_out, int out_size) {
    const float* inp   = (const float*)d_in[0];
    const float* WU_e  = (const float*)d_in[1];
    const float* v_e   = (const float*)d_in[2];
    const float* Wih_e = (const float*)d_in[3];
    const float* Whh_e = (const float*)d_in[4];
    const float* bih_e = (const float*)d_in[5];
    const float* bhh_e = (const float*)d_in[6];
    const float* WU_d  = (const float*)d_in[7];
    const float* v_d   = (const float*)d_in[8];
    const float* wbt   = (const float*)d_in[9];
    const float* Wih_d = (const float*)d_in[10];
    const float* Whh_d = (const float*)d_in[11];
    const float* bih_d = (const float*)d_in[12];
    const float* bhh_d = (const float*)d_in[13];
    const float* WbW   = (const float*)d_in[14];
    const float* Wbb   = (const float*)d_in[15];
    const float* vbW   = (const float*)d_in[16];
    const float* vbb   = (const float*)d_in[17];
    float* out = (float*)d_out;

    k_darnn<<<NBLK, 256>>>(inp, WU_e, v_e, Wih_e, Whh_e, bih_e, bhh_e,
                           WU_d, v_d, wbt, Wih_d, Whh_d, bih_d, bhh_d,
                           WbW, Wbb, vbW, vbb, out);
}

// round 14
// speedup vs baseline: 1.0825x; 1.0012x over previous
#include <cuda_runtime.h>
#include <math.h>

#define BB 256
#define TT 64
#define NN 128
#define MM 256
#define INROW 129   // N + YD
#define NBLK 256

typedef unsigned long long ull;

// ---------------- scratch (device globals; no allocation) ----------------
__device__ float g_Xp[BB*TT*NN];     // immutable after xp
__device__ float g_Xe[BB*TT*MM];     // immutable after encode
__device__ float g_Xd[BB*TT*MM];     // immutable after xd
__device__ float g_h[2][BB*MM];      // mutable (ldcg)
__device__ float g_c[2][BB*MM];      // mutable (ldcg)
__device__ float g_xin[BB*NN];       // mutable (ldcg)
__device__ float g_hsW[BB*MM];       // mutable (ldcg)
__device__ float g_gpre[BB*1024];    // mutable (ldcg) dec gate preactivations (h-part)
__device__ float g_ctx[BB*MM];

// ---------------- grid barrier (release/acquire, single-thread arrival) ----------------
__device__ unsigned g_bar_count;
__device__ unsigned g_bar_gen;

__device__ __forceinline__ unsigned ld_acq(const unsigned* p) {
    unsigned v;
    asm volatile("ld.acquire.gpu.u32 %0, [%1];" : "=r"(v) : "l"(p) : "memory");
    return v;
}

__device__ __forceinline__ void grid_sync() {
    __syncthreads();
    if (threadIdx.x == 0) {
        unsigned gen = g_bar_gen;
        unsigned old;
        asm volatile("atom.add.release.gpu.u32 %0, [%1], 1;"
                     : "=r"(old) : "l"(&g_bar_count) : "memory");
        if (old == NBLK - 1) {
            g_bar_count = 0;
            asm volatile("st.release.gpu.u32 [%0], %1;"
                         :: "l"(&g_bar_gen), "r"(gen + 1) : "memory");
        } else {
            while (ld_acq(&g_bar_gen) == gen) { }
        }
    }
    __syncthreads();
}

// ---------------- math helpers ----------------
__device__ __forceinline__ float fast_sigm(float x) {
    return __fdividef(1.0f, 1.0f + __expf(-x));
}
__device__ __forceinline__ float fast_tanh(float x) {
    float e = __expf(2.0f * x);
    return 1.0f - __fdividef(2.0f, e + 1.0f);
}
// single-MUFU tanh — attention score loops only
__device__ __forceinline__ float tanh_apx(float x) {
    float y; asm("tanh.approx.f32 %0, %1;" : "=f"(y) : "f"(x)); return y;
}
__device__ __forceinline__ float wredsum(float v) {
    #pragma unroll
    for (int o = 16; o > 0; o >>= 1) v += __shfl_down_sync(0xffffffffu, v, o);
    return v;
}
__device__ __forceinline__ float wredmax(float v) {
    #pragma unroll
    for (int o = 16; o > 0; o >>= 1) v = fmaxf(v, __shfl_down_sync(0xffffffffu, v, o));
    return v;
}
__device__ __forceinline__ ull f2pack(float lo, float hi) {
    ull r; asm("mov.b64 %0, {%1, %2};" : "=l"(r) : "f"(lo), "f"(hi)); return r;
}
__device__ __forceinline__ void ffma2(ull& d, ull a, ull b) {
    asm("fma.rn.f32x2 %0, %1, %2, %3;" : "=l"(d) : "l"(a), "l"(b), "l"(d));
}
__device__ __forceinline__ float2 f2unpack(ull v) {
    float2 r; asm("mov.b64 {%0, %1}, %2;" : "=f"(r.x), "=f"(r.y) : "l"(v)); return r;
}
// L2-only async copy — weight streams must NOT thrash L1 (WU_e/Xp residency)
__device__ __forceinline__ void cp4(void* dst, const float* src) {
    unsigned d = (unsigned)__cvta_generic_to_shared(dst);
    asm volatile("cp.async.cg.shared.global [%0], [%1], 16;" :: "r"(d), "l"(src));
}
// 4-byte variant (cg requires 16B; keep a .ca 4B for the mixed-source A path)
__device__ __forceinline__ void cp4b(void* dst, const float* src) {
    unsigned d = (unsigned)__cvta_generic_to_shared(dst);
    asm volatile("cp.async.ca.shared.global [%0], [%1], 4;" :: "r"(d), "l"(src));
}
__device__ __forceinline__ void cp_commit() {
    asm volatile("cp.async.commit_group;" ::: "memory");
}
template <int N>
__device__ __forceinline__ void cp_wait() {
    asm volatile("cp.async.wait_group %0;" :: "n"(N) : "memory");
}
// streaming loads (evict-first): read-once-per-step big arrays
__device__ __forceinline__ float ldcs(const float* p) {
    float v; asm volatile("ld.global.cs.f32 %0, [%1];" : "=f"(v) : "l"(p)); return v;
}

// ---------------- shared memory union ----------------
struct SmGates { float A[2][2][32][18]; float W[2][2][32][68]; float red[16][66]; };
struct SmXp    { float WUx[4096]; float Xs[8192]; };
struct SmAtt   { float hs[512]; float hsW[64]; float ves[64]; float ep[128]; float redm[4]; float reds[4]; };
struct SmHsw   { float A[2][32][20]; float W[2][32][20]; float red[16][18]; };
struct SmXd    { float A[32][68]; float W[32][68]; };
struct SmDatt  { float hsw[256]; float vds[256]; float l[64]; float beta[64]; float reds[8]; float yt; };
struct SmFin   { float hc[512]; float hid[256]; float reds[8]; };
union SmAll {
    SmGates g; SmXp xp; SmAtt a; SmHsw h; SmXd xd; SmDatt d; SmFin f;
};

// ---------------- phase: Xp precompute (+ zero h/c) ----------------
__device__ __forceinline__ void ph_xp(const float* __restrict__ inp,
                                      const float* __restrict__ WU_e, SmXp& s) {
    int b = blockIdx.x, tid = threadIdx.x;
    {
        int idx = b * 256 + tid;
        g_h[0][idx] = 0.f; g_h[1][idx] = 0.f;
        g_c[0][idx] = 0.f; g_c[1][idx] = 0.f;
    }
    for (int idx = tid; idx < 4096; idx += 256) {
        int t = idx >> 6, tp = idx & 63;
        s.WUx[idx] = WU_e[t*576 + 512 + tp];
    }
    for (int idx = tid; idx < 8192; idx += 256) {
        int tp = idx >> 7, n = idx & 127;
        s.Xs[idx] = inp[b*TT*INROW + tp*INROW + n];
    }
    __syncthreads();
    int half = tid >> 7, n = tid & 127;
    float acc[32];
    #pragma unroll
    for (int t = 0; t < 32; ++t) acc[t] = 0.f;
    for (int tp = 0; tp < 64; ++tp) {
        float xv = s.Xs[tp*128 + n];
        #pragma unroll
        for (int t = 0; t < 32; ++t) acc[t] += xv * s.WUx[(half*32 + t)*64 + tp];
    }
    #pragma unroll
    for (int t = 0; t < 32; ++t) g_Xp[(b*TT + half*32 + t)*NN + n] = acc[t];
}

// ---------------- phase: encoder attention (hsW fused) ----------------
__device__ __forceinline__ void ph_enc_att(const float* __restrict__ inp,
                                           const float* __restrict__ WU_e,
                                           const float* __restrict__ v_e,
                                           int step, int par, SmAtt& s) {
    int b = blockIdx.x, tid = threadIdx.x;
    int w = tid >> 5, l = tid & 31;
    s.hs[tid]       = __ldcg(&g_h[par][b*MM + tid]);
    s.hs[tid + 256] = __ldcg(&g_c[par][b*MM + tid]);
    if (tid < 64) s.ves[tid] = v_e[tid];
    __syncthreads();
    #pragma unroll
    for (int t = w*8; t < w*8 + 8; ++t) {
        const float* row = WU_e + t*576;
        float sv = 0.f;
        #pragma unroll
        for (int k = l; k < 512; k += 32) sv += s.hs[k] * row[k];
        sv = wredsum(sv);
        if (l == 0) s.hsW[t] = sv;
    }
    __syncthreads();
    int half = tid >> 7, n = tid & 127;
    float e = 0.f;
    {
        const float* xp = g_Xp + b*TT*NN + half*32*NN + n;
        const float* vh = s.ves + half*32;
        const float* hh = s.hsW + half*32;
        #pragma unroll 8
        for (int t = 0; t < 32; ++t) e += vh[t] * tanh_apx(hh[t] + xp[t*NN]);
    }
    if (half == 1) s.ep[n] = e;
    __syncthreads();
    float p = 0.f;
    if (half == 0) {
        e += s.ep[n];
        float m = wredmax(e);
        if (l == 0) s.redm[w] = m;
    }
    __syncthreads();
    if (half == 0) {
        float m = fmaxf(fmaxf(s.redm[0], s.redm[1]), fmaxf(s.redm[2], s.redm[3]));
        p = __expf(e - m);
        float sv = wredsum(p);
        if (l == 0) s.reds[w] = sv;
    }
    __syncthreads();
    if (half == 0) {
        float tot = s.reds[0] + s.reds[1] + s.reds[2] + s.reds[3];
        float alpha = __fdividef(p, tot);
        g_xin[b*NN + n] = inp[b*TT*INROW + step*INROW + n] * alpha;
    }
}

// ---------------- phase: encoder gates GEMM + LSTM ----------------
__device__ __forceinline__ void ph_enc_gates(const float* __restrict__ Wih,
                                             const float* __restrict__ Whh,
                                             const float* __restrict__ bih,
                                             const float* __restrict__ bhh,
                                             int step, int par, SmGates& s) {
    int bb = blockIdx.x >> 4, mo = blockIdx.x & 15;
    int tid = threadIdx.x;
    int kg = tid >> 7;
    int t128 = tid & 127;
    int ty = t128 >> 4, tx = t128 & 15;
    ull acc[2][2] = {{0ull, 0ull}, {0ull, 0ull}};
    const float* hsrc = g_h[par];
    int kbase = kg * 192;
    float ra[4];

    // W rows are contiguous 128/256-float rows; each thread copies 16B-aligned
    // quads: thread t handles (co, kk4) with kk4 = 4-aligned k offset.
    // layout match: W[st][kg][kk..kk+3][co] is NOT contiguous, so keep per-4B
    // issue for A and 16B .cg for W via 4 consecutive kk? W smem is [kk][co]
    // (kk outer) — 16B contiguous in co. Global W row is contiguous in k.
    // So a 16B copy must be 4 consecutive co from 4 consecutive k — mismatch.
    // => use 4B .cg copies for W (cp.async cg requires 16B; fall back to
    //    evict-last hint via ld+sts is worse). Use inline 4B variant with .cg
    //    not allowed — so: keep 4B .ca for A path, and for W use 4B copies with
    //    L2 hint via "cp.async.ca.shared.global.L2::256B" prefetch variant.
    #define ENC_LOAD_A(c) do {                                                 \
        int kc = kbase + (c)*32;                                               \
        _Pragma("unroll")                                                      \
        for (int u = 0; u < 4; ++u) {                                          \
            int idx = t128 + u*128;                                            \
            int row = idx >> 5, kk = idx & 31;                                 \
            int k = kc + kk, gb = bb*16 + row;                                 \
            ra[u] = (k < 128) ? __ldcg(g_xin + gb*NN + k)                      \
                              : __ldcg(hsrc + gb*MM + (k - 128));              \
        }                                                                      \
    } while (0)
    #define ENC_STORE_A(st) do {                                               \
        _Pragma("unroll")                                                      \
        for (int u = 0; u < 4; ++u) {                                          \
            int idx = t128 + u*128;                                            \
            s.A[st][kg][idx & 31][idx >> 5] = ra[u];                           \
        }                                                                      \
    } while (0)
    // W tile: copy as 16B quads along k into [co][k-quad]-style slots:
    // reorganize index so each thread copies W row segment of 4 k's for one co,
    // storing into 4 separate [kk][co] slots via 4B stores is required anyway.
    // Simplest correct .cg usage: 16B along *co* requires gathering 4 k-rows —
    // not possible. So stream W through L2 with ld.global.cg + st.shared.
    #define ENC_ISSUE_W(c, st) do {                                            \
        int kc = kbase + (c)*32;                                               \
        _Pragma("unroll")                                                      \
        for (int u = 0; u < 16; ++u) {                                         \
            int idx = t128 + u*128;                                            \
            int co = idx >> 5, kk = idx & 31;                                  \
            int row = (co >> 4)*256 + mo*16 + (co & 15);                       \
            int k = kc + kk;                                                   \
            const float* src = (k < 128) ? (Wih + row*128 + k)                 \
                                         : (Whh + row*256 + (k - 128));        \
            s.W[st][kg][kk][co] = __ldcg(src);                                 \
        }                                                                      \
    } while (0)

    ENC_LOAD_A(0); ENC_ISSUE_W(0, 0); ENC_STORE_A(0);
    __syncthreads();
    #pragma unroll
    for (int c = 0; c < 6; ++c) {
        int st = c & 1;
        if (c < 5) { ENC_LOAD_A(c + 1); }
        #pragma unroll
        for (int kk = 0; kk < 32; ++kk) {
            float2 a = *(const float2*)&s.A[st][kg][kk][ty*2];
            float4 w = *(const float4*)&s.W[st][kg][kk][tx*4];
            ull ax = f2pack(a.x, a.x), ay = f2pack(a.y, a.y);
            ull w01 = f2pack(w.x, w.y), w23 = f2pack(w.z, w.w);
            ffma2(acc[0][0], ax, w01); ffma2(acc[0][1], ax, w23);
            ffma2(acc[1][0], ay, w01); ffma2(acc[1][1], ay, w23);
        }
        if (c < 5) {
            ENC_ISSUE_W(c + 1, st ^ 1);
            ENC_STORE_A(st ^ 1);
            __syncthreads();
        }
    }
    #undef ENC_LOAD_A
    #undef ENC_STORE_A
    #undef ENC_ISSUE_W
    __syncthreads();

    if (kg == 0) {
        #pragma unroll
        for (int i = 0; i < 2; ++i) {
            *(float2*)&s.red[ty*2 + i][tx*4]     = f2unpack(acc[i][0]);
            *(float2*)&s.red[ty*2 + i][tx*4 + 2] = f2unpack(acc[i][1]);
        }
    }
    __syncthreads();
    if (kg == 1) {
        #pragma unroll
        for (int i = 0; i < 2; ++i) {
            float2 v0 = f2unpack(acc[i][0]), v1 = f2unpack(acc[i][1]);
            float2 c0 = *(float2*)&s.red[ty*2 + i][tx*4];
            float2 c1 = *(float2*)&s.red[ty*2 + i][tx*4 + 2];
            c0.x += v0.x; c0.y += v0.y; c1.x += v1.x; c1.y += v1.y;
            *(float2*)&s.red[ty*2 + i][tx*4]     = c0;
            *(float2*)&s.red[ty*2 + i][tx*4 + 2] = c1;
        }
    }
    __syncthreads();
    {
        int bi = tid >> 4, ml = tid & 15;
        int gb = bb*16 + bi, m = mo*16 + ml;
        float gi = s.red[bi][ml]      + bih[m]       + bhh[m];
        float gf = s.red[bi][16 + ml] + bih[256 + m] + bhh[256 + m];
        float gg = s.red[bi][32 + ml] + bih[512 + m] + bhh[512 + m];
        float go = s.red[bi][48 + ml] + bih[768 + m] + bhh[768 + m];
        float cold = __ldcg(&g_c[par][gb*MM + m]);
        float cn = fast_sigm(gf)*cold + fast_sigm(gi)*fast_tanh(gg);
        float hn = fast_sigm(go)*fast_tanh(cn);
        g_c[par ^ 1][gb*MM + m] = cn;
        g_h[par ^ 1][gb*MM + m] = hn;
        g_Xe[(gb*TT + step)*MM + m] = hn;
    }
}

// ---------------- phase: Xd precompute (+ re-zero h/c) ----------------
__device__ __forceinline__ void ph_xd(const float* __restrict__ WU_d, SmXd& s) {
    int rb = blockIdx.x, tid = threadIdx.x;
    int ty = tid >> 4, tx = tid & 15;
    for (int ob = 0; ob < 4; ++ob) {
        float acc[4][4];
        #pragma unroll
        for (int i = 0; i < 4; ++i)
            #pragma unroll
            for (int j = 0; j < 4; ++j) acc[i][j] = 0.f;
        for (int kc = 0; kc < 256; kc += 32) {
            for (int idx = tid; idx < 2048; idx += 256) {
                int ri = idx >> 5, kk = idx & 31;
                s.A[kk][ri] = g_Xe[(rb*64 + ri)*MM + kc + kk];
            }
            for (int idx = tid; idx < 2048; idx += 256) {
                int co = idx >> 5, kk = idx & 31;
                s.W[kk][co] = WU_d[(ob*64 + co)*768 + 512 + kc + kk];
            }
            __syncthreads();
            #pragma unroll
            for (int kk = 0; kk < 32; ++kk) {
                float4 a = *(const float4*)&s.A[kk][ty*4];
                float4 w = *(const float4*)&s.W[kk][tx*4];
                acc[0][0] += a.x*w.x; acc[0][1] += a.x*w.y; acc[0][2] += a.x*w.z; acc[0][3] += a.x*w.w;
                acc[1][0] += a.y*w.x; acc[1][1] += a.y*w.y; acc[1][2] += a.y*w.z; acc[1][3] += a.y*w.w;
                acc[2][0] += a.z*w.x; acc[2][1] += a.z*w.y; acc[2][2] += a.z*w.z; acc[2][3] += a.z*w.w;
                acc[3][0] += a.w*w.x; acc[3][1] += a.w*w.y; acc[3][2] += a.w*w.z; acc[3][3] += a.w*w.w;
            }
            __syncthreads();
        }
        #pragma unroll
        for (int i = 0; i < 4; ++i)
            #pragma unroll
            for (int j = 0; j < 4; ++j)
                g_Xd[(rb*64 + ty*4 + i)*MM + ob*64 + tx*4 + j] = acc[i][j];
    }
    int idx = blockIdx.x * 256 + tid;
    g_h[0][idx] = 0.f; g_h[1][idx] = 0.f;
    g_c[0][idx] = 0.f; g_c[1][idx] = 0.f;
}

// ---------------- decoder sub-phase: h-gates GEMM (K=256) -> g_gpre ----------------
__device__ __forceinline__ void ph_gates_h(const float* __restrict__ Whh, int par, SmGates& s) {
    int bb = blockIdx.x >> 4, mo = blockIdx.x & 15;
    int tid = threadIdx.x;
    int kg = tid >> 7;
    int t128 = tid & 127;
    int ty = t128 >> 4, tx = t128 & 15;
    ull acc[2][2] = {{0ull, 0ull}, {0ull, 0ull}};
    const float* hsrc = g_h[par];
    int kbase = kg * 128;
    float ra[4];

    #define GH_LOAD_A(c) do {                                                  \
        int kc = kbase + (c)*32;                                               \
        _Pragma("unroll")                                                      \
        for (int u = 0; u < 4; ++u) {                                          \
            int idx = t128 + u*128;                                            \
            int row = idx >> 5, kk = idx & 31;                                 \
            ra[u] = __ldcg(hsrc + (bb*16 + row)*MM + kc + kk);                 \
        }                                                                      \
    } while (0)
    #define GH_STORE_A(st) do {                                                \
        _Pragma("unroll")                                                      \
        for (int u = 0; u < 4; ++u) {                                          \
            int idx = t128 + u*128;                                            \
            s.A[st][kg][idx & 31][idx >> 5] = ra[u];                           \
        }                                                                      \
    } while (0)
    #define GH_ISSUE_W(c, st) do {                                             \
        int kc = kbase + (c)*32;                                               \
        _Pragma("unroll")                                                      \
        for (int u = 0; u < 16; ++u) {                                         \
            int idx = t128 + u*128;                                            \
            int co = idx >> 5, kk = idx & 31;                                  \
            int row = (co >> 4)*256 + mo*16 + (co & 15);                       \
            s.W[st][kg][kk][co] = __ldcg(Whh + row*256 + kc + kk);             \
        }                                                                      \
    } while (0)

    GH_LOAD_A(0); GH_ISSUE_W(0, 0); GH_STORE_A(0);
    __syncthreads();
    #pragma unroll
    for (int c = 0; c < 4; ++c) {
        int st = c & 1;
        if (c < 3) { GH_LOAD_A(c + 1); }
        #pragma unroll
        for (int kk = 0; kk < 32; ++kk) {
            float2 a = *(const float2*)&s.A[st][kg][kk][ty*2];
            float4 w = *(const float4*)&s.W[st][kg][kk][tx*4];
            ull ax = f2pack(a.x, a.x), ay = f2pack(a.y, a.y);
            ull w01 = f2pack(w.x, w.y), w23 = f2pack(w.z, w.w);
            ffma2(acc[0][0], ax, w01); ffma2(acc[0][1], ax, w23);
            ffma2(acc[1][0], ay, w01); ffma2(acc[1][1], ay, w23);
        }
        if (c < 3) {
            GH_ISSUE_W(c + 1, st ^ 1);
            GH_STORE_A(st ^ 1);
            __syncthreads();
        }
    }
    #undef GH_LOAD_A
    #undef GH_STORE_A
    #undef GH_ISSUE_W
    __syncthreads();

    if (kg == 0) {
        #pragma unroll
        for (int i = 0; i < 2; ++i) {
            *(float2*)&s.red[ty*2 + i][tx*4]     = f2unpack(acc[i][0]);
            *(float2*)&s.red[ty*2 + i][tx*4 + 2] = f2unpack(acc[i][1]);
        }
    }
    __syncthreads();
    if (kg == 1) {
        #pragma unroll
        for (int i = 0; i < 2; ++i) {
            float2 v0 = f2unpack(acc[i][0]), v1 = f2unpack(acc[i][1]);
            float2 c0 = *(float2*)&s.red[ty*2 + i][tx*4];
            float2 c1 = *(float2*)&s.red[ty*2 + i][tx*4 + 2];
            c0.x += v0.x; c0.y += v0.y; c1.x += v1.x; c1.y += v1.y;
            *(float2*)&s.red[ty*2 + i][tx*4]     = c0;
            *(float2*)&s.red[ty*2 + i][tx*4 + 2] = c1;
        }
    }
    __syncthreads();
    for (int p = tid; p < 1024; p += 256) {
        int bi = p >> 6, co = p & 63;
        g_gpre[(bb*16 + bi)*1024 + mo*64 + co] = s.red[bi][co];
    }
}

// ---------------- decoder phase D1: hsW GEMM + h-gates GEMM ----------------
__device__ __forceinline__ void ph_dec_d1(const float* __restrict__ WU_d,
                                          const float* __restrict__ Whh_d,
                                          int par, SmAll& sm) {
    {
        SmHsw& s = sm.h;
        int rb = blockIdx.x >> 4, ob = blockIdx.x & 15;
        int tid = threadIdx.x;
        int kg = tid >> 7;
        int t128 = tid & 127;
        int ty = t128 >> 4, tx = t128 & 15;
        ull acc = 0ull;
        int kbase = kg * 256;
        for (int c = 0; c < 8; ++c) {
            int kc = kbase + c*32;
            #pragma unroll
            for (int u = 0; u < 4; ++u) {
                int idx = t128 + u*128;
                int ri = idx >> 5, kk = idx & 31;
                int k = kc + kk, gb = rb*16 + ri;
                s.A[kg][kk][ri] = (k < 256) ? __ldcg(&g_h[par][gb*MM + k])
                                            : __ldcg(&g_c[par][gb*MM + k - 256]);
            }
            #pragma unroll
            for (int u = 0; u < 4; ++u) {
                int idx = t128 + u*128;
                int co = idx >> 5, kk = idx & 31;
                s.W[kg][kk][co] = __ldcg(WU_d + (ob*16 + co)*768 + kc + kk);
            }
            __syncthreads();
            #pragma unroll
            for (int kk = 0; kk < 32; ++kk) {
                float2 a = *(const float2*)&s.A[kg][kk][ty*2];
                float w = s.W[kg][kk][tx];
                ffma2(acc, f2pack(a.x, a.y), f2pack(w, w));
            }
            __syncthreads();
        }
        float2 v = f2unpack(acc);
        if (kg == 0) { s.red[ty*2][tx] = v.x; s.red[ty*2 + 1][tx] = v.y; }
        __syncthreads();
        if (kg == 1) { s.red[ty*2][tx] += v.x; s.red[ty*2 + 1][tx] += v.y; }
        __syncthreads();
        {
            int ri = tid >> 4, co = tid & 15;
            g_hsW[(rb*16 + ri)*MM + ob*16 + co] = s.red[ri][co];
        }
    }
    __syncthreads();
    ph_gates_h(Whh_d, par, sm.g);
}

// ---------------- decoder phase D2: attention + ctx + y_tilde + LSTM epilogue ----------------
__device__ __forceinline__ void ph_dec_att2(const float* __restrict__ inp,
                                            const float* __restrict__ v_d,
                                            const float* __restrict__ wbt,
                                            const float* __restrict__ Wihd,
                                            const float* __restrict__ bih,
                                            const float* __restrict__ bhh,
                                            int step, int par, SmDatt& s) {
    int b = blockIdx.x, tid = threadIdx.x;
    int w = tid >> 5, l = tid & 31;
    s.hsw[tid] = __ldcg(&g_hsW[b*MM + tid]);
    s.vds[tid] = v_d[tid];
    __syncthreads();
    for (int t = w; t < 64; t += 8) {
        const float* xd = g_Xd + (b*TT + t)*MM;
        float sv = 0.f;
        #pragma unroll
        for (int m = l; m < 256; m += 32) sv += s.vds[m] * tanh_apx(s.hsw[m] + ldcs(xd + m));
        sv = wredsum(sv);
        if (l == 0) s.l[t] = sv;
    }
    __syncthreads();
    if (tid < 32) {
        float a0 = s.l[tid], a1 = s.l[tid + 32];
        float mx = wredmax(fmaxf(a0, a1));
        mx = __shfl_sync(0xffffffffu, mx, 0);
        float p0 = __expf(a0 - mx), p1 = __expf(a1 - mx);
        float sm2 = wredsum(p0 + p1);
        sm2 = __shfl_sync(0xffffffffu, sm2, 0);
        s.beta[tid] = __fdividef(p0, sm2);
        s.beta[tid + 32] = __fdividef(p1, sm2);
    }
    __syncthreads();
    float c = 0.f;
    const float* xe = g_Xe + b*TT*MM + tid;
    #pragma unroll 8
    for (int t = 0; t < 64; ++t) c += s.beta[t] * ldcs(xe + t*MM);
    g_ctx[b*MM + tid] = c;
    float part = wbt[1 + tid] * c;
    part = wredsum(part);
    if (l == 0) s.reds[w] = part;
    __syncthreads();
    if (tid == 0) {
        float tot = 0.f;
        #pragma unroll
        for (int i = 0; i < 8; ++i) tot += s.reds[i];
        s.yt = wbt[0] * inp[b*TT*INROW + step*INROW + 128] + tot;
    }
    __syncthreads();
    {
        float yt = s.yt;
        int mo = tid >> 4, ml = tid & 15, m = tid;
        const float* gp = g_gpre + b*1024 + mo*64;
        float gi = __ldcg(gp + ml)      + bih[m]       + bhh[m]       + yt*Wihd[m];
        float gf = __ldcg(gp + 16 + ml) + bih[256 + m] + bhh[256 + m] + yt*Wihd[256 + m];
        float gg = __ldcg(gp + 32 + ml) + bih[512 + m] + bhh[512 + m] + yt*Wihd[512 + m];
        float go = __ldcg(gp + 48 + ml) + bih[768 + m] + bhh[768 + m] + yt*Wihd[768 + m];
        float cold = __ldcg(&g_c[par][b*MM + m]);
        float cn = fast_sigm(gf)*cold + fast_sigm(gi)*fast_tanh(gg);
        float hn = fast_sigm(go)*fast_tanh(cn);
        g_c[par ^ 1][b*MM + m] = cn;
        g_h[par ^ 1][b*MM + m] = hn;
    }
}

// ---------------- phase: final projection ----------------
__device__ __forceinline__ void ph_final(const float* __restrict__ WbW,
                                         const float* __restrict__ Wbb,
                                         const float* __restrict__ vbW,
                                         const float* __restrict__ vbb,
                                         float* __restrict__ out, int par, SmFin& s) {
    int b = blockIdx.x, tid = threadIdx.x;
    int w = tid >> 5, l = tid & 31;
    s.hc[tid]       = __ldcg(&g_h[par][b*MM + tid]);
    s.hc[256 + tid] = __ldcg(&g_ctx[b*MM + tid]);
    __syncthreads();
    for (int p = w*32; p < w*32 + 32; ++p) {
        const float* row = WbW + p*512;
        float sv = 0.f;
        #pragma unroll
        for (int k = l; k < 512; k += 32) sv += s.hc[k] * row[k];
        sv = wredsum(sv);
        if (l == 0) s.hid[p] = sv + Wbb[p];
    }
    __syncthreads();
    float part = s.hid[tid] * vbW[tid];
    part = wredsum(part);
    if (l == 0) s.reds[w] = part;
    __syncthreads();
    if (tid == 0) {
        float tot = 0.f;
        #pragma unroll
        for (int i = 0; i < 8; ++i) tot += s.reds[i];
        out[b] = tot + vbb[0];
    }
}

// ---------------- persistent megakernel ----------------
__global__ void __launch_bounds__(256, 2) k_darnn(
        const float* __restrict__ inp,  const float* __restrict__ WU_e,
        const float* __restrict__ v_e,  const float* __restrict__ Wih_e,
        const float* __restrict__ Whh_e,const float* __restrict__ bih_e,
        const float* __restrict__ bhh_e,const float* __restrict__ WU_d,
        const float* __restrict__ v_d,  const float* __restrict__ wbt,
        const float* __restrict__ Wih_d,const float* __restrict__ Whh_d,
        const float* __restrict__ bih_d,const float* __restrict__ bhh_d,
        const float* __restrict__ WbW,  const float* __restrict__ Wbb,
        const float* __restrict__ vbW,  const float* __restrict__ vbb,
        float* __restrict__ out) {
    __shared__ SmAll sm;

    ph_xp(inp, WU_e, sm.xp);
    grid_sync();

    for (int s = 0; s < 64; ++s) {
        int par = s & 1;
        ph_enc_att(inp, WU_e, v_e, s, par, sm.a);
        grid_sync();
        ph_enc_gates(Wih_e, Whh_e, bih_e, bhh_e, s, par, sm.g);
        grid_sync();
    }

    ph_xd(WU_d, sm.xd);
    grid_sync();

    for (int s = 0; s < 63; ++s) {
        int par = s & 1;
        ph_dec_d1(WU_d, Whh_d, par, sm);
        grid_sync();
        ph_dec_att2(inp, v_d, wbt, Wih_d, bih_d, bhh_d, s, par, sm.d);
        grid_sync();
    }

    ph_final(WbW, Wbb, vbW, vbb, out, 1, sm.f);
}

// ---------------- launcher ----------------
extern "C" void kernel_launch(void* const* d_in, const int* in_sizes, int n_in,
                              void* d_out, int out_size) {
    const float* inp   = (const float*)d_in[0];
    const float* WU_e  = (const float*)d_in[1];
    const float* v_e   = (const float*)d_in[2];
    const float* Wih_e = (const float*)d_in[3];
    const float* Whh_e = (const float*)d_in[4];
    const float* bih_e = (const float*)d_in[5];
    const float* bhh_e = (const float*)d_in[6];
    const float* WU_d  = (const float*)d_in[7];
    const float* v_d   = (const float*)d_in[8];
    const float* wbt   = (const float*)d_in[9];
    const float* Wih_d = (const float*)d_in[10];
    const float* Whh_d = (const float*)d_in[11];
    const float* bih_d = (const float*)d_in[12];
    const float* bhh_d = (const float*)d_in[13];
    const float* WbW   = (const float*)d_in[14];
    const float* Wbb   = (const float*)d_in[15];
    const float* vbW   = (const float*)d_in[16];
    const float* vbb   = (const float*)d_in[17];
    float* out = (float*)d_out;

    k_darnn<<<NBLK, 256>>>(inp, WU_e, v_e, Wih_e, Whh_e, bih_e, bhh_e,
                           WU_d, v_d, wbt, Wih_d, Whh_d, bih_d, bhh_d,
                           WbW, Wbb, vbW, vbb, out);
}

// round 15
// speedup vs baseline: 1.2149x; 1.1222x over previous
#include <cuda_runtime.h>
#include <math.h>

#define BB 256
#define TT 64
#define NN 128
#define MM 256
#define INROW 129   // N + YD
#define NBLK 256

typedef unsigned long long ull;

// ---------------- scratch (device globals; no allocation) ----------------
__device__ float g_Xp[BB*TT*NN];     // immutable after xp
__device__ float g_Xe[BB*TT*MM];     // immutable after encode
__device__ float g_Xd[BB*TT*MM];     // immutable after xd
__device__ float g_h[2][BB*MM];      // mutable (ldcg)
__device__ float g_c[2][BB*MM];      // mutable (ldcg)
__device__ float g_xin[BB*NN];       // mutable (ldcg)
__device__ float g_hsW[BB*MM];       // mutable (ldcg)
__device__ float g_gpre[BB*1024];    // mutable (ldcg) gate preactivations (h-part)
__device__ float g_ctx[BB*MM];

// ---------------- grid barrier (release/acquire, single-thread arrival) ----------------
__device__ unsigned g_bar_count;
__device__ unsigned g_bar_gen;

__device__ __forceinline__ unsigned ld_acq(const unsigned* p) {
    unsigned v;
    asm volatile("ld.acquire.gpu.u32 %0, [%1];" : "=r"(v) : "l"(p) : "memory");
    return v;
}

__device__ __forceinline__ void grid_sync() {
    __syncthreads();
    if (threadIdx.x == 0) {
        unsigned gen = g_bar_gen;
        unsigned old;
        asm volatile("atom.add.release.gpu.u32 %0, [%1], 1;"
                     : "=r"(old) : "l"(&g_bar_count) : "memory");
        if (old == NBLK - 1) {
            g_bar_count = 0;
            asm volatile("st.release.gpu.u32 [%0], %1;"
                         :: "l"(&g_bar_gen), "r"(gen + 1) : "memory");
        } else {
            while (ld_acq(&g_bar_gen) == gen) { }
        }
    }
    __syncthreads();
}

// ---------------- math helpers ----------------
__device__ __forceinline__ float fast_sigm(float x) {
    return __fdividef(1.0f, 1.0f + __expf(-x));
}
__device__ __forceinline__ float fast_tanh(float x) {
    float e = __expf(2.0f * x);
    return 1.0f - __fdividef(2.0f, e + 1.0f);
}
// single-MUFU tanh — attention score loops only
__device__ __forceinline__ float tanh_apx(float x) {
    float y; asm("tanh.approx.f32 %0, %1;" : "=f"(y) : "f"(x)); return y;
}
__device__ __forceinline__ float wredsum(float v) {
    #pragma unroll
    for (int o = 16; o > 0; o >>= 1) v += __shfl_down_sync(0xffffffffu, v, o);
    return v;
}
__device__ __forceinline__ float wredmax(float v) {
    #pragma unroll
    for (int o = 16; o > 0; o >>= 1) v = fmaxf(v, __shfl_down_sync(0xffffffffu, v, o));
    return v;
}
__device__ __forceinline__ ull f2pack(float lo, float hi) {
    ull r; asm("mov.b64 %0, {%1, %2};" : "=l"(r) : "f"(lo), "f"(hi)); return r;
}
__device__ __forceinline__ void ffma2(ull& d, ull a, ull b) {
    asm("fma.rn.f32x2 %0, %1, %2, %3;" : "=l"(d) : "l"(a), "l"(b), "l"(d));
}
__device__ __forceinline__ float2 f2unpack(ull v) {
    float2 r; asm("mov.b64 {%0, %1}, %2;" : "=f"(r.x), "=f"(r.y) : "l"(v)); return r;
}
__device__ __forceinline__ float ldcs(const float* p) {
    float v; asm volatile("ld.global.cs.f32 %0, [%1];" : "=f"(v) : "l"(p)); return v;
}

// ---------------- shared memory union ----------------
struct SmGates { float A[2][2][32][18]; float W[2][2][32][68]; float red[16][66]; };
struct SmG32   { float A[2][32][36]; float W[2][32][68]; float red[32][66]; };
struct SmHsw2  { float A[2][32][18]; float W[2][32][34]; float red[16][33]; };
struct SmXp    { float WUx[4096]; float Xs[8192]; };
struct SmAtt   { float hs[512]; float hsW[64]; float ves[64]; float ep[128]; float redm[4]; float reds[4]; };
struct SmXd    { float A[32][68]; float W[32][68]; };
struct SmDatt  { float hsw[256]; float vds[256]; float l[64]; float beta[64]; float reds[8]; float yt; };
struct SmFin   { float hc[512]; float hid[256]; float reds[8]; };
union SmAll {
    SmGates g; SmG32 g32; SmHsw2 h2; SmXp xp; SmAtt a; SmXd xd; SmDatt d; SmFin f;
};

// ---------------- phase: Xp precompute (+ zero h/c) ----------------
__device__ __forceinline__ void ph_xp(const float* __restrict__ inp,
                                      const float* __restrict__ WU_e, SmXp& s) {
    int b = blockIdx.x, tid = threadIdx.x;
    {
        int idx = b * 256 + tid;
        g_h[0][idx] = 0.f; g_h[1][idx] = 0.f;
        g_c[0][idx] = 0.f; g_c[1][idx] = 0.f;
    }
    for (int idx = tid; idx < 4096; idx += 256) {
        int t = idx >> 6, tp = idx & 63;
        s.WUx[idx] = WU_e[t*576 + 512 + tp];
    }
    for (int idx = tid; idx < 8192; idx += 256) {
        int tp = idx >> 7, n = idx & 127;
        s.Xs[idx] = inp[b*TT*INROW + tp*INROW + n];
    }
    __syncthreads();
    int half = tid >> 7, n = tid & 127;
    float acc[32];
    #pragma unroll
    for (int t = 0; t < 32; ++t) acc[t] = 0.f;
    for (int tp = 0; tp < 64; ++tp) {
        float xv = s.Xs[tp*128 + n];
        #pragma unroll
        for (int t = 0; t < 32; ++t) acc[t] += xv * s.WUx[(half*32 + t)*64 + tp];
    }
    #pragma unroll
    for (int t = 0; t < 32; ++t) g_Xp[(b*TT + half*32 + t)*NN + n] = acc[t];
}

// ---------------- sub: encoder attention body for batch b ----------------
__device__ __forceinline__ void enc_att_body(const float* __restrict__ inp,
                                             const float* __restrict__ WU_e,
                                             const float* __restrict__ v_e,
                                             int step, int par, int b, SmAtt& s) {
    int tid = threadIdx.x;
    int w = tid >> 5, l = tid & 31;
    s.hs[tid]       = __ldcg(&g_h[par][b*MM + tid]);
    s.hs[tid + 256] = __ldcg(&g_c[par][b*MM + tid]);
    if (tid < 64) s.ves[tid] = v_e[tid];
    __syncthreads();
    #pragma unroll
    for (int t = w*8; t < w*8 + 8; ++t) {
        const float* row = WU_e + t*576;
        float sv = 0.f;
        #pragma unroll
        for (int k = l; k < 512; k += 32) sv += s.hs[k] * row[k];
        sv = wredsum(sv);
        if (l == 0) s.hsW[t] = sv;
    }
    __syncthreads();
    int half = tid >> 7, n = tid & 127;
    float e = 0.f;
    {
        const float* xp = g_Xp + b*TT*NN + half*32*NN + n;
        const float* vh = s.ves + half*32;
        const float* hh = s.hsW + half*32;
        #pragma unroll 8
        for (int t = 0; t < 32; ++t) e += vh[t] * tanh_apx(hh[t] + xp[t*NN]);
    }
    if (half == 1) s.ep[n] = e;
    __syncthreads();
    float p = 0.f;
    if (half == 0) {
        e += s.ep[n];
        float m = wredmax(e);
        if (l == 0) s.redm[w] = m;
    }
    __syncthreads();
    if (half == 0) {
        float m = fmaxf(fmaxf(s.redm[0], s.redm[1]), fmaxf(s.redm[2], s.redm[3]));
        p = __expf(e - m);
        float sv = wredsum(p);
        if (l == 0) s.reds[w] = sv;
    }
    __syncthreads();
    if (half == 0) {
        float tot = s.reds[0] + s.reds[1] + s.reds[2] + s.reds[3];
        float alpha = __fdividef(p, tot);
        g_xin[b*NN + n] = inp[b*TT*INROW + step*INROW + n] * alpha;
    }
}

// ---------------- sub: h-gates GEMM, 32b x 64co tile, K=256 -> g_gpre ----------------
// blk2 in [0,128): bb = blk2>>4 (32-batch group), mo = blk2&15 (16-m group)
__device__ __forceinline__ void gates_h32(const float* __restrict__ Whh,
                                          int par, int blk2, SmG32& s) {
    int bb = blk2 >> 4, mo = blk2 & 15;
    int tid = threadIdx.x;
    int kg = tid >> 7;
    int t128 = tid & 127;
    int ty = t128 >> 4, tx = t128 & 15;     // ty: 4 rows each, tx: 4 cols each
    ull acc[4][2] = {{0,0},{0,0},{0,0},{0,0}};
    const float* hsrc = g_h[par];
    int kbase = kg * 128;
    for (int c = 0; c < 4; ++c) {
        int kc = kbase + c*32;
        #pragma unroll
        for (int u = 0; u < 8; ++u) {
            int idx = t128 + u*128;          // 1024 = 32 rows x 32 kk
            int row = idx >> 5, kk = idx & 31;
            s.A[kg][kk][row] = __ldcg(hsrc + (bb*32 + row)*MM + kc + kk);
        }
        #pragma unroll
        for (int u = 0; u < 16; ++u) {
            int idx = t128 + u*128;          // 2048 = 64 co x 32 kk
            int co = idx >> 5, kk = idx & 31;
            int row = (co >> 4)*256 + mo*16 + (co & 15);
            s.W[kg][kk][co] = __ldcg(Whh + row*256 + kc + kk);
        }
        __syncthreads();
        #pragma unroll
        for (int kk = 0; kk < 32; ++kk) {
            float4 a = *(const float4*)&s.A[kg][kk][ty*4];
            float4 w = *(const float4*)&s.W[kg][kk][tx*4];
            ull w01 = f2pack(w.x, w.y), w23 = f2pack(w.z, w.w);
            ull a0 = f2pack(a.x, a.x), a1 = f2pack(a.y, a.y);
            ull a2 = f2pack(a.z, a.z), a3 = f2pack(a.w, a.w);
            ffma2(acc[0][0], a0, w01); ffma2(acc[0][1], a0, w23);
            ffma2(acc[1][0], a1, w01); ffma2(acc[1][1], a1, w23);
            ffma2(acc[2][0], a2, w01); ffma2(acc[2][1], a2, w23);
            ffma2(acc[3][0], a3, w01); ffma2(acc[3][1], a3, w23);
        }
        __syncthreads();
    }
    if (kg == 0) {
        #pragma unroll
        for (int r = 0; r < 4; ++r) {
            *(float2*)&s.red[ty*4 + r][tx*4]     = f2unpack(acc[r][0]);
            *(float2*)&s.red[ty*4 + r][tx*4 + 2] = f2unpack(acc[r][1]);
        }
    }
    __syncthreads();
    if (kg == 1) {
        #pragma unroll
        for (int r = 0; r < 4; ++r) {
            float2 v0 = f2unpack(acc[r][0]), v1 = f2unpack(acc[r][1]);
            float2 c0 = *(float2*)&s.red[ty*4 + r][tx*4];
            float2 c1 = *(float2*)&s.red[ty*4 + r][tx*4 + 2];
            c0.x += v0.x; c0.y += v0.y; c1.x += v1.x; c1.y += v1.y;
            *(float2*)&s.red[ty*4 + r][tx*4]     = c0;
            *(float2*)&s.red[ty*4 + r][tx*4 + 2] = c1;
        }
    }
    __syncthreads();
    #pragma unroll
    for (int u = 0; u < 8; ++u) {
        int p = tid + u*256;                 // 2048 values
        int bi = p >> 6, co = p & 63;
        g_gpre[(bb*32 + bi)*1024 + mo*64 + co] = s.red[bi][co];
    }
}

// ---------------- encoder phase 1: att (blocks 0-127, 2 batches) || h-gates (128-255) ----
__device__ __forceinline__ void ph_enc_p1(const float* __restrict__ inp,
                                          const float* __restrict__ WU_e,
                                          const float* __restrict__ v_e,
                                          const float* __restrict__ Whh_e,
                                          int step, int par, SmAll& sm) {
    int blk = blockIdx.x;
    if (blk < 128) {
        enc_att_body(inp, WU_e, v_e, step, par, blk*2, sm.a);
        __syncthreads();
        enc_att_body(inp, WU_e, v_e, step, par, blk*2 + 1, sm.a);
    } else {
        gates_h32(Whh_e, par, blk - 128, sm.g32);
    }
}

// ---------------- encoder phase 2: x-gates GEMM (K=128) + LSTM epilogue ----------------
__device__ __forceinline__ void ph_enc_p2(const float* __restrict__ Wih,
                                          const float* __restrict__ bih,
                                          const float* __restrict__ bhh,
                                          int step, int par, SmGates& s) {
    int bb = blockIdx.x >> 4, mo = blockIdx.x & 15;
    int tid = threadIdx.x;
    int kg = tid >> 7;
    int t128 = tid & 127;
    int ty = t128 >> 4, tx = t128 & 15;
    ull acc[2][2] = {{0ull, 0ull}, {0ull, 0ull}};
    int kbase = kg * 64;
    for (int c = 0; c < 2; ++c) {
        int kc = kbase + c*32;
        #pragma unroll
        for (int u = 0; u < 4; ++u) {
            int idx = t128 + u*128;
            int row = idx >> 5, kk = idx & 31;
            s.A[0][kg][kk][row] = __ldcg(g_xin + (bb*16 + row)*NN + kc + kk);
        }
        #pragma unroll
        for (int u = 0; u < 16; ++u) {
            int idx = t128 + u*128;
            int co = idx >> 5, kk = idx & 31;
            int row = (co >> 4)*256 + mo*16 + (co & 15);
            s.W[0][kg][kk][co] = __ldcg(Wih + row*128 + kc + kk);
        }
        __syncthreads();
        #pragma unroll
        for (int kk = 0; kk < 32; ++kk) {
            float2 a = *(const float2*)&s.A[0][kg][kk][ty*2];
            float4 w = *(const float4*)&s.W[0][kg][kk][tx*4];
            ull ax = f2pack(a.x, a.x), ay = f2pack(a.y, a.y);
            ull w01 = f2pack(w.x, w.y), w23 = f2pack(w.z, w.w);
            ffma2(acc[0][0], ax, w01); ffma2(acc[0][1], ax, w23);
            ffma2(acc[1][0], ay, w01); ffma2(acc[1][1], ay, w23);
        }
        __syncthreads();
    }
    if (kg == 0) {
        #pragma unroll
        for (int i = 0; i < 2; ++i) {
            *(float2*)&s.red[ty*2 + i][tx*4]     = f2unpack(acc[i][0]);
            *(float2*)&s.red[ty*2 + i][tx*4 + 2] = f2unpack(acc[i][1]);
        }
    }
    __syncthreads();
    if (kg == 1) {
        #pragma unroll
        for (int i = 0; i < 2; ++i) {
            float2 v0 = f2unpack(acc[i][0]), v1 = f2unpack(acc[i][1]);
            float2 c0 = *(float2*)&s.red[ty*2 + i][tx*4];
            float2 c1 = *(float2*)&s.red[ty*2 + i][tx*4 + 2];
            c0.x += v0.x; c0.y += v0.y; c1.x += v1.x; c1.y += v1.y;
            *(float2*)&s.red[ty*2 + i][tx*4]     = c0;
            *(float2*)&s.red[ty*2 + i][tx*4 + 2] = c1;
        }
    }
    __syncthreads();
    {
        int bi = tid >> 4, ml = tid & 15;
        int gb = bb*16 + bi, m = mo*16 + ml;
        const float* gp = g_gpre + gb*1024 + mo*64;
        float gi = s.red[bi][ml]      + __ldcg(gp + ml)      + bih[m]       + bhh[m];
        float gf = s.red[bi][16 + ml] + __ldcg(gp + 16 + ml) + bih[256 + m] + bhh[256 + m];
        float gg = s.red[bi][32 + ml] + __ldcg(gp + 32 + ml) + bih[512 + m] + bhh[512 + m];
        float go = s.red[bi][48 + ml] + __ldcg(gp + 48 + ml) + bih[768 + m] + bhh[768 + m];
        float cold = __ldcg(&g_c[par][gb*MM + m]);
        float cn = fast_sigm(gf)*cold + fast_sigm(gi)*fast_tanh(gg);
        float hn = fast_sigm(go)*fast_tanh(cn);
        g_c[par ^ 1][gb*MM + m] = cn;
        g_h[par ^ 1][gb*MM + m] = hn;
        g_Xe[(gb*TT + step)*MM + m] = hn;
    }
}

// ---------------- phase: Xd precompute (+ re-zero h/c) ----------------
__device__ __forceinline__ void ph_xd(const float* __restrict__ WU_d, SmXd& s) {
    int rb = blockIdx.x, tid = threadIdx.x;
    int ty = tid >> 4, tx = tid & 15;
    for (int ob = 0; ob < 4; ++ob) {
        float acc[4][4];
        #pragma unroll
        for (int i = 0; i < 4; ++i)
            #pragma unroll
            for (int j = 0; j < 4; ++j) acc[i][j] = 0.f;
        for (int kc = 0; kc < 256; kc += 32) {
            for (int idx = tid; idx < 2048; idx += 256) {
                int ri = idx >> 5, kk = idx & 31;
                s.A[kk][ri] = g_Xe[(rb*64 + ri)*MM + kc + kk];
            }
            for (int idx = tid; idx < 2048; idx += 256) {
                int co = idx >> 5, kk = idx & 31;
                s.W[kk][co] = WU_d[(ob*64 + co)*768 + 512 + kc + kk];
            }
            __syncthreads();
            #pragma unroll
            for (int kk = 0; kk < 32; ++kk) {
                float4 a = *(const float4*)&s.A[kk][ty*4];
                float4 w = *(const float4*)&s.W[kk][tx*4];
                acc[0][0] += a.x*w.x; acc[0][1] += a.x*w.y; acc[0][2] += a.x*w.z; acc[0][3] += a.x*w.w;
                acc[1][0] += a.y*w.x; acc[1][1] += a.y*w.y; acc[1][2] += a.y*w.z; acc[1][3] += a.y*w.w;
                acc[2][0] += a.z*w.x; acc[2][1] += a.z*w.y; acc[2][2] += a.z*w.z; acc[2][3] += a.z*w.w;
                acc[3][0] += a.w*w.x; acc[3][1] += a.w*w.y; acc[3][2] += a.w*w.z; acc[3][3] += a.w*w.w;
            }
            __syncthreads();
        }
        #pragma unroll
        for (int i = 0; i < 4; ++i)
            #pragma unroll
            for (int j = 0; j < 4; ++j)
                g_Xd[(rb*64 + ty*4 + i)*MM + ob*64 + tx*4 + j] = acc[i][j];
    }
    int idx = blockIdx.x * 256 + tid;
    g_h[0][idx] = 0.f; g_h[1][idx] = 0.f;
    g_c[0][idx] = 0.f; g_c[1][idx] = 0.f;
}

// ---------------- sub: decoder hsW GEMM, 16b x 32o tile, K=512 ----------------
// blk in [0,128): rb = blk>>3 (16-batch group), ob = blk&7 (32-col group)
__device__ __forceinline__ void dec_hsw2(const float* __restrict__ WU_d,
                                         int par, int blk, SmHsw2& s) {
    int rb = blk >> 3, ob = blk & 7;
    int tid = threadIdx.x;
    int kg = tid >> 7;
    int t128 = tid & 127;
    int ty = t128 >> 4, tx = t128 & 15;   // ty: 2 rows, tx: 2 cols
    ull acc0 = 0ull, acc1 = 0ull;          // (r0,r1) x col0 / col1
    int kbase = kg * 256;
    for (int c = 0; c < 8; ++c) {
        int kc = kbase + c*32;
        #pragma unroll
        for (int u = 0; u < 4; ++u) {
            int idx = t128 + u*128;        // 512 = 16 rows x 32 kk
            int ri = idx >> 5, kk = idx & 31;
            int k = kc + kk, gb = rb*16 + ri;
            s.A[kg][kk][ri] = (k < 256) ? __ldcg(&g_h[par][gb*MM + k])
                                        : __ldcg(&g_c[par][gb*MM + k - 256]);
        }
        #pragma unroll
        for (int u = 0; u < 8; ++u) {
            int idx = t128 + u*128;        // 1024 = 32 co x 32 kk
            int co = idx >> 5, kk = idx & 31;
            s.W[kg][kk][co] = __ldcg(WU_d + (ob*32 + co)*768 + kc + kk);
        }
        __syncthreads();
        #pragma unroll
        for (int kk = 0; kk < 32; ++kk) {
            ull a = *(const ull*)&s.A[kg][kk][ty*2];
            float w0 = s.W[kg][kk][tx*2], w1 = s.W[kg][kk][tx*2 + 1];
            ffma2(acc0, a, f2pack(w0, w0));
            ffma2(acc1, a, f2pack(w1, w1));
        }
        __syncthreads();
    }
    float2 v0 = f2unpack(acc0), v1 = f2unpack(acc1);
    if (kg == 0) {
        s.red[ty*2][tx*2] = v0.x;     s.red[ty*2 + 1][tx*2] = v0.y;
        s.red[ty*2][tx*2 + 1] = v1.x; s.red[ty*2 + 1][tx*2 + 1] = v1.y;
    }
    __syncthreads();
    if (kg == 1) {
        s.red[ty*2][tx*2] += v0.x;     s.red[ty*2 + 1][tx*2] += v0.y;
        s.red[ty*2][tx*2 + 1] += v1.x; s.red[ty*2 + 1][tx*2 + 1] += v1.y;
    }
    __syncthreads();
    #pragma unroll
    for (int u = 0; u < 2; ++u) {
        int p = tid + u*256;               // 512 values
        int ri = p >> 5, co = p & 31;
        g_hsW[(rb*16 + ri)*MM + ob*32 + co] = s.red[ri][co];
    }
}

// ---------------- decoder phase D1: hsW (blocks 0-127) || h-gates (128-255) ----------------
__device__ __forceinline__ void ph_dec_d1(const float* __restrict__ WU_d,
                                          const float* __restrict__ Whh_d,
                                          int par, SmAll& sm) {
    int blk = blockIdx.x;
    if (blk < 128) dec_hsw2(WU_d, par, blk, sm.h2);
    else           gates_h32(Whh_d, par, blk - 128, sm.g32);
}

// ---------------- decoder phase D2: attention + ctx + y_tilde + LSTM epilogue ----------------
__device__ __forceinline__ void ph_dec_att2(const float* __restrict__ inp,
                                            const float* __restrict__ v_d,
                                            const float* __restrict__ wbt,
                                            const float* __restrict__ Wihd,
                                            const float* __restrict__ bih,
                                            const float* __restrict__ bhh,
                                            int step, int par, SmDatt& s) {
    int b = blockIdx.x, tid = threadIdx.x;
    int w = tid >> 5, l = tid & 31;
    s.hsw[tid] = __ldcg(&g_hsW[b*MM + tid]);
    s.vds[tid] = v_d[tid];
    __syncthreads();
    for (int t = w; t < 64; t += 8) {
        const float* xd = g_Xd + (b*TT + t)*MM;
        float sv = 0.f;
        #pragma unroll
        for (int m = l; m < 256; m += 32) sv += s.vds[m] * tanh_apx(s.hsw[m] + ldcs(xd + m));
        sv = wredsum(sv);
        if (l == 0) s.l[t] = sv;
    }
    __syncthreads();
    if (tid < 32) {
        float a0 = s.l[tid], a1 = s.l[tid + 32];
        float mx = wredmax(fmaxf(a0, a1));
        mx = __shfl_sync(0xffffffffu, mx, 0);
        float p0 = __expf(a0 - mx), p1 = __expf(a1 - mx);
        float sm2 = wredsum(p0 + p1);
        sm2 = __shfl_sync(0xffffffffu, sm2, 0);
        s.beta[tid] = __fdividef(p0, sm2);
        s.beta[tid + 32] = __fdividef(p1, sm2);
    }
    __syncthreads();
    float c = 0.f;
    const float* xe = g_Xe + b*TT*MM + tid;
    #pragma unroll 8
    for (int t = 0; t < 64; ++t) c += s.beta[t] * ldcs(xe + t*MM);
    g_ctx[b*MM + tid] = c;
    float part = wbt[1 + tid] * c;
    part = wredsum(part);
    if (l == 0) s.reds[w] = part;
    __syncthreads();
    if (tid == 0) {
        float tot = 0.f;
        #pragma unroll
        for (int i = 0; i < 8; ++i) tot += s.reds[i];
        s.yt = wbt[0] * inp[b*TT*INROW + step*INROW + 128] + tot;
    }
    __syncthreads();
    {
        float yt = s.yt;
        int mo = tid >> 4, ml = tid & 15, m = tid;
        const float* gp = g_gpre + b*1024 + mo*64;
        float gi = __ldcg(gp + ml)      + bih[m]       + bhh[m]       + yt*Wihd[m];
        float gf = __ldcg(gp + 16 + ml) + bih[256 + m] + bhh[256 + m] + yt*Wihd[256 + m];
        float gg = __ldcg(gp + 32 + ml) + bih[512 + m] + bhh[512 + m] + yt*Wihd[512 + m];
        float go = __ldcg(gp + 48 + ml) + bih[768 + m] + bhh[768 + m] + yt*Wihd[768 + m];
        float cold = __ldcg(&g_c[par][b*MM + m]);
        float cn = fast_sigm(gf)*cold + fast_sigm(gi)*fast_tanh(gg);
        float hn = fast_sigm(go)*fast_tanh(cn);
        g_c[par ^ 1][b*MM + m] = cn;
        g_h[par ^ 1][b*MM + m] = hn;
    }
}

// ---------------- phase: final projection ----------------
__device__ __forceinline__ void ph_final(const float* __restrict__ WbW,
                                         const float* __restrict__ Wbb,
                                         const float* __restrict__ vbW,
                                         const float* __restrict__ vbb,
                                         float* __restrict__ out, int par, SmFin& s) {
    int b = blockIdx.x, tid = threadIdx.x;
    int w = tid >> 5, l = tid & 31;
    s.hc[tid]       = __ldcg(&g_h[par][b*MM + tid]);
    s.hc[256 + tid] = __ldcg(&g_ctx[b*MM + tid]);
    __syncthreads();
    for (int p = w*32; p < w*32 + 32; ++p) {
        const float* row = WbW + p*512;
        float sv = 0.f;
        #pragma unroll
        for (int k = l; k < 512; k += 32) sv += s.hc[k] * row[k];
        sv = wredsum(sv);
        if (l == 0) s.hid[p] = sv + Wbb[p];
    }
    __syncthreads();
    float part = s.hid[tid] * vbW[tid];
    part = wredsum(part);
    if (l == 0) s.reds[w] = part;
    __syncthreads();
    if (tid == 0) {
        float tot = 0.f;
        #pragma unroll
        for (int i = 0; i < 8; ++i) tot += s.reds[i];
        out[b] = tot + vbb[0];
    }
}

// ---------------- persistent megakernel ----------------
__global__ void __launch_bounds__(256, 2) k_darnn(
        const float* __restrict__ inp,  const float* __restrict__ WU_e,
        const float* __restrict__ v_e,  const float* __restrict__ Wih_e,
        const float* __restrict__ Whh_e,const float* __restrict__ bih_e,
        const float* __restrict__ bhh_e,const float* __restrict__ WU_d,
        const float* __restrict__ v_d,  const float* __restrict__ wbt,
        const float* __restrict__ Wih_d,const float* __restrict__ Whh_d,
        const float* __restrict__ bih_d,const float* __restrict__ bhh_d,
        const float* __restrict__ WbW,  const float* __restrict__ Wbb,
        const float* __restrict__ vbW,  const float* __restrict__ vbb,
        float* __restrict__ out) {
    __shared__ SmAll sm;

    ph_xp(inp, WU_e, sm.xp);
    grid_sync();

    for (int s = 0; s < 64; ++s) {
        int par = s & 1;
        ph_enc_p1(inp, WU_e, v_e, Whh_e, s, par, sm);
        grid_sync();
        ph_enc_p2(Wih_e, bih_e, bhh_e, s, par, sm.g);
        grid_sync();
    }

    ph_xd(WU_d, sm.xd);
    grid_sync();

    for (int s = 0; s < 63; ++s) {
        int par = s & 1;
        ph_dec_d1(WU_d, Whh_d, par, sm);
        grid_sync();
        ph_dec_att2(inp, v_d, wbt, Wih_d, bih_d, bhh_d, s, par, sm.d);
        grid_sync();
    }

    ph_final(WbW, Wbb, vbW, vbb, out, 1, sm.f);
}

// ---------------- launcher ----------------
extern "C" void kernel_launch(void* const* d_in, const int* in_sizes, int n_in,
                              void* d_out, int out_size) {
    const float* inp   = (const float*)d_in[0];
    const float* WU_e  = (const float*)d_in[1];
    const float* v_e   = (const float*)d_in[2];
    const float* Wih_e = (const float*)d_in[3];
    const float* Whh_e = (const float*)d_in[4];
    const float* bih_e = (const float*)d_in[5];
    const float* bhh_e = (const float*)d_in[6];
    const float* WU_d  = (const float*)d_in[7];
    const float* v_d   = (const float*)d_in[8];
    const float* wbt   = (const float*)d_in[9];
    const float* Wih_d = (const float*)d_in[10];
    const float* Whh_d = (const float*)d_in[11];
    const float* bih_d = (const float*)d_in[12];
    const float* bhh_d = (const float*)d_in[13];
    const float* WbW   = (const float*)d_in[14];
    const float* Wbb   = (const float*)d_in[15];
    const float* vbW   = (const float*)d_in[16];
    const float* vbb   = (const float*)d_in[17];
    float* out = (float*)d_out;

    k_darnn<<<NBLK, 256>>>(inp, WU_e, v_e, Wih_e, Whh_e, bih_e, bhh_e,
                           WU_d, v_d, wbt, Wih_d, Whh_d, bih_d, bhh_d,
                           WbW, Wbb, vbW, vbb, out);
}

// round 16
// speedup vs baseline: 1.3244x; 1.0901x over previous
#include <cuda_runtime.h>
#include <math.h>

#define BB 256
#define TT 64
#define NN 128
#define MM 256
#define INROW 129   // N + YD
#define NBLK 256

typedef unsigned long long ull;

// ---------------- scratch (device globals; no allocation) ----------------
__device__ float g_Xp[BB*TT*NN];     // immutable after xp
__device__ float g_Xe[BB*TT*MM];     // immutable after encode
__device__ float g_Xd[BB*TT*MM];     // immutable after xd
__device__ float g_h[2][BB*MM];      // mutable (ldcg)
__device__ float g_c[2][BB*MM];      // mutable (ldcg)
__device__ float g_xin[BB*NN];       // mutable (ldcg)
__device__ float g_hsW[BB*MM];       // mutable (ldcg)
__device__ float g_gpre[BB*1024];    // mutable (ldcg) gate preactivations (h-part)
__device__ float g_ctx[BB*MM];

// ---------------- grid barrier (release/acquire, single-thread arrival) ----------------
__device__ unsigned g_bar_count;
__device__ unsigned g_bar_gen;

__device__ __forceinline__ unsigned ld_acq(const unsigned* p) {
    unsigned v;
    asm volatile("ld.acquire.gpu.u32 %0, [%1];" : "=r"(v) : "l"(p) : "memory");
    return v;
}

__device__ __forceinline__ void grid_sync() {
    __syncthreads();
    if (threadIdx.x == 0) {
        unsigned gen = g_bar_gen;
        unsigned old;
        asm volatile("atom.add.release.gpu.u32 %0, [%1], 1;"
                     : "=r"(old) : "l"(&g_bar_count) : "memory");
        if (old == NBLK - 1) {
            g_bar_count = 0;
            asm volatile("st.release.gpu.u32 [%0], %1;"
                         :: "l"(&g_bar_gen), "r"(gen + 1) : "memory");
        } else {
            while (ld_acq(&g_bar_gen) == gen) { }
        }
    }
    __syncthreads();
}

// ---------------- math helpers ----------------
__device__ __forceinline__ float fast_sigm(float x) {
    return __fdividef(1.0f, 1.0f + __expf(-x));
}
__device__ __forceinline__ float fast_tanh(float x) {
    float e = __expf(2.0f * x);
    return 1.0f - __fdividef(2.0f, e + 1.0f);
}
// single-MUFU tanh — attention score loops only
__device__ __forceinline__ float tanh_apx(float x) {
    float y; asm("tanh.approx.f32 %0, %1;" : "=f"(y) : "f"(x)); return y;
}
__device__ __forceinline__ float wredsum(float v) {
    #pragma unroll
    for (int o = 16; o > 0; o >>= 1) v += __shfl_down_sync(0xffffffffu, v, o);
    return v;
}
__device__ __forceinline__ float wredmax(float v) {
    #pragma unroll
    for (int o = 16; o > 0; o >>= 1) v = fmaxf(v, __shfl_down_sync(0xffffffffu, v, o));
    return v;
}
__device__ __forceinline__ ull f2pack(float lo, float hi) {
    ull r; asm("mov.b64 %0, {%1, %2};" : "=l"(r) : "f"(lo), "f"(hi)); return r;
}
__device__ __forceinline__ void ffma2(ull& d, ull a, ull b) {
    asm("fma.rn.f32x2 %0, %1, %2, %3;" : "=l"(d) : "l"(a), "l"(b), "l"(d));
}
__device__ __forceinline__ float2 f2unpack(ull v) {
    float2 r; asm("mov.b64 {%0, %1}, %2;" : "=f"(r.x), "=f"(r.y) : "l"(v)); return r;
}
__device__ __forceinline__ float ldcs(const float* p) {
    float v; asm volatile("ld.global.cs.f32 %0, [%1];" : "=f"(v) : "l"(p)); return v;
}

// ---------------- shared memory union ----------------
struct SmGates { float A[2][2][32][18]; float W[2][2][32][68]; float red[16][66]; };
struct SmG32   { float A[2][32][36]; float W[2][32][68]; float red[32][66]; };
struct SmHsw2  { float A[2][32][18]; float W[2][32][34]; float red[16][33]; };
struct SmXp    { float WUx[4096]; float Xs[8192]; };
struct SmAtt   { float hs[2][512]; float hsW[2][64]; float ves[64]; float redm[2][4]; float reds[2][4]; };
struct SmXd    { float A[32][68]; float W[32][68]; };
struct SmDatt  { float hsw[256]; float vds[256]; float l[64]; float beta[64]; float reds[8]; float yt; };
struct SmFin   { float hc[512]; float hid[256]; float reds[8]; };
union SmAll {
    SmGates g; SmG32 g32; SmHsw2 h2; SmXp xp; SmAtt a; SmXd xd; SmDatt d; SmFin f;
};

// ---------------- phase: Xp precompute (+ zero h/c) ----------------
__device__ __forceinline__ void ph_xp(const float* __restrict__ inp,
                                      const float* __restrict__ WU_e, SmXp& s) {
    int b = blockIdx.x, tid = threadIdx.x;
    {
        int idx = b * 256 + tid;
        g_h[0][idx] = 0.f; g_h[1][idx] = 0.f;
        g_c[0][idx] = 0.f; g_c[1][idx] = 0.f;
    }
    for (int idx = tid; idx < 4096; idx += 256) {
        int t = idx >> 6, tp = idx & 63;
        s.WUx[idx] = WU_e[t*576 + 512 + tp];
    }
    for (int idx = tid; idx < 8192; idx += 256) {
        int tp = idx >> 7, n = idx & 127;
        s.Xs[idx] = inp[b*TT*INROW + tp*INROW + n];
    }
    __syncthreads();
    int half = tid >> 7, n = tid & 127;
    float acc[32];
    #pragma unroll
    for (int t = 0; t < 32; ++t) acc[t] = 0.f;
    for (int tp = 0; tp < 64; ++tp) {
        float xv = s.Xs[tp*128 + n];
        #pragma unroll
        for (int t = 0; t < 32; ++t) acc[t] += xv * s.WUx[(half*32 + t)*64 + tp];
    }
    #pragma unroll
    for (int t = 0; t < 32; ++t) g_Xp[(b*TT + half*32 + t)*NN + n] = acc[t];
}

// ---------------- sub: encoder attention, TWO batches in parallel ----------------
__device__ __forceinline__ void enc_att_pair(const float* __restrict__ inp,
                                             const float* __restrict__ WU_e,
                                             const float* __restrict__ v_e,
                                             int step, int par, int b0, SmAtt& s) {
    int tid = threadIdx.x;
    int bsel = tid >> 7, t128 = tid & 127;
    int w = tid >> 5, l = tid & 31;
    int b = b0 + bsel;
    // load [h|c] for both batches: half the threads per batch, 4 values each
    s.hs[bsel][t128]       = __ldcg(&g_h[par][b*MM + t128]);
    s.hs[bsel][t128 + 128] = __ldcg(&g_h[par][b*MM + t128 + 128]);
    s.hs[bsel][t128 + 256] = __ldcg(&g_c[par][b*MM + t128]);
    s.hs[bsel][t128 + 384] = __ldcg(&g_c[par][b*MM + t128 + 128]);
    if (tid < 64) s.ves[tid] = v_e[tid];
    __syncthreads();
    // hsW: warps 0-3 -> batch 0 (16 rows each), warps 4-7 -> batch 1
    {
        int wb = w >> 2, wi = w & 3;
        #pragma unroll
        for (int t = wi*16; t < wi*16 + 16; ++t) {
            const float* row = WU_e + t*576;
            float sv = 0.f;
            #pragma unroll
            for (int k = l; k < 512; k += 32) sv += s.hs[wb][k] * row[k];
            sv = wredsum(sv);
            if (l == 0) s.hsW[wb][t] = sv;
        }
    }
    __syncthreads();
    // E + softmax: thread halves handle their batch
    int n = t128;
    float e = 0.f;
    {
        const float* xp = g_Xp + b*TT*NN + n;
        const float* hh = s.hsW[bsel];
        #pragma unroll 8
        for (int t = 0; t < 64; ++t) e += s.ves[t] * tanh_apx(hh[t] + xp[t*NN]);
    }
    float m = wredmax(e);
    if (l == 0) s.redm[bsel][w & 3] = m;
    __syncthreads();
    m = fmaxf(fmaxf(s.redm[bsel][0], s.redm[bsel][1]),
              fmaxf(s.redm[bsel][2], s.redm[bsel][3]));
    float p = __expf(e - m);
    float sv = wredsum(p);
    if (l == 0) s.reds[bsel][w & 3] = sv;
    __syncthreads();
    float tot = s.reds[bsel][0] + s.reds[bsel][1] + s.reds[bsel][2] + s.reds[bsel][3];
    float alpha = __fdividef(p, tot);
    g_xin[b*NN + n] = inp[b*TT*INROW + step*INROW + n] * alpha;
}

// ---------------- sub: h-gates GEMM, 32b x 64co tile, K=256 -> g_gpre ----------------
__device__ __forceinline__ void gates_h32(const float* __restrict__ Whh,
                                          int par, int blk2, SmG32& s) {
    int bb = blk2 >> 4, mo = blk2 & 15;
    int tid = threadIdx.x;
    int kg = tid >> 7;
    int t128 = tid & 127;
    int ty = t128 >> 4, tx = t128 & 15;
    ull acc[4][2] = {{0,0},{0,0},{0,0},{0,0}};
    const float* hsrc = g_h[par];
    int kbase = kg * 128;
    for (int c = 0; c < 4; ++c) {
        int kc = kbase + c*32;
        #pragma unroll
        for (int u = 0; u < 8; ++u) {
            int idx = t128 + u*128;
            int row = idx >> 5, kk = idx & 31;
            s.A[kg][kk][row] = __ldcg(hsrc + (bb*32 + row)*MM + kc + kk);
        }
        #pragma unroll
        for (int u = 0; u < 16; ++u) {
            int idx = t128 + u*128;
            int co = idx >> 5, kk = idx & 31;
            int row = (co >> 4)*256 + mo*16 + (co & 15);
            s.W[kg][kk][co] = __ldcg(Whh + row*256 + kc + kk);
        }
        __syncthreads();
        #pragma unroll
        for (int kk = 0; kk < 32; ++kk) {
            float4 a = *(const float4*)&s.A[kg][kk][ty*4];
            float4 w = *(const float4*)&s.W[kg][kk][tx*4];
            ull w01 = f2pack(w.x, w.y), w23 = f2pack(w.z, w.w);
            ull a0 = f2pack(a.x, a.x), a1 = f2pack(a.y, a.y);
            ull a2 = f2pack(a.z, a.z), a3 = f2pack(a.w, a.w);
            ffma2(acc[0][0], a0, w01); ffma2(acc[0][1], a0, w23);
            ffma2(acc[1][0], a1, w01); ffma2(acc[1][1], a1, w23);
            ffma2(acc[2][0], a2, w01); ffma2(acc[2][1], a2, w23);
            ffma2(acc[3][0], a3, w01); ffma2(acc[3][1], a3, w23);
        }
        __syncthreads();
    }
    if (kg == 0) {
        #pragma unroll
        for (int r = 0; r < 4; ++r) {
            *(float2*)&s.red[ty*4 + r][tx*4]     = f2unpack(acc[r][0]);
            *(float2*)&s.red[ty*4 + r][tx*4 + 2] = f2unpack(acc[r][1]);
        }
    }
    __syncthreads();
    if (kg == 1) {
        #pragma unroll
        for (int r = 0; r < 4; ++r) {
            float2 v0 = f2unpack(acc[r][0]), v1 = f2unpack(acc[r][1]);
            float2 c0 = *(float2*)&s.red[ty*4 + r][tx*4];
            float2 c1 = *(float2*)&s.red[ty*4 + r][tx*4 + 2];
            c0.x += v0.x; c0.y += v0.y; c1.x += v1.x; c1.y += v1.y;
            *(float2*)&s.red[ty*4 + r][tx*4]     = c0;
            *(float2*)&s.red[ty*4 + r][tx*4 + 2] = c1;
        }
    }
    __syncthreads();
    #pragma unroll
    for (int u = 0; u < 8; ++u) {
        int p = tid + u*256;
        int bi = p >> 6, co = p & 63;
        g_gpre[(bb*32 + bi)*1024 + mo*64 + co] = s.red[bi][co];
    }
}

// ---------------- encoder phase 1: att-pair (blocks 0-127) || h-gates (128-255) ----------
__device__ __forceinline__ void ph_enc_p1(const float* __restrict__ inp,
                                          const float* __restrict__ WU_e,
                                          const float* __restrict__ v_e,
                                          const float* __restrict__ Whh_e,
                                          int step, int par, SmAll& sm) {
    int blk = blockIdx.x;
    if (blk < 128) enc_att_pair(inp, WU_e, v_e, step, par, blk*2, sm.a);
    else           gates_h32(Whh_e, par, blk - 128, sm.g32);
}

// ---------------- encoder phase 2: x-gates GEMM (K=128) + LSTM epilogue ----------------
__device__ __forceinline__ void ph_enc_p2(const float* __restrict__ Wih,
                                          const float* __restrict__ bih,
                                          const float* __restrict__ bhh,
                                          int step, int par, SmGates& s) {
    int bb = blockIdx.x >> 4, mo = blockIdx.x & 15;
    int tid = threadIdx.x;
    int kg = tid >> 7;
    int t128 = tid & 127;
    int ty = t128 >> 4, tx = t128 & 15;
    ull acc[2][2] = {{0ull, 0ull}, {0ull, 0ull}};
    int kbase = kg * 64;
    for (int c = 0; c < 2; ++c) {
        int kc = kbase + c*32;
        #pragma unroll
        for (int u = 0; u < 4; ++u) {
            int idx = t128 + u*128;
            int row = idx >> 5, kk = idx & 31;
            s.A[0][kg][kk][row] = __ldcg(g_xin + (bb*16 + row)*NN + kc + kk);
        }
        #pragma unroll
        for (int u = 0; u < 16; ++u) {
            int idx = t128 + u*128;
            int co = idx >> 5, kk = idx & 31;
            int row = (co >> 4)*256 + mo*16 + (co & 15);
            s.W[0][kg][kk][co] = __ldcg(Wih + row*128 + kc + kk);
        }
        __syncthreads();
        #pragma unroll
        for (int kk = 0; kk < 32; ++kk) {
            float2 a = *(const float2*)&s.A[0][kg][kk][ty*2];
            float4 w = *(const float4*)&s.W[0][kg][kk][tx*4];
            ull ax = f2pack(a.x, a.x), ay = f2pack(a.y, a.y);
            ull w01 = f2pack(w.x, w.y), w23 = f2pack(w.z, w.w);
            ffma2(acc[0][0], ax, w01); ffma2(acc[0][1], ax, w23);
            ffma2(acc[1][0], ay, w01); ffma2(acc[1][1], ay, w23);
        }
        __syncthreads();
    }
    if (kg == 0) {
        #pragma unroll
        for (int i = 0; i < 2; ++i) {
            *(float2*)&s.red[ty*2 + i][tx*4]     = f2unpack(acc[i][0]);
            *(float2*)&s.red[ty*2 + i][tx*4 + 2] = f2unpack(acc[i][1]);
        }
    }
    __syncthreads();
    if (kg == 1) {
        #pragma unroll
        for (int i = 0; i < 2; ++i) {
            float2 v0 = f2unpack(acc[i][0]), v1 = f2unpack(acc[i][1]);
            float2 c0 = *(float2*)&s.red[ty*2 + i][tx*4];
            float2 c1 = *(float2*)&s.red[ty*2 + i][tx*4 + 2];
            c0.x += v0.x; c0.y += v0.y; c1.x += v1.x; c1.y += v1.y;
            *(float2*)&s.red[ty*2 + i][tx*4]     = c0;
            *(float2*)&s.red[ty*2 + i][tx*4 + 2] = c1;
        }
    }
    __syncthreads();
    {
        int bi = tid >> 4, ml = tid & 15;
        int gb = bb*16 + bi, m = mo*16 + ml;
        const float* gp = g_gpre + gb*1024 + mo*64;
        float gi = s.red[bi][ml]      + __ldcg(gp + ml)      + bih[m]       + bhh[m];
        float gf = s.red[bi][16 + ml] + __ldcg(gp + 16 + ml) + bih[256 + m] + bhh[256 + m];
        float gg = s.red[bi][32 + ml] + __ldcg(gp + 32 + ml) + bih[512 + m] + bhh[512 + m];
        float go = s.red[bi][48 + ml] + __ldcg(gp + 48 + ml) + bih[768 + m] + bhh[768 + m];
        float cold = __ldcg(&g_c[par][gb*MM + m]);
        float cn = fast_sigm(gf)*cold + fast_sigm(gi)*fast_tanh(gg);
        float hn = fast_sigm(go)*fast_tanh(cn);
        g_c[par ^ 1][gb*MM + m] = cn;
        g_h[par ^ 1][gb*MM + m] = hn;
        g_Xe[(gb*TT + step)*MM + m] = hn;
    }
}

// ---------------- phase: Xd precompute (+ re-zero h/c) ----------------
__device__ __forceinline__ void ph_xd(const float* __restrict__ WU_d, SmXd& s) {
    int rb = blockIdx.x, tid = threadIdx.x;
    int ty = tid >> 4, tx = tid & 15;
    for (int ob = 0; ob < 4; ++ob) {
        float acc[4][4];
        #pragma unroll
        for (int i = 0; i < 4; ++i)
            #pragma unroll
            for (int j = 0; j < 4; ++j) acc[i][j] = 0.f;
        for (int kc = 0; kc < 256; kc += 32) {
            for (int idx = tid; idx < 2048; idx += 256) {
                int ri = idx >> 5, kk = idx & 31;
                s.A[kk][ri] = g_Xe[(rb*64 + ri)*MM + kc + kk];
            }
            for (int idx = tid; idx < 2048; idx += 256) {
                int co = idx >> 5, kk = idx & 31;
                s.W[kk][co] = WU_d[(ob*64 + co)*768 + 512 + kc + kk];
            }
            __syncthreads();
            #pragma unroll
            for (int kk = 0; kk < 32; ++kk) {
                float4 a = *(const float4*)&s.A[kk][ty*4];
                float4 w = *(const float4*)&s.W[kk][tx*4];
                acc[0][0] += a.x*w.x; acc[0][1] += a.x*w.y; acc[0][2] += a.x*w.z; acc[0][3] += a.x*w.w;
                acc[1][0] += a.y*w.x; acc[1][1] += a.y*w.y; acc[1][2] += a.y*w.z; acc[1][3] += a.y*w.w;
                acc[2][0] += a.z*w.x; acc[2][1] += a.z*w.y; acc[2][2] += a.z*w.z; acc[2][3] += a.z*w.w;
                acc[3][0] += a.w*w.x; acc[3][1] += a.w*w.y; acc[3][2] += a.w*w.z; acc[3][3] += a.w*w.w;
            }
            __syncthreads();
        }
        #pragma unroll
        for (int i = 0; i < 4; ++i)
            #pragma unroll
            for (int j = 0; j < 4; ++j)
                g_Xd[(rb*64 + ty*4 + i)*MM + ob*64 + tx*4 + j] = acc[i][j];
    }
    int idx = blockIdx.x * 256 + tid;
    g_h[0][idx] = 0.f; g_h[1][idx] = 0.f;
    g_c[0][idx] = 0.f; g_c[1][idx] = 0.f;
}

// ---------------- sub: decoder hsW GEMM, 16b x 32o tile, K=512 ----------------
__device__ __forceinline__ void dec_hsw2(const float* __restrict__ WU_d,
                                         int par, int blk, SmHsw2& s) {
    int rb = blk >> 3, ob = blk & 7;
    int tid = threadIdx.x;
    int kg = tid >> 7;
    int t128 = tid & 127;
    int ty = t128 >> 4, tx = t128 & 15;
    ull acc0 = 0ull, acc1 = 0ull;
    int kbase = kg * 256;
    for (int c = 0; c < 8; ++c) {
        int kc = kbase + c*32;
        #pragma unroll
        for (int u = 0; u < 4; ++u) {
            int idx = t128 + u*128;
            int ri = idx >> 5, kk = idx & 31;
            int k = kc + kk, gb = rb*16 + ri;
            s.A[kg][kk][ri] = (k < 256) ? __ldcg(&g_h[par][gb*MM + k])
                                        : __ldcg(&g_c[par][gb*MM + k - 256]);
        }
        #pragma unroll
        for (int u = 0; u < 8; ++u) {
            int idx = t128 + u*128;
            int co = idx >> 5, kk = idx & 31;
            s.W[kg][kk][co] = __ldcg(WU_d + (ob*32 + co)*768 + kc + kk);
        }
        __syncthreads();
        #pragma unroll
        for (int kk = 0; kk < 32; ++kk) {
            ull a = *(const ull*)&s.A[kg][kk][ty*2];
            float w0 = s.W[kg][kk][tx*2], w1 = s.W[kg][kk][tx*2 + 1];
            ffma2(acc0, a, f2pack(w0, w0));
            ffma2(acc1, a, f2pack(w1, w1));
        }
        __syncthreads();
    }
    float2 v0 = f2unpack(acc0), v1 = f2unpack(acc1);
    if (kg == 0) {
        s.red[ty*2][tx*2] = v0.x;     s.red[ty*2 + 1][tx*2] = v0.y;
        s.red[ty*2][tx*2 + 1] = v1.x; s.red[ty*2 + 1][tx*2 + 1] = v1.y;
    }
    __syncthreads();
    if (kg == 1) {
        s.red[ty*2][tx*2] += v0.x;     s.red[ty*2 + 1][tx*2] += v0.y;
        s.red[ty*2][tx*2 + 1] += v1.x; s.red[ty*2 + 1][tx*2 + 1] += v1.y;
    }
    __syncthreads();
    #pragma unroll
    for (int u = 0; u < 2; ++u) {
        int p = tid + u*256;
        int ri = p >> 5, co = p & 31;
        g_hsW[(rb*16 + ri)*MM + ob*32 + co] = s.red[ri][co];
    }
}

// ---------------- decoder phase D1: hsW (blocks 0-127) || h-gates (128-255) ----------------
__device__ __forceinline__ void ph_dec_d1(const float* __restrict__ WU_d,
                                          const float* __restrict__ Whh_d,
                                          int par, SmAll& sm) {
    int blk = blockIdx.x;
    if (blk < 128) dec_hsw2(WU_d, par, blk, sm.h2);
    else           gates_h32(Whh_d, par, blk - 128, sm.g32);
}

// ---------------- decoder phase D2: attention + ctx + y_tilde + LSTM epilogue ----------------
__device__ __forceinline__ void ph_dec_att2(const float* __restrict__ inp,
                                            const float* __restrict__ v_d,
                                            const float* __restrict__ wbt,
                                            const float* __restrict__ Wihd,
                                            const float* __restrict__ bih,
                                            const float* __restrict__ bhh,
                                            int step, int par, SmDatt& s) {
    int b = blockIdx.x, tid = threadIdx.x;
    int w = tid >> 5, l = tid & 31;
    s.hsw[tid] = __ldcg(&g_hsW[b*MM + tid]);
    s.vds[tid] = v_d[tid];
    __syncthreads();
    // score: 8 t-rows per warp accumulated concurrently (t = w + j*8)
    {
        float sv[8];
        #pragma unroll
        for (int j = 0; j < 8; ++j) sv[j] = 0.f;
        const float* xdb = g_Xd + b*TT*MM + l;
        #pragma unroll
        for (int mi = 0; mi < 8; ++mi) {
            int m = l + mi*32;
            float xv[8];
            #pragma unroll
            for (int j = 0; j < 8; ++j)
                xv[j] = ldcs(xdb + (w + j*8)*MM + mi*32);
            float hv = s.hsw[m], vv = s.vds[m];
            #pragma unroll
            for (int j = 0; j < 8; ++j)
                sv[j] += vv * tanh_apx(hv + xv[j]);
        }
        #pragma unroll
        for (int j = 0; j < 8; ++j) {
            float r = wredsum(sv[j]);
            if (l == 0) s.l[w + j*8] = r;
        }
    }
    __syncthreads();
    if (tid < 32) {
        float a0 = s.l[tid], a1 = s.l[tid + 32];
        float mx = wredmax(fmaxf(a0, a1));
        mx = __shfl_sync(0xffffffffu, mx, 0);
        float p0 = __expf(a0 - mx), p1 = __expf(a1 - mx);
        float sm2 = wredsum(p0 + p1);
        sm2 = __shfl_sync(0xffffffffu, sm2, 0);
        s.beta[tid] = __fdividef(p0, sm2);
        s.beta[tid + 32] = __fdividef(p1, sm2);
    }
    __syncthreads();
    float c0 = 0.f, c1 = 0.f;
    const float* xe = g_Xe + b*TT*MM + tid;
    #pragma unroll 8
    for (int t = 0; t < 64; t += 2) {
        c0 += s.beta[t]     * ldcs(xe + t*MM);
        c1 += s.beta[t + 1] * ldcs(xe + (t + 1)*MM);
    }
    float c = c0 + c1;
    g_ctx[b*MM + tid] = c;
    float part = wbt[1 + tid] * c;
    part = wredsum(part);
    if (l == 0) s.reds[w] = part;
    __syncthreads();
    if (tid == 0) {
        float tot = 0.f;
        #pragma unroll
        for (int i = 0; i < 8; ++i) tot += s.reds[i];
        s.yt = wbt[0] * inp[b*TT*INROW + step*INROW + 128] + tot;
    }
    __syncthreads();
    {
        float yt = s.yt;
        int mo = tid >> 4, ml = tid & 15, m = tid;
        const float* gp = g_gpre + b*1024 + mo*64;
        float gi = __ldcg(gp + ml)      + bih[m]       + bhh[m]       + yt*Wihd[m];
        float gf = __ldcg(gp + 16 + ml) + bih[256 + m] + bhh[256 + m] + yt*Wihd[256 + m];
        float gg = __ldcg(gp + 32 + ml) + bih[512 + m] + bhh[512 + m] + yt*Wihd[512 + m];
        float go = __ldcg(gp + 48 + ml) + bih[768 + m] + bhh[768 + m] + yt*Wihd[768 + m];
        float cold = __ldcg(&g_c[par][b*MM + m]);
        float cn = fast_sigm(gf)*cold + fast_sigm(gi)*fast_tanh(gg);
        float hn = fast_sigm(go)*fast_tanh(cn);
        g_c[par ^ 1][b*MM + m] = cn;
        g_h[par ^ 1][b*MM + m] = hn;
    }
}

// ---------------- phase: final projection ----------------
__device__ __forceinline__ void ph_final(const float* __restrict__ WbW,
                                         const float* __restrict__ Wbb,
                                         const float* __restrict__ vbW,
                                         const float* __restrict__ vbb,
                                         float* __restrict__ out, int par, SmFin& s) {
    int b = blockIdx.x, tid = threadIdx.x;
    int w = tid >> 5, l = tid & 31;
    s.hc[tid]       = __ldcg(&g_h[par][b*MM + tid]);
    s.hc[256 + tid] = __ldcg(&g_ctx[b*MM + tid]);
    __syncthreads();
    for (int p = w*32; p < w*32 + 32; ++p) {
        const float* row = WbW + p*512;
        float sv = 0.f;
        #pragma unroll
        for (int k = l; k < 512; k += 32) sv += s.hc[k] * row[k];
        sv = wredsum(sv);
        if (l == 0) s.hid[p] = sv + Wbb[p];
    }
    __syncthreads();
    float part = s.hid[tid] * vbW[tid];
    part = wredsum(part);
    if (l == 0) s.reds[w] = part;
    __syncthreads();
    if (tid == 0) {
        float tot = 0.f;
        #pragma unroll
        for (int i = 0; i < 8; ++i) tot += s.reds[i];
        out[b] = tot + vbb[0];
    }
}

// ---------------- persistent megakernel ----------------
__global__ void __launch_bounds__(256, 2) k_darnn(
        const float* __restrict__ inp,  const float* __restrict__ WU_e,
        const float* __restrict__ v_e,  const float* __restrict__ Wih_e,
        const float* __restrict__ Whh_e,const float* __restrict__ bih_e,
        const float* __restrict__ bhh_e,const float* __restrict__ WU_d,
        const float* __restrict__ v_d,  const float* __restrict__ wbt,
        const float* __restrict__ Wih_d,const float* __restrict__ Whh_d,
        const float* __restrict__ bih_d,const float* __restrict__ bhh_d,
        const float* __restrict__ WbW,  const float* __restrict__ Wbb,
        const float* __restrict__ vbW,  const float* __restrict__ vbb,
        float* __restrict__ out) {
    __shared__ SmAll sm;

    ph_xp(inp, WU_e, sm.xp);
    grid_sync();

    for (int s = 0; s < 64; ++s) {
        int par = s & 1;
        ph_enc_p1(inp, WU_e, v_e, Whh_e, s, par, sm);
        grid_sync();
        ph_enc_p2(Wih_e, bih_e, bhh_e, s, par, sm.g);
        grid_sync();
    }

    ph_xd(WU_d, sm.xd);
    grid_sync();

    for (int s = 0; s < 63; ++s) {
        int par = s & 1;
        ph_dec_d1(WU_d, Whh_d, par, sm);
        grid_sync();
        ph_dec_att2(inp, v_d, wbt, Wih_d, bih_d, bhh_d, s, par, sm.d);
        grid_sync();
    }

    ph_final(WbW, Wbb, vbW, vbb, out, 1, sm.f);
}

// ---------------- launcher ----------------
extern "C" void kernel_launch(void* const* d_in, const int* in_sizes, int n_in,
                              void* d_out, int out_size) {
    const float* inp   = (const float*)d_in[0];
    const float* WU_e  = (const float*)d_in[1];
    const float* v_e   = (const float*)d_in[2];
    const float* Wih_e = (const float*)d_in[3];
    const float* Whh_e = (const float*)d_in[4];
    const float* bih_e = (const float*)d_in[5];
    const float* bhh_e = (const float*)d_in[6];
    const float* WU_d  = (const float*)d_in[7];
    const float* v_d   = (const float*)d_in[8];
    const float* wbt   = (const float*)d_in[9];
    const float* Wih_d = (const float*)d_in[10];
    const float* Whh_d = (const float*)d_in[11];
    const float* bih_d = (const float*)d_in[12];
    const float* bhh_d = (const float*)d_in[13];
    const float* WbW   = (const float*)d_in[14];
    const float* Wbb   = (const float*)d_in[15];
    const float* vbW   = (const float*)d_in[16];
    const float* vbb   = (const float*)d_in[17];
    float* out = (float*)d_out;

    k_darnn<<<NBLK, 256>>>(inp, WU_e, v_e, Wih_e, Whh_e, bih_e, bhh_e,
                           WU_d, v_d, wbt, Wih_d, Whh_d, bih_d, bhh_d,
                           WbW, Wbb, vbW, vbb, out);
}

// round 17
// speedup vs baseline: 1.3365x; 1.0092x over previous
#include <cuda_runtime.h>
#include <math.h>

#define BB 256
#define TT 64
#define NN 128
#define MM 256
#define INROW 129   // N + YD
#define NBLK 256

typedef unsigned long long ull;

// ---------------- scratch (device globals; no allocation) ----------------
__device__ float g_Xp[BB*TT*NN];     // immutable after xp
__device__ float g_Xe[BB*TT*MM];     // immutable after encode
__device__ float g_Xd[BB*TT*MM];     // immutable after xd
__device__ float g_h[2][BB*MM];      // mutable (ldcg)
__device__ float g_c[2][BB*MM];      // mutable (ldcg)
__device__ float g_xin[BB*NN];       // mutable (ldcg)
__device__ float g_hsW[BB*MM];       // mutable (ldcg)
__device__ float g_gpre[BB*1024];    // mutable (ldcg) gate preactivations (h-part)
__device__ float g_ctx[BB*MM];

// ---------------- grid barrier (release/acquire, single-thread arrival) ----------------
__device__ unsigned g_bar_count;
__device__ unsigned g_bar_gen;

__device__ __forceinline__ unsigned ld_acq(const unsigned* p) {
    unsigned v;
    asm volatile("ld.acquire.gpu.u32 %0, [%1];" : "=r"(v) : "l"(p) : "memory");
    return v;
}

__device__ __forceinline__ void grid_sync() {
    __syncthreads();
    if (threadIdx.x == 0) {
        unsigned gen = g_bar_gen;
        unsigned old;
        asm volatile("atom.add.release.gpu.u32 %0, [%1], 1;"
                     : "=r"(old) : "l"(&g_bar_count) : "memory");
        if (old == NBLK - 1) {
            g_bar_count = 0;
            asm volatile("st.release.gpu.u32 [%0], %1;"
                         :: "l"(&g_bar_gen), "r"(gen + 1) : "memory");
        } else {
            while (ld_acq(&g_bar_gen) == gen) { }
        }
    }
    __syncthreads();
}

// ---------------- math helpers ----------------
__device__ __forceinline__ float fast_sigm(float x) {
    return __fdividef(1.0f, 1.0f + __expf(-x));
}
__device__ __forceinline__ float fast_tanh(float x) {
    float e = __expf(2.0f * x);
    return 1.0f - __fdividef(2.0f, e + 1.0f);
}
// single-MUFU tanh — attention score loops only
__device__ __forceinline__ float tanh_apx(float x) {
    float y; asm("tanh.approx.f32 %0, %1;" : "=f"(y) : "f"(x)); return y;
}
__device__ __forceinline__ float wredsum(float v) {
    #pragma unroll
    for (int o = 16; o > 0; o >>= 1) v += __shfl_down_sync(0xffffffffu, v, o);
    return v;
}
__device__ __forceinline__ float wredmax(float v) {
    #pragma unroll
    for (int o = 16; o > 0; o >>= 1) v = fmaxf(v, __shfl_down_sync(0xffffffffu, v, o));
    return v;
}
__device__ __forceinline__ ull f2pack(float lo, float hi) {
    ull r; asm("mov.b64 %0, {%1, %2};" : "=l"(r) : "f"(lo), "f"(hi)); return r;
}
__device__ __forceinline__ void ffma2(ull& d, ull a, ull b) {
    asm("fma.rn.f32x2 %0, %1, %2, %3;" : "=l"(d) : "l"(a), "l"(b), "l"(d));
}
__device__ __forceinline__ float2 f2unpack(ull v) {
    float2 r; asm("mov.b64 {%0, %1}, %2;" : "=f"(r.x), "=f"(r.y) : "l"(v)); return r;
}
__device__ __forceinline__ float ldcs(const float* p) {
    float v; asm volatile("ld.global.cs.f32 %0, [%1];" : "=f"(v) : "l"(p)); return v;
}

// ---------------- shared memory union ----------------
struct SmGates { float A[2][2][32][18]; float W[2][2][32][68]; float red[16][66]; };
struct SmG32   { float A[2][32][36]; float W[2][32][68]; float red[32][66]; };
struct SmHsw2  { float A[2][32][18]; float W[2][32][34]; float red[16][33]; };
struct SmXp    { float WUx[4096]; float Xs[8192]; };
struct SmAtt   { float hs[2][512]; float hsW[2][64]; float ves[64]; float redm[2][4]; float reds[2][4]; };
struct SmXd    { float A[32][68]; float W[32][68]; };
struct SmDatt  { float hsw[256]; float vds[256]; float l[64]; float beta[64]; float reds[8]; float yt; };
struct SmFin   { float hc[512]; float hid[256]; float reds[8]; };
union SmAll {
    SmGates g; SmG32 g32; SmHsw2 h2; SmXp xp; SmAtt a; SmXd xd; SmDatt d; SmFin f;
};

// ---------------- phase: Xp precompute (+ zero h/c) ----------------
__device__ __forceinline__ void ph_xp(const float* __restrict__ inp,
                                      const float* __restrict__ WU_e, SmXp& s) {
    int b = blockIdx.x, tid = threadIdx.x;
    {
        int idx = b * 256 + tid;
        g_h[0][idx] = 0.f; g_h[1][idx] = 0.f;
        g_c[0][idx] = 0.f; g_c[1][idx] = 0.f;
    }
    for (int idx = tid; idx < 4096; idx += 256) {
        int t = idx >> 6, tp = idx & 63;
        s.WUx[idx] = WU_e[t*576 + 512 + tp];
    }
    for (int idx = tid; idx < 8192; idx += 256) {
        int tp = idx >> 7, n = idx & 127;
        s.Xs[idx] = inp[b*TT*INROW + tp*INROW + n];
    }
    __syncthreads();
    int half = tid >> 7, n = tid & 127;
    float acc[32];
    #pragma unroll
    for (int t = 0; t < 32; ++t) acc[t] = 0.f;
    for (int tp = 0; tp < 64; ++tp) {
        float xv = s.Xs[tp*128 + n];
        #pragma unroll
        for (int t = 0; t < 32; ++t) acc[t] += xv * s.WUx[(half*32 + t)*64 + tp];
    }
    #pragma unroll
    for (int t = 0; t < 32; ++t) g_Xp[(b*TT + half*32 + t)*NN + n] = acc[t];
}

// ---------------- sub: encoder attention, TWO batches in parallel ----------------
__device__ __forceinline__ void enc_att_pair(const float* __restrict__ inp,
                                             const float* __restrict__ WU_e,
                                             const float* __restrict__ v_e,
                                             int step, int par, int b0, SmAtt& s) {
    int tid = threadIdx.x;
    int bsel = tid >> 7, t128 = tid & 127;
    int w = tid >> 5, l = tid & 31;
    int b = b0 + bsel;
    s.hs[bsel][t128]       = __ldcg(&g_h[par][b*MM + t128]);
    s.hs[bsel][t128 + 128] = __ldcg(&g_h[par][b*MM + t128 + 128]);
    s.hs[bsel][t128 + 256] = __ldcg(&g_c[par][b*MM + t128]);
    s.hs[bsel][t128 + 384] = __ldcg(&g_c[par][b*MM + t128 + 128]);
    if (tid < 64) s.ves[tid] = v_e[tid];
    __syncthreads();
    // hsW: warps 0-3 -> batch 0 (16 rows each), warps 4-7 -> batch 1
    {
        int wb = w >> 2, wi = w & 3;
        #pragma unroll
        for (int t = wi*16; t < wi*16 + 16; ++t) {
            const float* row = WU_e + t*576;
            float sv = 0.f;
            #pragma unroll
            for (int k = l; k < 512; k += 32) sv += s.hs[wb][k] * row[k];
            sv = wredsum(sv);
            if (l == 0) s.hsW[wb][t] = sv;
        }
    }
    __syncthreads();
    // E + softmax: 4 striped accumulators to break the dependency chain
    int n = t128;
    float e0 = 0.f, e1 = 0.f, e2 = 0.f, e3 = 0.f;
    {
        const float* xp = g_Xp + b*TT*NN + n;
        const float* hh = s.hsW[bsel];
        #pragma unroll
        for (int t = 0; t < 16; ++t) {
            e0 += s.ves[t]      * tanh_apx(hh[t]      + xp[t*NN]);
            e1 += s.ves[t + 16] * tanh_apx(hh[t + 16] + xp[(t + 16)*NN]);
            e2 += s.ves[t + 32] * tanh_apx(hh[t + 32] + xp[(t + 32)*NN]);
            e3 += s.ves[t + 48] * tanh_apx(hh[t + 48] + xp[(t + 48)*NN]);
        }
    }
    float e = (e0 + e1) + (e2 + e3);
    float m = wredmax(e);
    if (l == 0) s.redm[bsel][w & 3] = m;
    __syncthreads();
    m = fmaxf(fmaxf(s.redm[bsel][0], s.redm[bsel][1]),
              fmaxf(s.redm[bsel][2], s.redm[bsel][3]));
    float p = __expf(e - m);
    float sv = wredsum(p);
    if (l == 0) s.reds[bsel][w & 3] = sv;
    __syncthreads();
    float tot = s.reds[bsel][0] + s.reds[bsel][1] + s.reds[bsel][2] + s.reds[bsel][3];
    float alpha = __fdividef(p, tot);
    g_xin[b*NN + n] = inp[b*TT*INROW + step*INROW + n] * alpha;
}

// ---------------- sub: h-gates GEMM, 32b x 64co tile, K=256 -> g_gpre ----------------
// register-prefetch pipelined: load chunk c+1 into regs while computing chunk c
__device__ __forceinline__ void gates_h32(const float* __restrict__ Whh,
                                          int par, int blk2, SmG32& s) {
    int bb = blk2 >> 4, mo = blk2 & 15;
    int tid = threadIdx.x;
    int kg = tid >> 7;
    int t128 = tid & 127;
    int ty = t128 >> 4, tx = t128 & 15;
    ull acc[4][2] = {{0,0},{0,0},{0,0},{0,0}};
    const float* hsrc = g_h[par];
    int kbase = kg * 128;
    float ra[8], rw[16];

    #define G32_LOAD(c) do {                                                   \
        int kc = kbase + (c)*32;                                               \
        _Pragma("unroll")                                                      \
        for (int u = 0; u < 8; ++u) {                                          \
            int idx = t128 + u*128;                                            \
            int row = idx >> 5, kk = idx & 31;                                 \
            ra[u] = __ldcg(hsrc + (bb*32 + row)*MM + kc + kk);                 \
        }                                                                      \
        _Pragma("unroll")                                                      \
        for (int u = 0; u < 16; ++u) {                                         \
            int idx = t128 + u*128;                                            \
            int co = idx >> 5, kk = idx & 31;                                  \
            int row = (co >> 4)*256 + mo*16 + (co & 15);                       \
            rw[u] = __ldcg(Whh + row*256 + kc + kk);                           \
        }                                                                      \
    } while (0)
    #define G32_STS() do {                                                     \
        _Pragma("unroll")                                                      \
        for (int u = 0; u < 8; ++u) {                                          \
            int idx = t128 + u*128;                                            \
            s.A[kg][idx & 31][idx >> 5] = ra[u];                               \
        }                                                                      \
        _Pragma("unroll")                                                      \
        for (int u = 0; u < 16; ++u) {                                         \
            int idx = t128 + u*128;                                            \
            s.W[kg][idx & 31][idx >> 5] = rw[u];                               \
        }                                                                      \
    } while (0)

    G32_LOAD(0); G32_STS();
    __syncthreads();
    #pragma unroll
    for (int c = 0; c < 4; ++c) {
        if (c < 3) G32_LOAD(c + 1);
        #pragma unroll
        for (int kk = 0; kk < 32; ++kk) {
            float4 a = *(const float4*)&s.A[kg][kk][ty*4];
            float4 w = *(const float4*)&s.W[kg][kk][tx*4];
            ull w01 = f2pack(w.x, w.y), w23 = f2pack(w.z, w.w);
            ull a0 = f2pack(a.x, a.x), a1 = f2pack(a.y, a.y);
            ull a2 = f2pack(a.z, a.z), a3 = f2pack(a.w, a.w);
            ffma2(acc[0][0], a0, w01); ffma2(acc[0][1], a0, w23);
            ffma2(acc[1][0], a1, w01); ffma2(acc[1][1], a1, w23);
            ffma2(acc[2][0], a2, w01); ffma2(acc[2][1], a2, w23);
            ffma2(acc[3][0], a3, w01); ffma2(acc[3][1], a3, w23);
        }
        __syncthreads();
        if (c < 3) { G32_STS(); __syncthreads(); }
    }
    #undef G32_LOAD
    #undef G32_STS

    if (kg == 0) {
        #pragma unroll
        for (int r = 0; r < 4; ++r) {
            *(float2*)&s.red[ty*4 + r][tx*4]     = f2unpack(acc[r][0]);
            *(float2*)&s.red[ty*4 + r][tx*4 + 2] = f2unpack(acc[r][1]);
        }
    }
    __syncthreads();
    if (kg == 1) {
        #pragma unroll
        for (int r = 0; r < 4; ++r) {
            float2 v0 = f2unpack(acc[r][0]), v1 = f2unpack(acc[r][1]);
            float2 c0 = *(float2*)&s.red[ty*4 + r][tx*4];
            float2 c1 = *(float2*)&s.red[ty*4 + r][tx*4 + 2];
            c0.x += v0.x; c0.y += v0.y; c1.x += v1.x; c1.y += v1.y;
            *(float2*)&s.red[ty*4 + r][tx*4]     = c0;
            *(float2*)&s.red[ty*4 + r][tx*4 + 2] = c1;
        }
    }
    __syncthreads();
    #pragma unroll
    for (int u = 0; u < 8; ++u) {
        int p = tid + u*256;
        int bi = p >> 6, co = p & 63;
        g_gpre[(bb*32 + bi)*1024 + mo*64 + co] = s.red[bi][co];
    }
}

// ---------------- encoder phase 1: att-pair (blocks 0-127) || h-gates (128-255) ----------
__device__ __forceinline__ void ph_enc_p1(const float* __restrict__ inp,
                                          const float* __restrict__ WU_e,
                                          const float* __restrict__ v_e,
                                          const float* __restrict__ Whh_e,
                                          int step, int par, SmAll& sm) {
    int blk = blockIdx.x;
    if (blk < 128) enc_att_pair(inp, WU_e, v_e, step, par, blk*2, sm.a);
    else           gates_h32(Whh_e, par, blk - 128, sm.g32);
}

// ---------------- encoder phase 2: x-gates GEMM (K=128) + LSTM epilogue ----------------
__device__ __forceinline__ void ph_enc_p2(const float* __restrict__ Wih,
                                          const float* __restrict__ bih,
                                          const float* __restrict__ bhh,
                                          int step, int par, SmGates& s) {
    int bb = blockIdx.x >> 4, mo = blockIdx.x & 15;
    int tid = threadIdx.x;
    int kg = tid >> 7;
    int t128 = tid & 127;
    int ty = t128 >> 4, tx = t128 & 15;
    ull acc[2][2] = {{0ull, 0ull}, {0ull, 0ull}};
    int kbase = kg * 64;
    float ra[4], rw[16];

    #define P2_LOAD(c) do {                                                    \
        int kc = kbase + (c)*32;                                               \
        _Pragma("unroll")                                                      \
        for (int u = 0; u < 4; ++u) {                                          \
            int idx = t128 + u*128;                                            \
            int row = idx >> 5, kk = idx & 31;                                 \
            ra[u] = __ldcg(g_xin + (bb*16 + row)*NN + kc + kk);                \
        }                                                                      \
        _Pragma("unroll")                                                      \
        for (int u = 0; u < 16; ++u) {                                         \
            int idx = t128 + u*128;                                            \
            int co = idx >> 5, kk = idx & 31;                                  \
            int row = (co >> 4)*256 + mo*16 + (co & 15);                       \
            rw[u] = __ldcg(Wih + row*128 + kc + kk);                           \
        }                                                                      \
    } while (0)
    #define P2_STS(st) do {                                                    \
        _Pragma("unroll")                                                      \
        for (int u = 0; u < 4; ++u) {                                          \
            int idx = t128 + u*128;                                            \
            s.A[st][kg][idx & 31][idx >> 5] = ra[u];                           \
        }                                                                      \
        _Pragma("unroll")                                                      \
        for (int u = 0; u < 16; ++u) {                                         \
            int idx = t128 + u*128;                                            \
            s.W[st][kg][idx & 31][idx >> 5] = rw[u];                           \
        }                                                                      \
    } while (0)

    P2_LOAD(0); P2_STS(0);
    __syncthreads();
    #pragma unroll
    for (int c = 0; c < 2; ++c) {
        int st = c & 1;
        if (c < 1) { P2_LOAD(1); P2_STS(1); }   // stage 1 free: write while computing stage 0
        #pragma unroll
        for (int kk = 0; kk < 32; ++kk) {
            float2 a = *(const float2*)&s.A[st][kg][kk][ty*2];
            float4 w = *(const float4*)&s.W[st][kg][kk][tx*4];
            ull ax = f2pack(a.x, a.x), ay = f2pack(a.y, a.y);
            ull w01 = f2pack(w.x, w.y), w23 = f2pack(w.z, w.w);
            ffma2(acc[0][0], ax, w01); ffma2(acc[0][1], ax, w23);
            ffma2(acc[1][0], ay, w01); ffma2(acc[1][1], ay, w23);
        }
        __syncthreads();
    }
    #undef P2_LOAD
    #undef P2_STS

    if (kg == 0) {
        #pragma unroll
        for (int i = 0; i < 2; ++i) {
            *(float2*)&s.red[ty*2 + i][tx*4]     = f2unpack(acc[i][0]);
            *(float2*)&s.red[ty*2 + i][tx*4 + 2] = f2unpack(acc[i][1]);
        }
    }
    __syncthreads();
    if (kg == 1) {
        #pragma unroll
        for (int i = 0; i < 2; ++i) {
            float2 v0 = f2unpack(acc[i][0]), v1 = f2unpack(acc[i][1]);
            float2 c0 = *(float2*)&s.red[ty*2 + i][tx*4];
            float2 c1 = *(float2*)&s.red[ty*2 + i][tx*4 + 2];
            c0.x += v0.x; c0.y += v0.y; c1.x += v1.x; c1.y += v1.y;
            *(float2*)&s.red[ty*2 + i][tx*4]     = c0;
            *(float2*)&s.red[ty*2 + i][tx*4 + 2] = c1;
        }
    }
    __syncthreads();
    {
        int bi = tid >> 4, ml = tid & 15;
        int gb = bb*16 + bi, m = mo*16 + ml;
        const float* gp = g_gpre + gb*1024 + mo*64;
        float gi = s.red[bi][ml]      + __ldcg(gp + ml)      + bih[m]       + bhh[m];
        float gf = s.red[bi][16 + ml] + __ldcg(gp + 16 + ml) + bih[256 + m] + bhh[256 + m];
        float gg = s.red[bi][32 + ml] + __ldcg(gp + 32 + ml) + bih[512 + m] + bhh[512 + m];
        float go = s.red[bi][48 + ml] + __ldcg(gp + 48 + ml) + bih[768 + m] + bhh[768 + m];
        float cold = __ldcg(&g_c[par][gb*MM + m]);
        float cn = fast_sigm(gf)*cold + fast_sigm(gi)*fast_tanh(gg);
        float hn = fast_sigm(go)*fast_tanh(cn);
        g_c[par ^ 1][gb*MM + m] = cn;
        g_h[par ^ 1][gb*MM + m] = hn;
        g_Xe[(gb*TT + step)*MM + m] = hn;
    }
}

// ---------------- phase: Xd precompute (+ re-zero h/c) ----------------
__device__ __forceinline__ void ph_xd(const float* __restrict__ WU_d, SmXd& s) {
    int rb = blockIdx.x, tid = threadIdx.x;
    int ty = tid >> 4, tx = tid & 15;
    for (int ob = 0; ob < 4; ++ob) {
        float acc[4][4];
        #pragma unroll
        for (int i = 0; i < 4; ++i)
            #pragma unroll
            for (int j = 0; j < 4; ++j) acc[i][j] = 0.f;
        for (int kc = 0; kc < 256; kc += 32) {
            for (int idx = tid; idx < 2048; idx += 256) {
                int ri = idx >> 5, kk = idx & 31;
                s.A[kk][ri] = g_Xe[(rb*64 + ri)*MM + kc + kk];
            }
            for (int idx = tid; idx < 2048; idx += 256) {
                int co = idx >> 5, kk = idx & 31;
                s.W[kk][co] = WU_d[(ob*64 + co)*768 + 512 + kc + kk];
            }
            __syncthreads();
            #pragma unroll
            for (int kk = 0; kk < 32; ++kk) {
                float4 a = *(const float4*)&s.A[kk][ty*4];
                float4 w = *(const float4*)&s.W[kk][tx*4];
                acc[0][0] += a.x*w.x; acc[0][1] += a.x*w.y; acc[0][2] += a.x*w.z; acc[0][3] += a.x*w.w;
                acc[1][0] += a.y*w.x; acc[1][1] += a.y*w.y; acc[1][2] += a.y*w.z; acc[1][3] += a.y*w.w;
                acc[2][0] += a.z*w.x; acc[2][1] += a.z*w.y; acc[2][2] += a.z*w.z; acc[2][3] += a.z*w.w;
                acc[3][0] += a.w*w.x; acc[3][1] += a.w*w.y; acc[3][2] += a.w*w.z; acc[3][3] += a.w*w.w;
            }
            __syncthreads();
        }
        #pragma unroll
        for (int i = 0; i < 4; ++i)
            #pragma unroll
            for (int j = 0; j < 4; ++j)
                g_Xd[(rb*64 + ty*4 + i)*MM + ob*64 + tx*4 + j] = acc[i][j];
    }
    int idx = blockIdx.x * 256 + tid;
    g_h[0][idx] = 0.f; g_h[1][idx] = 0.f;
    g_c[0][idx] = 0.f; g_c[1][idx] = 0.f;
}

// ---------------- sub: decoder hsW GEMM, 16b x 32o tile, K=512, reg-prefetch ----------------
__device__ __forceinline__ void dec_hsw2(const float* __restrict__ WU_d,
                                         int par, int blk, SmHsw2& s) {
    int rb = blk >> 3, ob = blk & 7;
    int tid = threadIdx.x;
    int kg = tid >> 7;
    int t128 = tid & 127;
    int ty = t128 >> 4, tx = t128 & 15;
    ull acc0 = 0ull, acc1 = 0ull;
    int kbase = kg * 256;
    float ra[4], rw[8];

    #define H2_LOAD(c) do {                                                    \
        int kc = kbase + (c)*32;                                               \
        _Pragma("unroll")                                                      \
        for (int u = 0; u < 4; ++u) {                                          \
            int idx = t128 + u*128;                                            \
            int ri = idx >> 5, kk = idx & 31;                                  \
            int k = kc + kk, gb = rb*16 + ri;                                  \
            ra[u] = (k < 256) ? __ldcg(&g_h[par][gb*MM + k])                   \
                              : __ldcg(&g_c[par][gb*MM + k - 256]);            \
        }                                                                      \
        _Pragma("unroll")                                                      \
        for (int u = 0; u < 8; ++u) {                                          \
            int idx = t128 + u*128;                                            \
            int co = idx >> 5, kk = idx & 31;                                  \
            rw[u] = __ldcg(WU_d + (ob*32 + co)*768 + kc + kk);                 \
        }                                                                      \
    } while (0)
    #define H2_STS() do {                                                      \
        _Pragma("unroll")                                                      \
        for (int u = 0; u < 4; ++u) {                                          \
            int idx = t128 + u*128;                                            \
            s.A[kg][idx & 31][idx >> 5] = ra[u];                               \
        }                                                                      \
        _Pragma("unroll")                                                      \
        for (int u = 0; u < 8; ++u) {                                          \
            int idx = t128 + u*128;                                            \
            s.W[kg][idx & 31][idx >> 5] = rw[u];                               \
        }                                                                      \
    } while (0)

    H2_LOAD(0); H2_STS();
    __syncthreads();
    #pragma unroll
    for (int c = 0; c < 8; ++c) {
        if (c < 7) H2_LOAD(c + 1);
        #pragma unroll
        for (int kk = 0; kk < 32; ++kk) {
            ull a = *(const ull*)&s.A[kg][kk][ty*2];
            float w0 = s.W[kg][kk][tx*2], w1 = s.W[kg][kk][tx*2 + 1];
            ffma2(acc0, a, f2pack(w0, w0));
            ffma2(acc1, a, f2pack(w1, w1));
        }
        __syncthreads();
        if (c < 7) { H2_STS(); __syncthreads(); }
    }
    #undef H2_LOAD
    #undef H2_STS

    float2 v0 = f2unpack(acc0), v1 = f2unpack(acc1);
    if (kg == 0) {
        s.red[ty*2][tx*2] = v0.x;     s.red[ty*2 + 1][tx*2] = v0.y;
        s.red[ty*2][tx*2 + 1] = v1.x; s.red[ty*2 + 1][tx*2 + 1] = v1.y;
    }
    __syncthreads();
    if (kg == 1) {
        s.red[ty*2][tx*2] += v0.x;     s.red[ty*2 + 1][tx*2] += v0.y;
        s.red[ty*2][tx*2 + 1] += v1.x; s.red[ty*2 + 1][tx*2 + 1] += v1.y;
    }
    __syncthreads();
    #pragma unroll
    for (int u = 0; u < 2; ++u) {
        int p = tid + u*256;
        int ri = p >> 5, co = p & 31;
        g_hsW[(rb*16 + ri)*MM + ob*32 + co] = s.red[ri][co];
    }
}

// ---------------- decoder phase D1: hsW (blocks 0-127) || h-gates (128-255) ----------------
__device__ __forceinline__ void ph_dec_d1(const float* __restrict__ WU_d,
                                          const float* __restrict__ Whh_d,
                                          int par, SmAll& sm) {
    int blk = blockIdx.x;
    if (blk < 128) dec_hsw2(WU_d, par, blk, sm.h2);
    else           gates_h32(Whh_d, par, blk - 128, sm.g32);
}

// ---------------- decoder phase D2: attention + ctx + y_tilde + LSTM epilogue ----------------
__device__ __forceinline__ void ph_dec_att2(const float* __restrict__ inp,
                                            const float* __restrict__ v_d,
                                            const float* __restrict__ wbt,
                                            const float* __restrict__ Wihd,
                                            const float* __restrict__ bih,
                                            const float* __restrict__ bhh,
                                            int step, int par, SmDatt& s) {
    int b = blockIdx.x, tid = threadIdx.x;
    int w = tid >> 5, l = tid & 31;
    s.hsw[tid] = __ldcg(&g_hsW[b*MM + tid]);
    s.vds[tid] = v_d[tid];
    __syncthreads();
    // score: 8 t-rows per warp accumulated concurrently (t = w + j*8)
    {
        float sv[8];
        #pragma unroll
        for (int j = 0; j < 8; ++j) sv[j] = 0.f;
        const float* xdb = g_Xd + b*TT*MM + l;
        #pragma unroll
        for (int mi = 0; mi < 8; ++mi) {
            int m = l + mi*32;
            float xv[8];
            #pragma unroll
            for (int j = 0; j < 8; ++j)
                xv[j] = ldcs(xdb + (w + j*8)*MM + mi*32);
            float hv = s.hsw[m], vv = s.vds[m];
            #pragma unroll
            for (int j = 0; j < 8; ++j)
                sv[j] += vv * tanh_apx(hv + xv[j]);
        }
        #pragma unroll
        for (int j = 0; j < 8; ++j) {
            float r = wredsum(sv[j]);
            if (l == 0) s.l[w + j*8] = r;
        }
    }
    __syncthreads();
    if (tid < 32) {
        float a0 = s.l[tid], a1 = s.l[tid + 32];
        float mx = wredmax(fmaxf(a0, a1));
        mx = __shfl_sync(0xffffffffu, mx, 0);
        float p0 = __expf(a0 - mx), p1 = __expf(a1 - mx);
        float sm2 = wredsum(p0 + p1);
        sm2 = __shfl_sync(0xffffffffu, sm2, 0);
        s.beta[tid] = __fdividef(p0, sm2);
        s.beta[tid + 32] = __fdividef(p1, sm2);
    }
    __syncthreads();
    float c0 = 0.f, c1 = 0.f;
    const float* xe = g_Xe + b*TT*MM + tid;
    #pragma unroll 8
    for (int t = 0; t < 64; t += 2) {
        c0 += s.beta[t]     * ldcs(xe + t*MM);
        c1 += s.beta[t + 1] * ldcs(xe + (t + 1)*MM);
    }
    float c = c0 + c1;
    g_ctx[b*MM + tid] = c;
    float part = wbt[1 + tid] * c;
    part = wredsum(part);
    if (l == 0) s.reds[w] = part;
    __syncthreads();
    if (tid == 0) {
        float tot = 0.f;
        #pragma unroll
        for (int i = 0; i < 8; ++i) tot += s.reds[i];
        s.yt = wbt[0] * inp[b*TT*INROW + step*INROW + 128] + tot;
    }
    __syncthreads();
    {
        float yt = s.yt;
        int mo = tid >> 4, ml = tid & 15, m = tid;
        const float* gp = g_gpre + b*1024 + mo*64;
        float gi = __ldcg(gp + ml)      + bih[m]       + bhh[m]       + yt*Wihd[m];
        float gf = __ldcg(gp + 16 + ml) + bih[256 + m] + bhh[256 + m] + yt*Wihd[256 + m];
        float gg = __ldcg(gp + 32 + ml) + bih[512 + m] + bhh[512 + m] + yt*Wihd[512 + m];
        float go = __ldcg(gp + 48 + ml) + bih[768 + m] + bhh[768 + m] + yt*Wihd[768 + m];
        float cold = __ldcg(&g_c[par][b*MM + m]);
        float cn = fast_sigm(gf)*cold + fast_sigm(gi)*fast_tanh(gg);
        float hn = fast_sigm(go)*fast_tanh(cn);
        g_c[par ^ 1][b*MM + m] = cn;
        g_h[par ^ 1][b*MM + m] = hn;
    }
}

// ---------------- phase: final projection ----------------
__device__ __forceinline__ void ph_final(const float* __restrict__ WbW,
                                         const float* __restrict__ Wbb,
                                         const float* __restrict__ vbW,
                                         const float* __restrict__ vbb,
                                         float* __restrict__ out, int par, SmFin& s) {
    int b = blockIdx.x, tid = threadIdx.x;
    int w = tid >> 5, l = tid & 31;
    s.hc[tid]       = __ldcg(&g_h[par][b*MM + tid]);
    s.hc[256 + tid] = __ldcg(&g_ctx[b*MM + tid]);
    __syncthreads();
    for (int p = w*32; p < w*32 + 32; ++p) {
        const float* row = WbW + p*512;
        float sv = 0.f;
        #pragma unroll
        for (int k = l; k < 512; k += 32) sv += s.hc[k] * row[k];
        sv = wredsum(sv);
        if (l == 0) s.hid[p] = sv + Wbb[p];
    }
    __syncthreads();
    float part = s.hid[tid] * vbW[tid];
    part = wredsum(part);
    if (l == 0) s.reds[w] = part;
    __syncthreads();
    if (tid == 0) {
        float tot = 0.f;
        #pragma unroll
        for (int i = 0; i < 8; ++i) tot += s.reds[i];
        out[b] = tot + vbb[0];
    }
}

// ---------------- persistent megakernel ----------------
__global__ void __launch_bounds__(256, 2) k_darnn(
        const float* __restrict__ inp,  const float* __restrict__ WU_e,
        const float* __restrict__ v_e,  const float* __restrict__ Wih_e,
        const float* __restrict__ Whh_e,const float* __restrict__ bih_e,
        const float* __restrict__ bhh_e,const float* __restrict__ WU_d,
        const float* __restrict__ v_d,  const float* __restrict__ wbt,
        const float* __restrict__ Wih_d,const float* __restrict__ Whh_d,
        const float* __restrict__ bih_d,const float* __restrict__ bhh_d,
        const float* __restrict__ WbW,  const float* __restrict__ Wbb,
        const float* __restrict__ vbW,  const float* __restrict__ vbb,
        float* __restrict__ out) {
    __shared__ SmAll sm;

    ph_xp(inp, WU_e, sm.xp);
    grid_sync();

    for (int s = 0; s < 64; ++s) {
        int par = s & 1;
        ph_enc_p1(inp, WU_e, v_e, Whh_e, s, par, sm);
        grid_sync();
        ph_enc_p2(Wih_e, bih_e, bhh_e, s, par, sm.g);
        grid_sync();
    }

    ph_xd(WU_d, sm.xd);
    grid_sync();

    for (int s = 0; s < 63; ++s) {
        int par = s & 1;
        ph_dec_d1(WU_d, Whh_d, par, sm);
        grid_sync();
        ph_dec_att2(inp, v_d, wbt, Wih_d, bih_d, bhh_d, s, par, sm.d);
        grid_sync();
    }

    ph_final(WbW, Wbb, vbW, vbb, out, 1, sm.f);
}

// ---------------- launcher ----------------
extern "C" void kernel_launch(void* const* d_in, const int* in_sizes, int n_in,
                              void* d_out, int out_size) {
    const float* inp   = (const float*)d_in[0];
    const float* WU_e  = (const float*)d_in[1];
    const float* v_e   = (const float*)d_in[2];
    const float* Wih_e = (const float*)d_in[3];
    const float* Whh_e = (const float*)d_in[4];
    const float* bih_e = (const float*)d_in[5];
    const float* bhh_e = (const float*)d_in[6];
    const float* WU_d  = (const float*)d_in[7];
    const float* v_d   = (const float*)d_in[8];
    const float* wbt   = (const float*)d_in[9];
    const float* Wih_d = (const float*)d_in[10];
    const float* Whh_d = (const float*)d_in[11];
    const float* bih_d = (const float*)d_in[12];
    const float* bhh_d = (const float*)d_in[13];
    const float* WbW   = (const float*)d_in[14];
    const float* Wbb   = (const float*)d_in[15];
    const float* vbW   = (const float*)d_in[16];
    const float* vbb   = (const float*)d_in[17];
    float* out = (float*)d_out;

    k_darnn<<<NBLK, 256>>>(inp, WU_e, v_e, Wih_e, Whh_e, bih_e, bhh_e,
                           WU_d, v_d, wbt, Wih_d, Whh_d, bih_d, bhh_d,
                           WbW, Wbb, vbW, vbb, out);
}